// round 5
// baseline (speedup 1.0000x reference)
#include <cuda_runtime.h>
#include <cstdint>
#include <math.h>

#define T_LEN 16384
#define D_IN  2048
#define HID   256
#define G3H   768
#define NCLUS 8
#define ROWS_PER_CTA 96     // 768 / 8
#define SCAN_THREADS 768    // 96 rows * 8 segs
#define SEG_LEN 32          // 256 / 8

// ---------------- device scratch (static, no allocation) ----------------
__device__ float d_gx[2][(size_t)T_LEN * G3H];   // input projections, both dirs
__device__ float d_h[(size_t)T_LEN * 512];       // concat(h_f, h_b)

// ---------------- small PTX helpers ----------------
__device__ __forceinline__ uint32_t smem_u32(const void* p) {
    return (uint32_t)__cvta_generic_to_shared(p);
}
__device__ __forceinline__ uint32_t mapa_rank(uint32_t addr, uint32_t rank) {
    uint32_t d;
    asm("mapa.shared::cluster.u32 %0, %1, %2;" : "=r"(d) : "r"(addr), "r"(rank));
    return d;
}
__device__ __forceinline__ void st_cluster_f32(uint32_t addr, float v) {
    asm volatile("st.shared::cluster.f32 [%0], %1;" :: "r"(addr), "f"(v) : "memory");
}

// =====================================================================
// Kernel 1: gx[dir] = feat @ W_ih[dir]^T + b_ih[dir]
// Tiled fp32 GEMM-NT: 128x64 tile, BK=16, 256 threads, 8x4 per thread.
// =====================================================================
__global__ __launch_bounds__(256)
void gemm_gx_kernel(const float* __restrict__ feat,
                    const float* __restrict__ Wf, const float* __restrict__ bf,
                    const float* __restrict__ Wb, const float* __restrict__ bb)
{
    const int dir = blockIdx.z;
    const float* __restrict__ W    = dir ? Wb : Wf;
    const float* __restrict__ bias = dir ? bb : bf;
    float* __restrict__ C = d_gx[dir];

    const int t0 = blockIdx.y * 128;
    const int o0 = blockIdx.x * 64;

    __shared__ float As[16][132];  // [k][m], padded
    __shared__ float Bs[16][68];   // [k][n], padded

    const int tid = threadIdx.x;
    const int tx = tid & 15, ty = tid >> 4;
    const int m0 = ty * 8, n0 = tx * 4;

    const int ar0 = tid >> 2;            // 0..63
    const int akq = (tid & 3) * 4;       // 0,4,8,12

    const float* aptr0 = feat + (size_t)(t0 + ar0)      * D_IN + akq;
    const float* aptr1 = feat + (size_t)(t0 + ar0 + 64) * D_IN + akq;
    const float* bptr  = W    + (size_t)(o0 + ar0)      * D_IN + akq;

    float4 pa0 = *(const float4*)(aptr0);
    float4 pa1 = *(const float4*)(aptr1);
    float4 pb  = *(const float4*)(bptr);

    float acc[8][4];
#pragma unroll
    for (int i = 0; i < 8; i++)
#pragma unroll
        for (int j = 0; j < 4; j++) acc[i][j] = 0.f;

    for (int kt = 0; kt < D_IN; kt += 16) {
        // commit prefetched tile to smem (transposed)
        As[akq + 0][ar0] = pa0.x; As[akq + 1][ar0] = pa0.y;
        As[akq + 2][ar0] = pa0.z; As[akq + 3][ar0] = pa0.w;
        As[akq + 0][ar0 + 64] = pa1.x; As[akq + 1][ar0 + 64] = pa1.y;
        As[akq + 2][ar0 + 64] = pa1.z; As[akq + 3][ar0 + 64] = pa1.w;
        Bs[akq + 0][ar0] = pb.x; Bs[akq + 1][ar0] = pb.y;
        Bs[akq + 2][ar0] = pb.z; Bs[akq + 3][ar0] = pb.w;
        __syncthreads();

        if (kt + 16 < D_IN) {
            pa0 = *(const float4*)(aptr0 + kt + 16);
            pa1 = *(const float4*)(aptr1 + kt + 16);
            pb  = *(const float4*)(bptr  + kt + 16);
        }

#pragma unroll
        for (int k = 0; k < 16; k++) {
            const float4 a0 = *(const float4*)&As[k][m0];
            const float4 a1 = *(const float4*)&As[k][m0 + 4];
            const float4 b  = *(const float4*)&Bs[k][n0];
            float av[8] = {a0.x, a0.y, a0.z, a0.w, a1.x, a1.y, a1.z, a1.w};
            float bv[4] = {b.x, b.y, b.z, b.w};
#pragma unroll
            for (int i = 0; i < 8; i++)
#pragma unroll
                for (int j = 0; j < 4; j++)
                    acc[i][j] = fmaf(av[i], bv[j], acc[i][j]);
        }
        __syncthreads();
    }

    const float4 bv4 = *(const float4*)&bias[o0 + n0];
#pragma unroll
    for (int i = 0; i < 8; i++) {
        float4 v;
        v.x = acc[i][0] + bv4.x;
        v.y = acc[i][1] + bv4.y;
        v.z = acc[i][2] + bv4.z;
        v.w = acc[i][3] + bv4.w;
        *(float4*)&C[(size_t)(t0 + m0 + i) * G3H + o0 + n0] = v;
    }
}

// =====================================================================
// Kernel 2: BiGRU scan. Grid = 16 CTAs = 2 clusters of 8 (dir = blk/8).
// Each CTA: 96 rows of W_hh in registers (32 fp32/thread, 8 threads/row).
// Per step: matvec -> shfl-reduce -> DSMEM broadcast of gh slice to all
// 8 CTAs (double-buffered) -> barrier.cluster -> redundant gate combine.
// =====================================================================
__global__ void __cluster_dims__(NCLUS, 1, 1) __launch_bounds__(SCAN_THREADS, 1)
scan_kernel(const float* __restrict__ Whf, const float* __restrict__ bhf,
            const float* __restrict__ Whb, const float* __restrict__ bhb)
{
    // padded h: idx(k) = k + (k>>5)*4  -> seg s reads contiguous 32 floats
    // at word 36*s, bank-conflict-free float4 across the 8 segs.
    __shared__ float sh_h[288];
    __shared__ float sh_gh[2][G3H];

    const int rank = blockIdx.x & 7;
    const int dir  = blockIdx.x >> 3;
    const float* __restrict__ Whh = dir ? Whb : Whf;
    const float* __restrict__ bhh = dir ? bhb : bhf;
    const float* __restrict__ gx  = d_gx[dir];

    const int tid = threadIdx.x;
    const int rl  = tid >> 3;          // 0..95 local row
    const int seg = tid & 7;           // 0..7  inner segment
    const int row = rank * ROWS_PER_CTA + rl;
    const int k0  = seg * SEG_LEN;

    // weights in registers
    float4 w[8];
    const float4* wp = (const float4*)(Whh + (size_t)row * HID + k0);
#pragma unroll
    for (int i = 0; i < 8; i++) w[i] = wp[i];
    const float bias = bhh[row];

    const float* hbase = sh_h + 36 * seg;

    for (int i = tid; i < 288; i += SCAN_THREADS) sh_h[i] = 0.f;
    __syncthreads();

    // remote gh slot addresses (byte addresses in shared::cluster window)
    const uint32_t gh_local = smem_u32(&sh_gh[0][0]);
    uint32_t rbase[NCLUS];
#pragma unroll
    for (int r = 0; r < NCLUS; r++)
        rbase[r] = mapa_rank(gh_local, (uint32_t)r) + (uint32_t)row * 4u;

    // prefetch gx for step 0
    float xr = 0.f, xz = 0.f, xn = 0.f;
    int t = dir ? (T_LEN - 1) : 0;
    if (tid < HID) {
        const float* g = gx + (size_t)t * G3H + tid;
        xr = g[0]; xz = g[HID]; xn = g[2 * HID];
    }

    for (int s = 0; s < T_LEN; s++) {
        const int p = s & 1;

        // ---- matvec: gh[row] partial over [k0, k0+32) ----
        float acc = 0.f;
#pragma unroll
        for (int i = 0; i < 8; i++) {
            const float4 hv = *(const float4*)(hbase + 4 * i);
            acc = fmaf(w[i].x, hv.x, acc);
            acc = fmaf(w[i].y, hv.y, acc);
            acc = fmaf(w[i].z, hv.z, acc);
            acc = fmaf(w[i].w, hv.w, acc);
        }
        acc += __shfl_down_sync(0xffffffffu, acc, 4);
        acc += __shfl_down_sync(0xffffffffu, acc, 2);
        acc += __shfl_down_sync(0xffffffffu, acc, 1);

        if (seg == 0) {
            const float g = acc + bias;
            const uint32_t off = (uint32_t)p * (G3H * 4u);
#pragma unroll
            for (int r = 0; r < NCLUS; r++) st_cluster_f32(rbase[r] + off, g);
        }

        asm volatile("barrier.cluster.arrive.aligned;" ::: "memory");

        // prefetch gx for next step while barrier drains
        const int tn = dir ? (T_LEN - 2 - s) : (s + 1);
        float nxr = 0.f, nxz = 0.f, nxn = 0.f;
        if (tid < HID && s + 1 < T_LEN) {
            const float* g2 = gx + (size_t)tn * G3H + tid;
            nxr = g2[0]; nxz = g2[HID]; nxn = g2[2 * HID];
        }

        asm volatile("barrier.cluster.wait.aligned;" ::: "memory");

        // ---- gate combine (redundant in every CTA) ----
        if (tid < HID) {
            const int j = tid;
            const float hr = sh_gh[p][j];
            const float hz = sh_gh[p][HID + j];
            const float hn = sh_gh[p][2 * HID + j];
            const float r = 1.f / (1.f + __expf(-(xr + hr)));
            const float z = 1.f / (1.f + __expf(-(xz + hz)));
            const float n = tanhf(xn + r * hn);
            const int hi = j + ((j >> 5) << 2);
            const float hp = sh_h[hi];
            const float hnew = (1.f - z) * n + z * hp;
            sh_h[hi] = hnew;
            if (rank == 0) d_h[(size_t)t * 512 + dir * HID + j] = hnew;
            xr = nxr; xz = nxz; xn = nxn;
        }
        t = tn;
        __syncthreads();
    }
}

// =====================================================================
// Kernel 3: scores[t] = relu(h[t] @ Ws1^T + bs1) @ Ws2^T + bs2
// Ws1 (padded) + 32-row h stage in dynamic smem; 1 warp per row.
// =====================================================================
#define SCORES_SMEM_FLOATS (64 * 513 + 64 + 64 + 32 * 512)
__global__ __launch_bounds__(512)
void scores_kernel(const float* __restrict__ Ws1, const float* __restrict__ bs1,
                   const float* __restrict__ Ws2, const float* __restrict__ bs2,
                   float* __restrict__ out)
{
    extern __shared__ float sm[];
    float* sW1 = sm;                  // 64 x 513 (padded)
    float* sW2 = sm + 64 * 513;       // 64
    float* sb1 = sW2 + 64;            // 64
    float* sh  = sb1 + 64;            // 32 x 512

    const int tid = threadIdx.x;
    for (int i = tid; i < 64 * 512; i += 512) {
        const int kk = i >> 9, j = i & 511;
        sW1[kk * 513 + j] = Ws1[i];
    }
    if (tid < 64) { sW2[tid] = Ws2[tid]; sb1[tid] = bs1[tid]; }
    const float bs2v = bs2[0];
    __syncthreads();

    const int warp = tid >> 5, lane = tid & 31;
    const float* w0p = sW1 + (size_t)lane * 513;
    const float* w1p = sW1 + (size_t)(lane + 32) * 513;

    for (int iter = 0; iter < 4; iter++) {
        const int r0 = blockIdx.x * 128 + iter * 32;
        __syncthreads();  // protect previous stage reads
        for (int e = tid * 4; e < 32 * 512; e += 512 * 4) {
            const int rrow = e >> 9, col = e & 511;
            *(float4*)&sh[e] = *(const float4*)&d_h[(size_t)(r0 + rrow) * 512 + col];
        }
        __syncthreads();

#pragma unroll
        for (int rr = 0; rr < 2; rr++) {
            const int rowl = warp * 2 + rr;
            const float* hrow = sh + (size_t)rowl * 512;
            float acc0 = 0.f, acc1 = 0.f;
            for (int j = 0; j < 512; j += 4) {
                const float4 hv = *(const float4*)(hrow + j);
                acc0 = fmaf(hv.x, w0p[j + 0], acc0);
                acc0 = fmaf(hv.y, w0p[j + 1], acc0);
                acc0 = fmaf(hv.z, w0p[j + 2], acc0);
                acc0 = fmaf(hv.w, w0p[j + 3], acc0);
                acc1 = fmaf(hv.x, w1p[j + 0], acc1);
                acc1 = fmaf(hv.y, w1p[j + 1], acc1);
                acc1 = fmaf(hv.z, w1p[j + 2], acc1);
                acc1 = fmaf(hv.w, w1p[j + 3], acc1);
            }
            float v = fmaxf(acc0 + sb1[lane], 0.f) * sW2[lane]
                    + fmaxf(acc1 + sb1[lane + 32], 0.f) * sW2[lane + 32];
#pragma unroll
            for (int o = 16; o; o >>= 1) v += __shfl_down_sync(0xffffffffu, v, o);
            if (lane == 0) out[2 + r0 + rowl] = v + bs2v;
        }
    }
}

// =====================================================================
// Kernel 4: top-8 -> softmax weights -> clip_repr -> classifier -> logits
// Single CTA, 1024 threads. scores read from out[2..].
// =====================================================================
__global__ __launch_bounds__(1024)
void finalize_kernel(const float* __restrict__ feat, const float* __restrict__ temp,
                     const float* __restrict__ Wc1, const float* __restrict__ bc1,
                     const float* __restrict__ Wc2, const float* __restrict__ bc2,
                     float* __restrict__ out)
{
    __shared__ float rv[1024];
    __shared__ int   ri[1024];
    __shared__ int   chosen[8];
    __shared__ float chval[8];
    __shared__ float wts[8];
    __shared__ float clip[2048];
    __shared__ float c1s[256];

    const float* scores = out + 2;
    const int tid = threadIdx.x;

    // --- iterative top-8 argmax ---
    for (int k = 0; k < 8; k++) {
        float best = -3.4e38f; int bi = 0x7fffffff;
#pragma unroll
        for (int i = 0; i < 16; i++) {
            const int j = tid + (i << 10);
            const float v = scores[j];
            bool skip = false;
            for (int kk = 0; kk < k; kk++) if (chosen[kk] == j) skip = true;
            if (!skip && (v > best || (v == best && j < bi))) { best = v; bi = j; }
        }
        rv[tid] = best; ri[tid] = bi;
        __syncthreads();
        for (int s = 512; s; s >>= 1) {
            if (tid < s) {
                if (rv[tid + s] > rv[tid] ||
                    (rv[tid + s] == rv[tid] && ri[tid + s] < ri[tid])) {
                    rv[tid] = rv[tid + s]; ri[tid] = ri[tid + s];
                }
            }
            __syncthreads();
        }
        if (tid == 0) { chosen[k] = ri[0]; chval[k] = rv[0]; }
        __syncthreads();
    }

    // --- softmax over selected (others underflow to exactly 0) ---
    if (tid == 0) {
        const float tmp = temp[0];
        float m = chval[0];
        for (int k = 1; k < 8; k++) m = fmaxf(m, chval[k]);
        float ssum = 0.f;
        for (int k = 0; k < 8; k++) { const float e = expf((chval[k] - m) / tmp); wts[k] = e; ssum += e; }
        for (int k = 0; k < 8; k++) wts[k] /= ssum;
    }
    __syncthreads();

    // --- clip_repr = sum_k w_k * feat[idx_k] ---
    for (int d = tid; d < 2048; d += 1024) {
        float c = 0.f;
#pragma unroll
        for (int k = 0; k < 8; k++)
            c = fmaf(wts[k], feat[(size_t)chosen[k] * D_IN + d], c);
        clip[d] = c;
    }
    __syncthreads();

    // --- c1 = relu(Wc1 @ clip + bc1), 4 threads per output ---
    {
        const int o = tid >> 2, part = tid & 3;
        const float* wr = Wc1 + (size_t)o * D_IN + part * 512;
        const float* cp = clip + part * 512;
        float s = 0.f;
        for (int j = 0; j < 512; j += 4) {
            const float4 c4 = *(const float4*)(cp + j);
            const float4 w4 = *(const float4*)(wr + j);
            s = fmaf(c4.x, w4.x, s);
            s = fmaf(c4.y, w4.y, s);
            s = fmaf(c4.z, w4.z, s);
            s = fmaf(c4.w, w4.w, s);
        }
        s += __shfl_xor_sync(0xffffffffu, s, 1);
        s += __shfl_xor_sync(0xffffffffu, s, 2);
        if (part == 0) c1s[o] = fmaxf(s + bc1[o], 0.f);
    }
    __syncthreads();

    // --- logits = c1 @ Wc2^T + bc2 ---
    if (tid < 64) {
        const int c = tid >> 5, lane = tid & 31;
        float s = 0.f;
        for (int kk = lane; kk < 256; kk += 32)
            s = fmaf(c1s[kk], Wc2[(size_t)c * 256 + kk], s);
#pragma unroll
        for (int o = 16; o; o >>= 1) s += __shfl_down_sync(0xffffffffu, s, o);
        if (lane == 0) out[c] = s + bc2[c];
    }
}

// =====================================================================
extern "C" void kernel_launch(void* const* d_in, const int* in_sizes, int n_in,
                              void* d_out, int out_size)
{
    const float* feat   = (const float*)d_in[0];
    const float* temp   = (const float*)d_in[1];
    const float* W_ih_f = (const float*)d_in[2];
    const float* W_hh_f = (const float*)d_in[3];
    const float* b_ih_f = (const float*)d_in[4];
    const float* b_hh_f = (const float*)d_in[5];
    const float* W_ih_b = (const float*)d_in[6];
    const float* W_hh_b = (const float*)d_in[7];
    const float* b_ih_b = (const float*)d_in[8];
    const float* b_hh_b = (const float*)d_in[9];
    const float* Ws1    = (const float*)d_in[10];
    const float* bs1    = (const float*)d_in[11];
    const float* Ws2    = (const float*)d_in[12];
    const float* bs2    = (const float*)d_in[13];
    const float* Wc1    = (const float*)d_in[14];
    const float* bc1    = (const float*)d_in[15];
    const float* Wc2    = (const float*)d_in[16];
    const float* bc2    = (const float*)d_in[17];
    float* out = (float*)d_out;

    // 1) input projections (both directions)
    gemm_gx_kernel<<<dim3(12, 128, 2), 256>>>(feat, W_ih_f, b_ih_f, W_ih_b, b_ih_b);

    // 2) BiGRU scan: 2 clusters of 8 CTAs
    scan_kernel<<<16, SCAN_THREADS>>>(W_hh_f, b_hh_f, W_hh_b, b_hh_b);

    // 3) frame scores
    cudaFuncSetAttribute(scores_kernel, cudaFuncAttributeMaxDynamicSharedMemorySize,
                         SCORES_SMEM_FLOATS * 4);
    scores_kernel<<<128, 512, SCORES_SMEM_FLOATS * 4>>>(Ws1, bs1, Ws2, bs2, out);

    // 4) top-k + softmax + weighted sum + classifier
    finalize_kernel<<<1, 1024>>>(feat, temp, Wc1, bc1, Wc2, bc2, out);
}

// round 8
// speedup vs baseline: 1.2146x; 1.2146x over previous
#include <cuda_runtime.h>
#include <cstdint>
#include <math.h>

#define T_LEN 16384
#define D_IN  2048
#define HID   256
#define G3H   768
#define NCLUS 8
#define SCAN_THREADS 768

// ---------------- device scratch (static, no allocation) ----------------
__device__ float d_gx[2][(size_t)T_LEN * G3H];   // input projections, both dirs
__device__ float d_h[(size_t)T_LEN * 512];       // concat(h_f, h_b)
__device__ float d_clip[D_IN];
__device__ float d_wts[8];
__device__ int   d_chosen[8];
__device__ float d_c1[256];

// ---------------- helpers ----------------
union F4U { float4 f4; unsigned long long u[2]; float f[4]; float2 f2[2]; };

#define FMA_F32X2(d, a, b, c) \
    asm("fma.rn.f32x2 %0, %1, %2, %3;" : "=l"(d) : "l"(a), "l"(b), "l"(c))
#define ADD_F32X2_(d, a, b) \
    asm("add.rn.f32x2 %0, %1, %2;" : "=l"(d) : "l"(a), "l"(b))
#define PACKF2(u, x, y) \
    asm("mov.b64 %0, {%1, %2};" : "=l"(u) : "f"(x), "f"(y))

__device__ __forceinline__ float2 u2f2(unsigned long long u) {
    float2 r; asm("mov.b64 {%0, %1}, %2;" : "=f"(r.x), "=f"(r.y) : "l"(u)); return r;
}
__device__ __forceinline__ uint32_t smem_u32(const void* p) {
    return (uint32_t)__cvta_generic_to_shared(p);
}
__device__ __forceinline__ uint32_t mapa_rank(uint32_t addr, uint32_t rank) {
    uint32_t d;
    asm("mapa.shared::cluster.u32 %0, %1, %2;" : "=r"(d) : "r"(addr), "r"(rank));
    return d;
}
__device__ __forceinline__ void st_cluster_f32(uint32_t addr, float v) {
    asm volatile("st.shared::cluster.f32 [%0], %1;" :: "r"(addr), "f"(v) : "memory");
}
__device__ __forceinline__ void mbar_init(uint32_t addr, uint32_t cnt) {
    asm volatile("mbarrier.init.shared.b64 [%0], %1;" :: "r"(addr), "r"(cnt) : "memory");
}
__device__ __forceinline__ void mbar_arrive_rel_cluster(uint32_t addr) {
    asm volatile("mbarrier.arrive.release.cluster.shared::cluster.b64 _, [%0];"
                 :: "r"(addr) : "memory");
}
__device__ __forceinline__ void mbar_wait_parity_acq_cluster(uint32_t addr, uint32_t par) {
    asm volatile(
        "{\n\t.reg .pred P;\n\t"
        "W%=:\n\t"
        "mbarrier.try_wait.parity.acquire.cluster.shared::cta.b64 P, [%0], %1, 0x989680;\n\t"
        "@P bra D%=;\n\t"
        "bra W%=;\n\t"
        "D%=:\n\t}"
        :: "r"(addr), "r"(par) : "memory");
}

// =====================================================================
// Kernel 1: gx[dir] = feat @ W_ih[dir]^T + b_ih[dir]
// 128x64 tile, BK=16, 256 threads, 8x4 per thread, f32x2 packed FMA.
// =====================================================================
__global__ __launch_bounds__(256)
void gemm_gx_kernel(const float* __restrict__ feat,
                    const float* __restrict__ Wf, const float* __restrict__ bf,
                    const float* __restrict__ Wb, const float* __restrict__ bb)
{
    const int dir = blockIdx.z;
    const float* __restrict__ W    = dir ? Wb : Wf;
    const float* __restrict__ bias = dir ? bb : bf;
    float* __restrict__ C = d_gx[dir];

    const int t0 = blockIdx.y * 128;
    const int o0 = blockIdx.x * 64;

    __shared__ float As[16][132];
    __shared__ float Bs[16][68];

    const int tid = threadIdx.x;
    const int tx = tid & 15, ty = tid >> 4;
    const int m0 = ty * 8, n0 = tx * 4;

    const int ar0 = tid >> 2;
    const int akq = (tid & 3) * 4;

    const float* aptr0 = feat + (size_t)(t0 + ar0)      * D_IN + akq;
    const float* aptr1 = feat + (size_t)(t0 + ar0 + 64) * D_IN + akq;
    const float* bptr  = W    + (size_t)(o0 + ar0)      * D_IN + akq;

    float4 pa0 = *(const float4*)(aptr0);
    float4 pa1 = *(const float4*)(aptr1);
    float4 pb  = *(const float4*)(bptr);

    // acc2[i2][j]: i2 = m-pair (m0+2*i2, m0+2*i2+1), j = n0+j
    unsigned long long acc2[4][4];
#pragma unroll
    for (int i = 0; i < 4; i++)
#pragma unroll
        for (int j = 0; j < 4; j++) acc2[i][j] = 0ull;

    for (int kt = 0; kt < D_IN; kt += 16) {
        As[akq + 0][ar0] = pa0.x; As[akq + 1][ar0] = pa0.y;
        As[akq + 2][ar0] = pa0.z; As[akq + 3][ar0] = pa0.w;
        As[akq + 0][ar0 + 64] = pa1.x; As[akq + 1][ar0 + 64] = pa1.y;
        As[akq + 2][ar0 + 64] = pa1.z; As[akq + 3][ar0 + 64] = pa1.w;
        Bs[akq + 0][ar0] = pb.x; Bs[akq + 1][ar0] = pb.y;
        Bs[akq + 2][ar0] = pb.z; Bs[akq + 3][ar0] = pb.w;
        __syncthreads();

        if (kt + 16 < D_IN) {
            pa0 = *(const float4*)(aptr0 + kt + 16);
            pa1 = *(const float4*)(aptr1 + kt + 16);
            pb  = *(const float4*)(bptr  + kt + 16);
        }

#pragma unroll
        for (int k = 0; k < 16; k++) {
            F4U a0, a1, b;
            a0.f4 = *(const float4*)&As[k][m0];
            a1.f4 = *(const float4*)&As[k][m0 + 4];
            b.f4  = *(const float4*)&Bs[k][n0];
            unsigned long long a2[4] = {a0.u[0], a0.u[1], a1.u[0], a1.u[1]};
            unsigned long long bd[4];
            PACKF2(bd[0], b.f[0], b.f[0]);
            PACKF2(bd[1], b.f[1], b.f[1]);
            PACKF2(bd[2], b.f[2], b.f[2]);
            PACKF2(bd[3], b.f[3], b.f[3]);
#pragma unroll
            for (int i = 0; i < 4; i++)
#pragma unroll
                for (int j = 0; j < 4; j++)
                    FMA_F32X2(acc2[i][j], a2[i], bd[j], acc2[i][j]);
        }
        __syncthreads();
    }

    const float4 bv4 = *(const float4*)&bias[o0 + n0];
#pragma unroll
    for (int i2 = 0; i2 < 4; i2++) {
        float2 p0 = u2f2(acc2[i2][0]);
        float2 p1 = u2f2(acc2[i2][1]);
        float2 p2 = u2f2(acc2[i2][2]);
        float2 p3 = u2f2(acc2[i2][3]);
        float4 v0, v1;
        v0.x = p0.x + bv4.x; v0.y = p1.x + bv4.y; v0.z = p2.x + bv4.z; v0.w = p3.x + bv4.w;
        v1.x = p0.y + bv4.x; v1.y = p1.y + bv4.y; v1.z = p2.y + bv4.z; v1.w = p3.y + bv4.w;
        *(float4*)&C[(size_t)(t0 + m0 + 2 * i2 + 0) * G3H + o0 + n0] = v0;
        *(float4*)&C[(size_t)(t0 + m0 + 2 * i2 + 1) * G3H + o0 + n0] = v1;
    }
}

// =====================================================================
// Kernel 2: BiGRU scan. Grid = 16 CTAs = 2 clusters of 8 (dir = blk/8).
// j-partitioned: CTA rank owns j in [32*rank, 32*rank+32) and its 3 gate
// rows (96 rows total). Per step:
//   matvec (f32x2, W in regs) -> shfl reduce -> seg0 STS gh_buf ->
//   __syncthreads -> warp0: gates for its 32 j, DSMEM-store new h[j] to
//   all 8 CTAs (double-buffered), release-arrive on 8 remote mbarriers ->
//   all threads acquire-wait local mbarrier parity (count=8).
// =====================================================================
__global__ void __cluster_dims__(NCLUS, 1, 1) __launch_bounds__(SCAN_THREADS, 1)
scan_kernel(const float* __restrict__ Whf, const float* __restrict__ bhf,
            const float* __restrict__ Whb, const float* __restrict__ bhb)
{
    // padded h: idx(k) = k + (k>>5)*4 ; buffer stride 288 floats
    __shared__ float sh_h[2 * 288];
    __shared__ float gh_buf[96];
    __shared__ __align__(8) unsigned long long mbar;

    const int rank = blockIdx.x & 7;
    const int dir  = blockIdx.x >> 3;
    const float* __restrict__ Whh = dir ? Whb : Whf;
    const float* __restrict__ bhh = dir ? bhb : bhf;
    const float* __restrict__ gx  = d_gx[dir];

    const int tid = threadIdx.x;
    const int rl  = tid >> 3;          // 0..95 local row
    const int seg = tid & 7;           // 0..7
    const int g   = rl >> 5;           // gate 0..2 (r,z,n)
    const int jj  = rl & 31;
    const int row = (g << 8) + (rank << 5) + jj;   // 256*g + 32*rank + jj

    // weights in registers: 32 floats = 8 float4 = 16 f32x2
    F4U w[8];
    const float4* wp = (const float4*)(Whh + (size_t)row * HID + seg * 32);
#pragma unroll
    for (int i = 0; i < 8; i++) w[i].f4 = wp[i];
    const float bias = bhh[row];

    for (int i = tid; i < 2 * 288; i += SCAN_THREADS) sh_h[i] = 0.f;
    const uint32_t mb_local = smem_u32(&mbar);
    if (tid == 0) mbar_init(mb_local, NCLUS);
    __syncthreads();
    asm volatile("barrier.cluster.arrive.aligned;" ::: "memory");
    asm volatile("barrier.cluster.wait.aligned;" ::: "memory");

    const float* hs0 = sh_h + 36 * seg;

    // combine-warp state (warp 0 only)
    const bool isComb = (tid < 32);
    const int  j      = (rank << 5) + tid;         // valid for warp 0
    const uint32_t hoff = (uint32_t)(j + ((j >> 5) << 2)) * 4u;  // padded byte off
    uint32_t rh[NCLUS], rm[NCLUS];
    float xr = 0.f, xz = 0.f, xn = 0.f;
    int t = dir ? (T_LEN - 1) : 0;
    const int tstep = dir ? -1 : 1;
    if (isComb) {
        const uint32_t h_local = smem_u32(&sh_h[0]);
#pragma unroll
        for (int r = 0; r < NCLUS; r++) {
            rh[r] = mapa_rank(h_local, (uint32_t)r) + hoff;
            rm[r] = mapa_rank(mb_local, (uint32_t)r);
        }
        const float* gp = gx + (size_t)t * G3H + j;
        xr = gp[0]; xz = gp[HID]; xn = gp[2 * HID];
    }

#pragma unroll 2
    for (int s = 0; s < T_LEN; s++) {
        const int b = s & 1;

        // ---- matvec: gh[row] partial over this seg's 32 h values ----
        const float* hp = hs0 + b * 288;
        unsigned long long a0 = 0ull, a1 = 0ull, a2 = 0ull, a3 = 0ull;
#pragma unroll
        for (int i = 0; i < 8; i += 2) {
            F4U h0, h1;
            h0.f4 = *(const float4*)(hp + 4 * i);
            h1.f4 = *(const float4*)(hp + 4 * i + 4);
            FMA_F32X2(a0, w[i].u[0],     h0.u[0], a0);
            FMA_F32X2(a1, w[i].u[1],     h0.u[1], a1);
            FMA_F32X2(a2, w[i + 1].u[0], h1.u[0], a2);
            FMA_F32X2(a3, w[i + 1].u[1], h1.u[1], a3);
        }
        ADD_F32X2_(a0, a0, a1);
        ADD_F32X2_(a2, a2, a3);
        ADD_F32X2_(a0, a0, a2);
        float2 pr = u2f2(a0);
        float acc = pr.x + pr.y;
        acc += __shfl_down_sync(0xffffffffu, acc, 4);
        acc += __shfl_down_sync(0xffffffffu, acc, 2);
        acc += __shfl_down_sync(0xffffffffu, acc, 1);
        if (seg == 0) gh_buf[rl] = acc + bias;
        __syncthreads();

        if (isComb) {
            const float hr = gh_buf[tid];
            const float hz = gh_buf[32 + tid];
            const float hn = gh_buf[64 + tid];
            const float r = 1.f / (1.f + __expf(-(xr + hr)));
            const float z = 1.f / (1.f + __expf(-(xz + hz)));
            const float n = tanhf(xn + r * hn);
            const float hold = *(sh_h + b * 288 + (hoff >> 2));
            const float hnew = (1.f - z) * n + z * hold;

            const uint32_t boff = (uint32_t)(b ^ 1) * 1152u;
#pragma unroll
            for (int r8 = 0; r8 < NCLUS; r8++)
                st_cluster_f32(rh[r8] + boff, hnew);
            d_h[(size_t)t * 512 + dir * HID + j] = hnew;

            __syncwarp();
            if (tid < NCLUS) mbar_arrive_rel_cluster(rm[tid]);

            // prefetch gx for next step
            if (s + 1 < T_LEN) {
                t += tstep;
                const float* gp = gx + (size_t)t * G3H + j;
                xr = gp[0]; xz = gp[HID]; xn = gp[2 * HID];
            }
        }

        mbar_wait_parity_acq_cluster(mb_local, (uint32_t)(s & 1));
    }
}

// =====================================================================
// Kernel 3: scores[t] = relu(h[t] @ Ws1^T + bs1) @ Ws2^T + bs2
// =====================================================================
#define SCORES_SMEM_FLOATS (64 * 516 + 64 + 64 + 32 * 512)
__global__ __launch_bounds__(512)
void scores_kernel(const float* __restrict__ Ws1, const float* __restrict__ bs1,
                   const float* __restrict__ Ws2, const float* __restrict__ bs2,
                   float* __restrict__ out)
{
    extern __shared__ float sm[];
    float* sW1 = sm;                  // 64 x 516 (padded, 16B-aligned rows)
    float* sW2 = sm + 64 * 516;       // 64
    float* sb1 = sW2 + 64;            // 64
    float* sh  = sb1 + 64;            // 32 x 512

    const int tid = threadIdx.x;
    for (int i = tid; i < 64 * 512; i += 512) {
        const int kk = i >> 9, jcol = i & 511;
        sW1[kk * 516 + jcol] = Ws1[i];
    }
    if (tid < 64) { sW2[tid] = Ws2[tid]; sb1[tid] = bs1[tid]; }
    const float bs2v = bs2[0];
    __syncthreads();

    const int warp = tid >> 5, lane = tid & 31;
    const float* w0p = sW1 + (size_t)lane * 516;
    const float* w1p = sW1 + (size_t)(lane + 32) * 516;

    for (int iter = 0; iter < 4; iter++) {
        const int r0 = blockIdx.x * 128 + iter * 32;
        __syncthreads();
        for (int e = tid * 4; e < 32 * 512; e += 512 * 4) {
            const int rrow = e >> 9, col = e & 511;
            *(float4*)&sh[e] = *(const float4*)&d_h[(size_t)(r0 + rrow) * 512 + col];
        }
        __syncthreads();

#pragma unroll
        for (int rr = 0; rr < 2; rr++) {
            const int rowl = warp * 2 + rr;
            const float* hrow = sh + (size_t)rowl * 512;
            unsigned long long c00 = 0ull, c01 = 0ull, c10 = 0ull, c11 = 0ull;
            for (int jc = 0; jc < 512; jc += 4) {
                F4U hv, w0v, w1v;
                hv.f4  = *(const float4*)(hrow + jc);
                w0v.f4 = *(const float4*)(w0p + jc);
                w1v.f4 = *(const float4*)(w1p + jc);
                FMA_F32X2(c00, hv.u[0], w0v.u[0], c00);
                FMA_F32X2(c01, hv.u[1], w0v.u[1], c01);
                FMA_F32X2(c10, hv.u[0], w1v.u[0], c10);
                FMA_F32X2(c11, hv.u[1], w1v.u[1], c11);
            }
            ADD_F32X2_(c00, c00, c01);
            ADD_F32X2_(c10, c10, c11);
            float2 s0 = u2f2(c00), s1 = u2f2(c10);
            const float acc0 = s0.x + s0.y;
            const float acc1 = s1.x + s1.y;
            float v = fmaxf(acc0 + sb1[lane], 0.f) * sW2[lane]
                    + fmaxf(acc1 + sb1[lane + 32], 0.f) * sW2[lane + 32];
#pragma unroll
            for (int o = 16; o; o >>= 1) v += __shfl_down_sync(0xffffffffu, v, o);
            if (lane == 0) out[2 + r0 + rowl] = v + bs2v;
        }
    }
}

// =====================================================================
// Kernel 4a: top-8 -> softmax weights -> clip_repr (1 CTA, 1024 thr)
// =====================================================================
__global__ __launch_bounds__(1024)
void topk_clip_kernel(const float* __restrict__ feat, const float* __restrict__ temp,
                      const float* __restrict__ out_scores)
{
    __shared__ float rv[1024];
    __shared__ int   ri[1024];
    __shared__ int   chosen[8];
    __shared__ float chval[8];
    __shared__ float wts[8];

    const float* scores = out_scores + 2;
    const int tid = threadIdx.x;

    float sc[16];
#pragma unroll
    for (int i = 0; i < 16; i++) sc[i] = scores[tid + (i << 10)];
    unsigned taken = 0;

    for (int k = 0; k < 8; k++) {
        float best = -3.4e38f; int bi = 0x7fffffff;
#pragma unroll
        for (int i = 0; i < 16; i++) {
            const int jg = tid + (i << 10);
            const float v = sc[i];
            if (!(taken & (1u << i)) && (v > best || (v == best && jg < bi))) {
                best = v; bi = jg;
            }
        }
        rv[tid] = best; ri[tid] = bi;
        __syncthreads();
        for (int s = 512; s; s >>= 1) {
            if (tid < s) {
                if (rv[tid + s] > rv[tid] ||
                    (rv[tid + s] == rv[tid] && ri[tid + s] < ri[tid])) {
                    rv[tid] = rv[tid + s]; ri[tid] = ri[tid + s];
                }
            }
            __syncthreads();
        }
        if (tid == 0) { chosen[k] = ri[0]; chval[k] = rv[0]; }
        __syncthreads();
        const int ck = chosen[k];
        if ((ck & 1023) == tid) taken |= 1u << (ck >> 10);
    }

    if (tid == 0) {
        const float tmp = temp[0];
        float m = chval[0];
        for (int k = 1; k < 8; k++) m = fmaxf(m, chval[k]);
        float ssum = 0.f;
        for (int k = 0; k < 8; k++) { const float e = expf((chval[k] - m) / tmp); wts[k] = e; ssum += e; }
        for (int k = 0; k < 8; k++) { wts[k] /= ssum; d_wts[k] = wts[k]; d_chosen[k] = chosen[k]; }
    }
    __syncthreads();

    for (int d = tid; d < D_IN; d += 1024) {
        float c = 0.f;
#pragma unroll
        for (int k = 0; k < 8; k++)
            c = fmaf(wts[k], feat[(size_t)chosen[k] * D_IN + d], c);
        d_clip[d] = c;
    }
}

// =====================================================================
// Kernel 4b: c1 = relu(Wc1 @ clip + bc1), 16 CTAs x 256 thr (16 thr/row)
// =====================================================================
__global__ __launch_bounds__(256)
void classify_kernel(const float* __restrict__ Wc1, const float* __restrict__ bc1)
{
    const int tid = threadIdx.x;
    const int o = blockIdx.x * 16 + (tid >> 4);
    const int part = tid & 15;
    const float* wr = Wc1 + (size_t)o * D_IN + part * 128;
    const float* cp = d_clip + part * 128;
    float s0 = 0.f, s1 = 0.f, s2 = 0.f, s3 = 0.f;
#pragma unroll
    for (int jc = 0; jc < 128; jc += 16) {
        const float4 c0 = *(const float4*)(cp + jc);
        const float4 w0 = *(const float4*)(wr + jc);
        const float4 c1v = *(const float4*)(cp + jc + 4);
        const float4 w1 = *(const float4*)(wr + jc + 4);
        const float4 c2 = *(const float4*)(cp + jc + 8);
        const float4 w2 = *(const float4*)(wr + jc + 8);
        const float4 c3 = *(const float4*)(cp + jc + 12);
        const float4 w3 = *(const float4*)(wr + jc + 12);
        s0 = fmaf(c0.x, w0.x, s0); s0 = fmaf(c0.y, w0.y, s0);
        s0 = fmaf(c0.z, w0.z, s0); s0 = fmaf(c0.w, w0.w, s0);
        s1 = fmaf(c1v.x, w1.x, s1); s1 = fmaf(c1v.y, w1.y, s1);
        s1 = fmaf(c1v.z, w1.z, s1); s1 = fmaf(c1v.w, w1.w, s1);
        s2 = fmaf(c2.x, w2.x, s2); s2 = fmaf(c2.y, w2.y, s2);
        s2 = fmaf(c2.z, w2.z, s2); s2 = fmaf(c2.w, w2.w, s2);
        s3 = fmaf(c3.x, w3.x, s3); s3 = fmaf(c3.y, w3.y, s3);
        s3 = fmaf(c3.z, w3.z, s3); s3 = fmaf(c3.w, w3.w, s3);
    }
    float s = (s0 + s1) + (s2 + s3);
    s += __shfl_down_sync(0xffffffffu, s, 8, 16);
    s += __shfl_down_sync(0xffffffffu, s, 4, 16);
    s += __shfl_down_sync(0xffffffffu, s, 2, 16);
    s += __shfl_down_sync(0xffffffffu, s, 1, 16);
    if (part == 0) d_c1[o] = fmaxf(s + bc1[o], 0.f);
}

// =====================================================================
// Kernel 4c: logits = c1 @ Wc2^T + bc2 (1 CTA, 64 thr)
// =====================================================================
__global__ __launch_bounds__(64)
void logits_kernel(const float* __restrict__ Wc2, const float* __restrict__ bc2,
                   float* __restrict__ out)
{
    const int tid = threadIdx.x;
    const int c = tid >> 5, lane = tid & 31;
    float s = 0.f;
    for (int kk = lane; kk < 256; kk += 32)
        s = fmaf(d_c1[kk], Wc2[(size_t)c * 256 + kk], s);
#pragma unroll
    for (int o = 16; o; o >>= 1) s += __shfl_down_sync(0xffffffffu, s, o);
    if (lane == 0) out[c] = s + bc2[c];
}

// =====================================================================
extern "C" void kernel_launch(void* const* d_in, const int* in_sizes, int n_in,
                              void* d_out, int out_size)
{
    const float* feat   = (const float*)d_in[0];
    const float* temp   = (const float*)d_in[1];
    const float* W_ih_f = (const float*)d_in[2];
    const float* W_hh_f = (const float*)d_in[3];
    const float* b_ih_f = (const float*)d_in[4];
    const float* b_hh_f = (const float*)d_in[5];
    const float* W_ih_b = (const float*)d_in[6];
    const float* W_hh_b = (const float*)d_in[7];
    const float* b_ih_b = (const float*)d_in[8];
    const float* b_hh_b = (const float*)d_in[9];
    const float* Ws1    = (const float*)d_in[10];
    const float* bs1    = (const float*)d_in[11];
    const float* Ws2    = (const float*)d_in[12];
    const float* bs2    = (const float*)d_in[13];
    const float* Wc1    = (const float*)d_in[14];
    const float* bc1    = (const float*)d_in[15];
    const float* Wc2    = (const float*)d_in[16];
    const float* bc2    = (const float*)d_in[17];
    float* out = (float*)d_out;

    // 1) input projections (both directions)
    gemm_gx_kernel<<<dim3(12, 128, 2), 256>>>(feat, W_ih_f, b_ih_f, W_ih_b, b_ih_b);

    // 2) BiGRU scan: 2 clusters of 8 CTAs
    scan_kernel<<<16, SCAN_THREADS>>>(W_hh_f, b_hh_f, W_hh_b, b_hh_b);

    // 3) frame scores
    cudaFuncSetAttribute(scores_kernel, cudaFuncAttributeMaxDynamicSharedMemorySize,
                         SCORES_SMEM_FLOATS * 4);
    scores_kernel<<<128, 512, SCORES_SMEM_FLOATS * 4>>>(Ws1, bs1, Ws2, bs2, out);

    // 4) top-k + softmax + weighted sum + classifier
    topk_clip_kernel<<<1, 1024>>>(feat, temp, out);
    classify_kernel<<<16, 256>>>(Wc1, bc1);
    logits_kernel<<<1, 64>>>(Wc2, bc2, out);
}

// round 9
// speedup vs baseline: 1.2766x; 1.0511x over previous
#include <cuda_runtime.h>
#include <cstdint>
#include <math.h>

#define T_LEN 16384
#define D_IN  2048
#define HID   256
#define G3H   768
#define NCLUS 8
#define SCAN_THREADS 768

// ---------------- device scratch (static, no allocation) ----------------
__device__ float d_gx[2][(size_t)T_LEN * G3H];   // input projections, both dirs
__device__ float d_h[(size_t)T_LEN * 512];       // concat(h_f, h_b)
__device__ float d_clip[D_IN];
__device__ float d_wts[8];
__device__ int   d_chosen[8];
__device__ float d_c1[256];

// ---------------- helpers ----------------
union F4U { float4 f4; unsigned long long u[2]; float f[4]; float2 f2[2]; };

#define FMA_F32X2(d, a, b, c) \
    asm("fma.rn.f32x2 %0, %1, %2, %3;" : "=l"(d) : "l"(a), "l"(b), "l"(c))
#define ADD_F32X2_(d, a, b) \
    asm("add.rn.f32x2 %0, %1, %2;" : "=l"(d) : "l"(a), "l"(b))
#define PACKF2(u, x, y) \
    asm("mov.b64 %0, {%1, %2};" : "=l"(u) : "f"(x), "f"(y))

__device__ __forceinline__ float2 u2f2(unsigned long long u) {
    float2 r; asm("mov.b64 {%0, %1}, %2;" : "=f"(r.x), "=f"(r.y) : "l"(u)); return r;
}
__device__ __forceinline__ uint32_t smem_u32(const void* p) {
    return (uint32_t)__cvta_generic_to_shared(p);
}
__device__ __forceinline__ uint32_t mapa_rank(uint32_t addr, uint32_t rank) {
    uint32_t d;
    asm("mapa.shared::cluster.u32 %0, %1, %2;" : "=r"(d) : "r"(addr), "r"(rank));
    return d;
}
__device__ __forceinline__ void st_cluster_f32(uint32_t addr, float v) {
    asm volatile("st.shared::cluster.f32 [%0], %1;" :: "r"(addr), "f"(v) : "memory");
}
__device__ __forceinline__ void mbar_init(uint32_t addr, uint32_t cnt) {
    asm volatile("mbarrier.init.shared.b64 [%0], %1;" :: "r"(addr), "r"(cnt) : "memory");
}
__device__ __forceinline__ void mbar_arrive_rel_cluster(uint32_t addr) {
    asm volatile("mbarrier.arrive.release.cluster.shared::cluster.b64 _, [%0];"
                 :: "r"(addr) : "memory");
}
__device__ __forceinline__ void mbar_wait_parity_acq_cluster(uint32_t addr, uint32_t par) {
    asm volatile(
        "{\n\t.reg .pred P;\n\t"
        "W%=:\n\t"
        "mbarrier.try_wait.parity.acquire.cluster.shared::cta.b64 P, [%0], %1, 0x989680;\n\t"
        "@P bra D%=;\n\t"
        "bra W%=;\n\t"
        "D%=:\n\t}"
        :: "r"(addr), "r"(par) : "memory");
}
// fast sigmoid / tanh (MUFU-based, ~1e-7 rel err)
__device__ __forceinline__ float fast_sigmoid(float x) {
    return __fdividef(1.f, 1.f + __expf(-x));
}
__device__ __forceinline__ float fast_tanh(float x) {
    return __fdividef(2.f, 1.f + __expf(-2.f * x)) - 1.f;
}

// =====================================================================
// Kernel 1: gx[dir] = feat @ W_ih[dir]^T + b_ih[dir]
// 128x64 tile, BK=16, 256 threads, 8x4 per thread, f32x2 packed FMA.
// =====================================================================
__global__ __launch_bounds__(256)
void gemm_gx_kernel(const float* __restrict__ feat,
                    const float* __restrict__ Wf, const float* __restrict__ bf,
                    const float* __restrict__ Wb, const float* __restrict__ bb)
{
    const int dir = blockIdx.z;
    const float* __restrict__ W    = dir ? Wb : Wf;
    const float* __restrict__ bias = dir ? bb : bf;
    float* __restrict__ C = d_gx[dir];

    const int t0 = blockIdx.y * 128;
    const int o0 = blockIdx.x * 64;

    __shared__ float As[16][132];
    __shared__ float Bs[16][68];

    const int tid = threadIdx.x;
    const int tx = tid & 15, ty = tid >> 4;
    const int m0 = ty * 8, n0 = tx * 4;

    const int ar0 = tid >> 2;
    const int akq = (tid & 3) * 4;

    const float* aptr0 = feat + (size_t)(t0 + ar0)      * D_IN + akq;
    const float* aptr1 = feat + (size_t)(t0 + ar0 + 64) * D_IN + akq;
    const float* bptr  = W    + (size_t)(o0 + ar0)      * D_IN + akq;

    float4 pa0 = *(const float4*)(aptr0);
    float4 pa1 = *(const float4*)(aptr1);
    float4 pb  = *(const float4*)(bptr);

    unsigned long long acc2[4][4];
#pragma unroll
    for (int i = 0; i < 4; i++)
#pragma unroll
        for (int j = 0; j < 4; j++) acc2[i][j] = 0ull;

    for (int kt = 0; kt < D_IN; kt += 16) {
        As[akq + 0][ar0] = pa0.x; As[akq + 1][ar0] = pa0.y;
        As[akq + 2][ar0] = pa0.z; As[akq + 3][ar0] = pa0.w;
        As[akq + 0][ar0 + 64] = pa1.x; As[akq + 1][ar0 + 64] = pa1.y;
        As[akq + 2][ar0 + 64] = pa1.z; As[akq + 3][ar0 + 64] = pa1.w;
        Bs[akq + 0][ar0] = pb.x; Bs[akq + 1][ar0] = pb.y;
        Bs[akq + 2][ar0] = pb.z; Bs[akq + 3][ar0] = pb.w;
        __syncthreads();

        if (kt + 16 < D_IN) {
            pa0 = *(const float4*)(aptr0 + kt + 16);
            pa1 = *(const float4*)(aptr1 + kt + 16);
            pb  = *(const float4*)(bptr  + kt + 16);
        }

#pragma unroll
        for (int k = 0; k < 16; k++) {
            F4U a0, a1, b;
            a0.f4 = *(const float4*)&As[k][m0];
            a1.f4 = *(const float4*)&As[k][m0 + 4];
            b.f4  = *(const float4*)&Bs[k][n0];
            unsigned long long a2[4] = {a0.u[0], a0.u[1], a1.u[0], a1.u[1]};
            unsigned long long bd[4];
            PACKF2(bd[0], b.f[0], b.f[0]);
            PACKF2(bd[1], b.f[1], b.f[1]);
            PACKF2(bd[2], b.f[2], b.f[2]);
            PACKF2(bd[3], b.f[3], b.f[3]);
#pragma unroll
            for (int i = 0; i < 4; i++)
#pragma unroll
                for (int j = 0; j < 4; j++)
                    FMA_F32X2(acc2[i][j], a2[i], bd[j], acc2[i][j]);
        }
        __syncthreads();
    }

    const float4 bv4 = *(const float4*)&bias[o0 + n0];
#pragma unroll
    for (int i2 = 0; i2 < 4; i2++) {
        float2 p0 = u2f2(acc2[i2][0]);
        float2 p1 = u2f2(acc2[i2][1]);
        float2 p2 = u2f2(acc2[i2][2]);
        float2 p3 = u2f2(acc2[i2][3]);
        float4 v0, v1;
        v0.x = p0.x + bv4.x; v0.y = p1.x + bv4.y; v0.z = p2.x + bv4.z; v0.w = p3.x + bv4.w;
        v1.x = p0.y + bv4.x; v1.y = p1.y + bv4.y; v1.z = p2.y + bv4.z; v1.w = p3.y + bv4.w;
        *(float4*)&C[(size_t)(t0 + m0 + 2 * i2 + 0) * G3H + o0 + n0] = v0;
        *(float4*)&C[(size_t)(t0 + m0 + 2 * i2 + 1) * G3H + o0 + n0] = v1;
    }
}

// =====================================================================
// Kernel 2: BiGRU scan. Grid = 16 CTAs = 2 clusters of 8 (dir = blk/8).
// CTA rank owns j in [32*rank, 32*rank+32) and its 3 gate rows.
// Per step:
//   matvec (f32x2, W in regs) -> shfl reduce -> seg0 STS gh_buf[b] ->
//   __syncthreads -> warps 0..7 EACH redundantly compute the 32 new h
//   values; warp w DSMEM-stores them to rank w only (double-buffered h)
//   and release-arrives on rank w's mbarrier (one store-drain per warp) ->
//   all threads acquire-wait local mbarrier parity (count=8).
// =====================================================================
__global__ void __cluster_dims__(NCLUS, 1, 1) __launch_bounds__(SCAN_THREADS, 1)
scan_kernel(const float* __restrict__ Whf, const float* __restrict__ bhf,
            const float* __restrict__ Whb, const float* __restrict__ bhb)
{
    // padded h: idx(k) = k + (k>>5)*4 ; buffer stride 288 floats
    __shared__ float sh_h[2 * 288];
    __shared__ float gh_buf[2][96];
    __shared__ __align__(8) unsigned long long mbar;

    const int rank = blockIdx.x & 7;
    const int dir  = blockIdx.x >> 3;
    const float* __restrict__ Whh = dir ? Whb : Whf;
    const float* __restrict__ bhh = dir ? bhb : bhf;
    const float* __restrict__ gx  = d_gx[dir];

    const int tid = threadIdx.x;
    const int rl  = tid >> 3;          // 0..95 local row
    const int seg = tid & 7;           // 0..7
    const int g   = rl >> 5;           // gate 0..2 (r,z,n)
    const int jj  = rl & 31;
    const int row = (g << 8) + (rank << 5) + jj;   // 256*g + 32*rank + jj

    // weights in registers: 32 floats = 8 float4 = 16 f32x2
    F4U w[8];
    const float4* wp = (const float4*)(Whh + (size_t)row * HID + seg * 32);
#pragma unroll
    for (int i = 0; i < 8; i++) w[i].f4 = wp[i];
    const float bias = bhh[row];

    for (int i = tid; i < 2 * 288; i += SCAN_THREADS) sh_h[i] = 0.f;
    const uint32_t mb_local = smem_u32(&mbar);
    if (tid == 0) mbar_init(mb_local, NCLUS);
    __syncthreads();
    asm volatile("barrier.cluster.arrive.aligned;" ::: "memory");
    asm volatile("barrier.cluster.wait.aligned;" ::: "memory");

    const float* hs0 = sh_h + 36 * seg;

    // combine warps: warps 0..7, warp cw targets remote rank cw.
    const bool isComb = (tid < 256);
    const int  cw     = tid >> 5;                  // target rank for this warp
    const int  lane   = tid & 31;
    const int  j      = (rank << 5) + lane;        // this CTA's owned j
    const uint32_t hword = (uint32_t)(36 * rank + lane);  // padded word index
    uint32_t rh = 0, rm = 0;
    float xr = 0.f, xz = 0.f, xn = 0.f;
    int t = dir ? (T_LEN - 1) : 0;
    const int tstep = dir ? -1 : 1;
    if (isComb) {
        rh = mapa_rank(smem_u32(&sh_h[0]), (uint32_t)cw) + hword * 4u;
        rm = mapa_rank(mb_local, (uint32_t)cw);
        const float* gp = gx + (size_t)t * G3H + j;
        xr = gp[0]; xz = gp[HID]; xn = gp[2 * HID];
    }

#pragma unroll 2
    for (int s = 0; s < T_LEN; s++) {
        const int b = s & 1;

        // ---- matvec: gh[row] partial over this seg's 32 h values ----
        const float* hp = hs0 + b * 288;
        unsigned long long a0 = 0ull, a1 = 0ull, a2 = 0ull, a3 = 0ull;
#pragma unroll
        for (int i = 0; i < 8; i += 2) {
            F4U h0, h1;
            h0.f4 = *(const float4*)(hp + 4 * i);
            h1.f4 = *(const float4*)(hp + 4 * i + 4);
            FMA_F32X2(a0, w[i].u[0],     h0.u[0], a0);
            FMA_F32X2(a1, w[i].u[1],     h0.u[1], a1);
            FMA_F32X2(a2, w[i + 1].u[0], h1.u[0], a2);
            FMA_F32X2(a3, w[i + 1].u[1], h1.u[1], a3);
        }
        ADD_F32X2_(a0, a0, a1);
        ADD_F32X2_(a2, a2, a3);
        ADD_F32X2_(a0, a0, a2);
        float2 pr = u2f2(a0);
        float acc = pr.x + pr.y;
        acc += __shfl_down_sync(0xffffffffu, acc, 4);
        acc += __shfl_down_sync(0xffffffffu, acc, 2);
        acc += __shfl_down_sync(0xffffffffu, acc, 1);
        if (seg == 0) gh_buf[b][rl] = acc + bias;
        __syncthreads();

        if (isComb) {
            // redundant gate combine (identical in warps 0..7)
            const float hr = gh_buf[b][lane];
            const float hz = gh_buf[b][32 + lane];
            const float hn = gh_buf[b][64 + lane];
            const float r = fast_sigmoid(xr + hr);
            const float z = fast_sigmoid(xz + hz);
            const float n = fast_tanh(xn + r * hn);
            const float hold = sh_h[b * 288 + hword];
            const float hnew = (1.f - z) * n + z * hold;

            // warp cw ships the 32 new h values to rank cw (one target each)
            st_cluster_f32(rh + (uint32_t)(b ^ 1) * 1152u, hnew);
            if (cw == 0) d_h[(size_t)t * 512 + dir * HID + j] = hnew;

            __syncwarp();
            if (lane == 0) mbar_arrive_rel_cluster(rm);

            // prefetch gx for next step (off critical path; L1-shared)
            if (s + 1 < T_LEN) {
                t += tstep;
                const float* gp = gx + (size_t)t * G3H + j;
                xr = gp[0]; xz = gp[HID]; xn = gp[2 * HID];
            }
        }

        mbar_wait_parity_acq_cluster(mb_local, (uint32_t)b);
    }
}

// =====================================================================
// Kernel 3: scores[t] = relu(h[t] @ Ws1^T + bs1) @ Ws2^T + bs2
// =====================================================================
#define SCORES_SMEM_FLOATS (64 * 516 + 64 + 64 + 32 * 512)
__global__ __launch_bounds__(512)
void scores_kernel(const float* __restrict__ Ws1, const float* __restrict__ bs1,
                   const float* __restrict__ Ws2, const float* __restrict__ bs2,
                   float* __restrict__ out)
{
    extern __shared__ float sm[];
    float* sW1 = sm;                  // 64 x 516 (padded, 16B-aligned rows)
    float* sW2 = sm + 64 * 516;       // 64
    float* sb1 = sW2 + 64;            // 64
    float* sh  = sb1 + 64;            // 32 x 512

    const int tid = threadIdx.x;
    for (int i = tid; i < 64 * 512; i += 512) {
        const int kk = i >> 9, jcol = i & 511;
        sW1[kk * 516 + jcol] = Ws1[i];
    }
    if (tid < 64) { sW2[tid] = Ws2[tid]; sb1[tid] = bs1[tid]; }
    const float bs2v = bs2[0];
    __syncthreads();

    const int warp = tid >> 5, lane = tid & 31;
    const float* w0p = sW1 + (size_t)lane * 516;
    const float* w1p = sW1 + (size_t)(lane + 32) * 516;

    for (int iter = 0; iter < 4; iter++) {
        const int r0 = blockIdx.x * 128 + iter * 32;
        __syncthreads();
        for (int e = tid * 4; e < 32 * 512; e += 512 * 4) {
            const int rrow = e >> 9, col = e & 511;
            *(float4*)&sh[e] = *(const float4*)&d_h[(size_t)(r0 + rrow) * 512 + col];
        }
        __syncthreads();

#pragma unroll
        for (int rr = 0; rr < 2; rr++) {
            const int rowl = warp * 2 + rr;
            const float* hrow = sh + (size_t)rowl * 512;
            unsigned long long c00 = 0ull, c01 = 0ull, c10 = 0ull, c11 = 0ull;
            for (int jc = 0; jc < 512; jc += 4) {
                F4U hv, w0v, w1v;
                hv.f4  = *(const float4*)(hrow + jc);
                w0v.f4 = *(const float4*)(w0p + jc);
                w1v.f4 = *(const float4*)(w1p + jc);
                FMA_F32X2(c00, hv.u[0], w0v.u[0], c00);
                FMA_F32X2(c01, hv.u[1], w0v.u[1], c01);
                FMA_F32X2(c10, hv.u[0], w1v.u[0], c10);
                FMA_F32X2(c11, hv.u[1], w1v.u[1], c11);
            }
            ADD_F32X2_(c00, c00, c01);
            ADD_F32X2_(c10, c10, c11);
            float2 s0 = u2f2(c00), s1 = u2f2(c10);
            const float acc0 = s0.x + s0.y;
            const float acc1 = s1.x + s1.y;
            float v = fmaxf(acc0 + sb1[lane], 0.f) * sW2[lane]
                    + fmaxf(acc1 + sb1[lane + 32], 0.f) * sW2[lane + 32];
#pragma unroll
            for (int o = 16; o; o >>= 1) v += __shfl_down_sync(0xffffffffu, v, o);
            if (lane == 0) out[2 + r0 + rowl] = v + bs2v;
        }
    }
}

// =====================================================================
// Kernel 4a: top-8 -> softmax weights -> clip_repr (1 CTA, 1024 thr)
// =====================================================================
__global__ __launch_bounds__(1024)
void topk_clip_kernel(const float* __restrict__ feat, const float* __restrict__ temp,
                      const float* __restrict__ out_scores)
{
    __shared__ float rv[1024];
    __shared__ int   ri[1024];
    __shared__ int   chosen[8];
    __shared__ float chval[8];
    __shared__ float wts[8];

    const float* scores = out_scores + 2;
    const int tid = threadIdx.x;

    float sc[16];
#pragma unroll
    for (int i = 0; i < 16; i++) sc[i] = scores[tid + (i << 10)];
    unsigned taken = 0;

    for (int k = 0; k < 8; k++) {
        float best = -3.4e38f; int bi = 0x7fffffff;
#pragma unroll
        for (int i = 0; i < 16; i++) {
            const int jg = tid + (i << 10);
            const float v = sc[i];
            if (!(taken & (1u << i)) && (v > best || (v == best && jg < bi))) {
                best = v; bi = jg;
            }
        }
        rv[tid] = best; ri[tid] = bi;
        __syncthreads();
        for (int s = 512; s; s >>= 1) {
            if (tid < s) {
                if (rv[tid + s] > rv[tid] ||
                    (rv[tid + s] == rv[tid] && ri[tid + s] < ri[tid])) {
                    rv[tid] = rv[tid + s]; ri[tid] = ri[tid + s];
                }
            }
            __syncthreads();
        }
        if (tid == 0) { chosen[k] = ri[0]; chval[k] = rv[0]; }
        __syncthreads();
        const int ck = chosen[k];
        if ((ck & 1023) == tid) taken |= 1u << (ck >> 10);
    }

    if (tid == 0) {
        const float tmp = temp[0];
        float m = chval[0];
        for (int k = 1; k < 8; k++) m = fmaxf(m, chval[k]);
        float ssum = 0.f;
        for (int k = 0; k < 8; k++) { const float e = expf((chval[k] - m) / tmp); wts[k] = e; ssum += e; }
        for (int k = 0; k < 8; k++) { wts[k] /= ssum; d_wts[k] = wts[k]; d_chosen[k] = chosen[k]; }
    }
    __syncthreads();

    for (int d = tid; d < D_IN; d += 1024) {
        float c = 0.f;
#pragma unroll
        for (int k = 0; k < 8; k++)
            c = fmaf(wts[k], feat[(size_t)chosen[k] * D_IN + d], c);
        d_clip[d] = c;
    }
}

// =====================================================================
// Kernel 4b: c1 = relu(Wc1 @ clip + bc1), 16 CTAs x 256 thr (16 thr/row)
// =====================================================================
__global__ __launch_bounds__(256)
void classify_kernel(const float* __restrict__ Wc1, const float* __restrict__ bc1)
{
    const int tid = threadIdx.x;
    const int o = blockIdx.x * 16 + (tid >> 4);
    const int part = tid & 15;
    const float* wr = Wc1 + (size_t)o * D_IN + part * 128;
    const float* cp = d_clip + part * 128;
    float s0 = 0.f, s1 = 0.f, s2 = 0.f, s3 = 0.f;
#pragma unroll
    for (int jc = 0; jc < 128; jc += 16) {
        const float4 c0 = *(const float4*)(cp + jc);
        const float4 w0 = *(const float4*)(wr + jc);
        const float4 c1v = *(const float4*)(cp + jc + 4);
        const float4 w1 = *(const float4*)(wr + jc + 4);
        const float4 c2 = *(const float4*)(cp + jc + 8);
        const float4 w2 = *(const float4*)(wr + jc + 8);
        const float4 c3 = *(const float4*)(cp + jc + 12);
        const float4 w3 = *(const float4*)(wr + jc + 12);
        s0 = fmaf(c0.x, w0.x, s0); s0 = fmaf(c0.y, w0.y, s0);
        s0 = fmaf(c0.z, w0.z, s0); s0 = fmaf(c0.w, w0.w, s0);
        s1 = fmaf(c1v.x, w1.x, s1); s1 = fmaf(c1v.y, w1.y, s1);
        s1 = fmaf(c1v.z, w1.z, s1); s1 = fmaf(c1v.w, w1.w, s1);
        s2 = fmaf(c2.x, w2.x, s2); s2 = fmaf(c2.y, w2.y, s2);
        s2 = fmaf(c2.z, w2.z, s2); s2 = fmaf(c2.w, w2.w, s2);
        s3 = fmaf(c3.x, w3.x, s3); s3 = fmaf(c3.y, w3.y, s3);
        s3 = fmaf(c3.z, w3.z, s3); s3 = fmaf(c3.w, w3.w, s3);
    }
    float s = (s0 + s1) + (s2 + s3);
    s += __shfl_down_sync(0xffffffffu, s, 8, 16);
    s += __shfl_down_sync(0xffffffffu, s, 4, 16);
    s += __shfl_down_sync(0xffffffffu, s, 2, 16);
    s += __shfl_down_sync(0xffffffffu, s, 1, 16);
    if (part == 0) d_c1[o] = fmaxf(s + bc1[o], 0.f);
}

// =====================================================================
// Kernel 4c: logits = c1 @ Wc2^T + bc2 (1 CTA, 64 thr)
// =====================================================================
__global__ __launch_bounds__(64)
void logits_kernel(const float* __restrict__ Wc2, const float* __restrict__ bc2,
                   float* __restrict__ out)
{
    const int tid = threadIdx.x;
    const int c = tid >> 5, lane = tid & 31;
    float s = 0.f;
    for (int kk = lane; kk < 256; kk += 32)
        s = fmaf(d_c1[kk], Wc2[(size_t)c * 256 + kk], s);
#pragma unroll
    for (int o = 16; o; o >>= 1) s += __shfl_down_sync(0xffffffffu, s, o);
    if (lane == 0) out[c] = s + bc2[c];
}

// =====================================================================
extern "C" void kernel_launch(void* const* d_in, const int* in_sizes, int n_in,
                              void* d_out, int out_size)
{
    const float* feat   = (const float*)d_in[0];
    const float* temp   = (const float*)d_in[1];
    const float* W_ih_f = (const float*)d_in[2];
    const float* W_hh_f = (const float*)d_in[3];
    const float* b_ih_f = (const float*)d_in[4];
    const float* b_hh_f = (const float*)d_in[5];
    const float* W_ih_b = (const float*)d_in[6];
    const float* W_hh_b = (const float*)d_in[7];
    const float* b_ih_b = (const float*)d_in[8];
    const float* b_hh_b = (const float*)d_in[9];
    const float* Ws1    = (const float*)d_in[10];
    const float* bs1    = (const float*)d_in[11];
    const float* Ws2    = (const float*)d_in[12];
    const float* bs2    = (const float*)d_in[13];
    const float* Wc1    = (const float*)d_in[14];
    const float* bc1    = (const float*)d_in[15];
    const float* Wc2    = (const float*)d_in[16];
    const float* bc2    = (const float*)d_in[17];
    float* out = (float*)d_out;

    // 1) input projections (both directions)
    gemm_gx_kernel<<<dim3(12, 128, 2), 256>>>(feat, W_ih_f, b_ih_f, W_ih_b, b_ih_b);

    // 2) BiGRU scan: 2 clusters of 8 CTAs
    scan_kernel<<<16, SCAN_THREADS>>>(W_hh_f, b_hh_f, W_hh_b, b_hh_b);

    // 3) frame scores
    cudaFuncSetAttribute(scores_kernel, cudaFuncAttributeMaxDynamicSharedMemorySize,
                         SCORES_SMEM_FLOATS * 4);
    scores_kernel<<<128, 512, SCORES_SMEM_FLOATS * 4>>>(Ws1, bs1, Ws2, bs2, out);

    // 4) top-k + softmax + weighted sum + classifier
    topk_clip_kernel<<<1, 1024>>>(feat, temp, out);
    classify_kernel<<<16, 256>>>(Wc1, bc1);
    logits_kernel<<<1, 64>>>(Wc2, bc2, out);
}

// round 10
// speedup vs baseline: 1.3330x; 1.0441x over previous
#include <cuda_runtime.h>
#include <cstdint>
#include <math.h>

#define T_LEN 16384
#define D_IN  2048
#define HID   256
#define G3H   768
#define NCLUS 8
#define SCAN_THREADS 384

// ---------------- device scratch (static, no allocation) ----------------
__device__ float d_gx[2][(size_t)T_LEN * G3H];   // input projections, both dirs
__device__ float d_h[(size_t)T_LEN * 512];       // concat(h_f, h_b)
__device__ float d_clip[D_IN];
__device__ float d_wts[8];
__device__ int   d_chosen[8];
__device__ float d_c1[256];

// ---------------- helpers ----------------
union F4U { float4 f4; unsigned long long u[2]; float f[4]; float2 f2[2]; };

#define FMA_F32X2(d, a, b, c) \
    asm("fma.rn.f32x2 %0, %1, %2, %3;" : "=l"(d) : "l"(a), "l"(b), "l"(c))
#define ADD_F32X2_(d, a, b) \
    asm("add.rn.f32x2 %0, %1, %2;" : "=l"(d) : "l"(a), "l"(b))
#define PACKF2(u, x, y) \
    asm("mov.b64 %0, {%1, %2};" : "=l"(u) : "f"(x), "f"(y))

__device__ __forceinline__ float2 u2f2(unsigned long long u) {
    float2 r; asm("mov.b64 {%0, %1}, %2;" : "=f"(r.x), "=f"(r.y) : "l"(u)); return r;
}
__device__ __forceinline__ uint32_t smem_u32(const void* p) {
    return (uint32_t)__cvta_generic_to_shared(p);
}
__device__ __forceinline__ uint32_t mapa_rank(uint32_t addr, uint32_t rank) {
    uint32_t d;
    asm("mapa.shared::cluster.u32 %0, %1, %2;" : "=r"(d) : "r"(addr), "r"(rank));
    return d;
}
__device__ __forceinline__ void st_cluster_f32(uint32_t addr, float v) {
    asm volatile("st.shared::cluster.f32 [%0], %1;" :: "r"(addr), "f"(v) : "memory");
}
__device__ __forceinline__ void mbar_init(uint32_t addr, uint32_t cnt) {
    asm volatile("mbarrier.init.shared.b64 [%0], %1;" :: "r"(addr), "r"(cnt) : "memory");
}
__device__ __forceinline__ void mbar_arrive_rel_cluster(uint32_t addr) {
    asm volatile("mbarrier.arrive.release.cluster.shared::cluster.b64 _, [%0];"
                 :: "r"(addr) : "memory");
}
// RELAXED wait: no acquire fence. Remote DSMEM stores are ordered by the
// producer's release-arrive and land directly in this CTA's SMEM (no local
// cache), so observing the parity flip suffices before plain LDS reads.
__device__ __forceinline__ void mbar_wait_parity_relaxed(uint32_t addr, uint32_t par) {
    asm volatile(
        "{\n\t.reg .pred P;\n\t"
        "W%=:\n\t"
        "mbarrier.try_wait.parity.relaxed.cta.shared::cta.b64 P, [%0], %1, 0x989680;\n\t"
        "@P bra D%=;\n\t"
        "bra W%=;\n\t"
        "D%=:\n\t}"
        :: "r"(addr), "r"(par) : "memory");
}
// fast sigmoid / tanh (MUFU-based, ~1e-7 rel err)
__device__ __forceinline__ float fast_sigmoid(float x) {
    return __fdividef(1.f, 1.f + __expf(-x));
}
__device__ __forceinline__ float fast_tanh(float x) {
    return __fdividef(2.f, 1.f + __expf(-2.f * x)) - 1.f;
}

// =====================================================================
// Kernel 1: gx[dir] = feat @ W_ih[dir]^T + b_ih[dir]
// 128x64 tile, BK=16, 256 threads, 8x4 per thread, f32x2 packed FMA.
// =====================================================================
__global__ __launch_bounds__(256)
void gemm_gx_kernel(const float* __restrict__ feat,
                    const float* __restrict__ Wf, const float* __restrict__ bf,
                    const float* __restrict__ Wb, const float* __restrict__ bb)
{
    const int dir = blockIdx.z;
    const float* __restrict__ W    = dir ? Wb : Wf;
    const float* __restrict__ bias = dir ? bb : bf;
    float* __restrict__ C = d_gx[dir];

    const int t0 = blockIdx.y * 128;
    const int o0 = blockIdx.x * 64;

    __shared__ float As[16][132];
    __shared__ float Bs[16][68];

    const int tid = threadIdx.x;
    const int tx = tid & 15, ty = tid >> 4;
    const int m0 = ty * 8, n0 = tx * 4;

    const int ar0 = tid >> 2;
    const int akq = (tid & 3) * 4;

    const float* aptr0 = feat + (size_t)(t0 + ar0)      * D_IN + akq;
    const float* aptr1 = feat + (size_t)(t0 + ar0 + 64) * D_IN + akq;
    const float* bptr  = W    + (size_t)(o0 + ar0)      * D_IN + akq;

    float4 pa0 = *(const float4*)(aptr0);
    float4 pa1 = *(const float4*)(aptr1);
    float4 pb  = *(const float4*)(bptr);

    unsigned long long acc2[4][4];
#pragma unroll
    for (int i = 0; i < 4; i++)
#pragma unroll
        for (int j = 0; j < 4; j++) acc2[i][j] = 0ull;

    for (int kt = 0; kt < D_IN; kt += 16) {
        As[akq + 0][ar0] = pa0.x; As[akq + 1][ar0] = pa0.y;
        As[akq + 2][ar0] = pa0.z; As[akq + 3][ar0] = pa0.w;
        As[akq + 0][ar0 + 64] = pa1.x; As[akq + 1][ar0 + 64] = pa1.y;
        As[akq + 2][ar0 + 64] = pa1.z; As[akq + 3][ar0 + 64] = pa1.w;
        Bs[akq + 0][ar0] = pb.x; Bs[akq + 1][ar0] = pb.y;
        Bs[akq + 2][ar0] = pb.z; Bs[akq + 3][ar0] = pb.w;
        __syncthreads();

        if (kt + 16 < D_IN) {
            pa0 = *(const float4*)(aptr0 + kt + 16);
            pa1 = *(const float4*)(aptr1 + kt + 16);
            pb  = *(const float4*)(bptr  + kt + 16);
        }

#pragma unroll
        for (int k = 0; k < 16; k++) {
            F4U a0, a1, b;
            a0.f4 = *(const float4*)&As[k][m0];
            a1.f4 = *(const float4*)&As[k][m0 + 4];
            b.f4  = *(const float4*)&Bs[k][n0];
            unsigned long long a2[4] = {a0.u[0], a0.u[1], a1.u[0], a1.u[1]};
            unsigned long long bd[4];
            PACKF2(bd[0], b.f[0], b.f[0]);
            PACKF2(bd[1], b.f[1], b.f[1]);
            PACKF2(bd[2], b.f[2], b.f[2]);
            PACKF2(bd[3], b.f[3], b.f[3]);
#pragma unroll
            for (int i = 0; i < 4; i++)
#pragma unroll
                for (int j = 0; j < 4; j++)
                    FMA_F32X2(acc2[i][j], a2[i], bd[j], acc2[i][j]);
        }
        __syncthreads();
    }

    const float4 bv4 = *(const float4*)&bias[o0 + n0];
#pragma unroll
    for (int i2 = 0; i2 < 4; i2++) {
        float2 p0 = u2f2(acc2[i2][0]);
        float2 p1 = u2f2(acc2[i2][1]);
        float2 p2 = u2f2(acc2[i2][2]);
        float2 p3 = u2f2(acc2[i2][3]);
        float4 v0, v1;
        v0.x = p0.x + bv4.x; v0.y = p1.x + bv4.y; v0.z = p2.x + bv4.z; v0.w = p3.x + bv4.w;
        v1.x = p0.y + bv4.x; v1.y = p1.y + bv4.y; v1.z = p2.y + bv4.z; v1.w = p3.y + bv4.w;
        *(float4*)&C[(size_t)(t0 + m0 + 2 * i2 + 0) * G3H + o0 + n0] = v0;
        *(float4*)&C[(size_t)(t0 + m0 + 2 * i2 + 1) * G3H + o0 + n0] = v1;
    }
}

// =====================================================================
// Kernel 2: BiGRU scan. Grid = 16 CTAs = 2 clusters of 8 (dir = blk/8).
// 384 threads/CTA (12 warps). CTA rank owns j in [32r, 32r+32) and its
// 3 gate rows (96 rows). Each row split over 4 segs of 64 h (32 FMA2).
// Per step: matvec -> 2-shfl reduce -> seg0 STS gh -> bar -> warps 0..7
// redundantly combine the 32 gates (hold in regs); warp w ships h to
// rank w (double-buffered sh_h) + release-arrive on rank w's mbarrier ->
// RELAXED parity wait (count=8).
// =====================================================================
__global__ void __cluster_dims__(NCLUS, 1, 1) __launch_bounds__(SCAN_THREADS, 1)
scan_kernel(const float* __restrict__ Whf, const float* __restrict__ bhf,
            const float* __restrict__ Whb, const float* __restrict__ bhb)
{
    // padded h: idx(k) = k + (k>>6)*8 ; buffer stride 288 floats
    __shared__ __align__(16) float sh_h[2 * 288];
    __shared__ float gh_buf[2][96];
    __shared__ __align__(8) unsigned long long mbar;

    const int rank = blockIdx.x & 7;
    const int dir  = blockIdx.x >> 3;
    const float* __restrict__ Whh = dir ? Whb : Whf;
    const float* __restrict__ bhh = dir ? bhb : bhf;
    const float* __restrict__ gx  = d_gx[dir];

    const int tid = threadIdx.x;
    const int rl  = tid >> 2;          // 0..95 local row
    const int seg = tid & 3;           // 0..3
    const int g   = rl >> 5;           // gate 0..2 (r,z,n)
    const int jj  = rl & 31;
    const int row = (g << 8) + (rank << 5) + jj;   // 256*g + 32*rank + jj

    // weights in registers: 64 floats = 16 float4 = 32 f32x2
    F4U w[16];
    const float4* wp = (const float4*)(Whh + (size_t)row * HID + seg * 64);
#pragma unroll
    for (int i = 0; i < 16; i++) w[i].f4 = wp[i];
    const float bias = bhh[row];

    for (int i = tid; i < 2 * 288; i += SCAN_THREADS) sh_h[i] = 0.f;
    const uint32_t mb_local = smem_u32(&mbar);
    if (tid == 0) mbar_init(mb_local, NCLUS);
    __syncthreads();
    asm volatile("barrier.cluster.arrive.aligned;" ::: "memory");
    asm volatile("barrier.cluster.wait.aligned;" ::: "memory");

    const float* hs0 = sh_h + 72 * seg;

    // combine warps 0..7: warp cw targets remote rank cw; own h in regs.
    const bool isComb = (tid < 256);
    const int  cw     = tid >> 5;
    const int  lane   = tid & 31;
    const int  j      = (rank << 5) + lane;               // owned j
    const uint32_t hword = (uint32_t)(j + ((j >> 6) << 3));  // padded word idx
    uint32_t rh = 0, rm = 0;
    float xr = 0.f, xz = 0.f, xn = 0.f;
    float hold = 0.f;
    int t = dir ? (T_LEN - 1) : 0;
    const int tstep = dir ? -1 : 1;
    if (isComb) {
        rh = mapa_rank(smem_u32(&sh_h[0]), (uint32_t)cw) + hword * 4u;
        rm = mapa_rank(mb_local, (uint32_t)cw);
        const float* gp = gx + (size_t)t * G3H + j;
        xr = gp[0]; xz = gp[HID]; xn = gp[2 * HID];
    }

#pragma unroll 2
    for (int s = 0; s < T_LEN; s++) {
        const int b = s & 1;

        // ---- matvec: gh[row] partial over this seg's 64 h values ----
        const float* hp = hs0 + b * 288;
        unsigned long long a0 = 0ull, a1 = 0ull, a2 = 0ull, a3 = 0ull;
#pragma unroll
        for (int i = 0; i < 16; i += 4) {
            F4U h0, h1, h2, h3;
            h0.f4 = *(const float4*)(hp + 4 * i);
            h1.f4 = *(const float4*)(hp + 4 * i + 4);
            h2.f4 = *(const float4*)(hp + 4 * i + 8);
            h3.f4 = *(const float4*)(hp + 4 * i + 12);
            FMA_F32X2(a0, w[i].u[0],     h0.u[0], a0);
            FMA_F32X2(a1, w[i].u[1],     h0.u[1], a1);
            FMA_F32X2(a2, w[i + 1].u[0], h1.u[0], a2);
            FMA_F32X2(a3, w[i + 1].u[1], h1.u[1], a3);
            FMA_F32X2(a0, w[i + 2].u[0], h2.u[0], a0);
            FMA_F32X2(a1, w[i + 2].u[1], h2.u[1], a1);
            FMA_F32X2(a2, w[i + 3].u[0], h3.u[0], a2);
            FMA_F32X2(a3, w[i + 3].u[1], h3.u[1], a3);
        }
        ADD_F32X2_(a0, a0, a1);
        ADD_F32X2_(a2, a2, a3);
        ADD_F32X2_(a0, a0, a2);
        float2 pr = u2f2(a0);
        float acc = pr.x + pr.y;
        acc += __shfl_down_sync(0xffffffffu, acc, 2);
        acc += __shfl_down_sync(0xffffffffu, acc, 1);
        if (seg == 0) gh_buf[b][rl] = acc + bias;
        __syncthreads();

        if (isComb) {
            // redundant gate combine (identical in warps 0..7)
            const float hr = gh_buf[b][lane];
            const float hz = gh_buf[b][32 + lane];
            const float hn = gh_buf[b][64 + lane];
            const float r = fast_sigmoid(xr + hr);
            const float z = fast_sigmoid(xz + hz);
            const float n = fast_tanh(xn + r * hn);
            const float hnew = (1.f - z) * n + z * hold;
            hold = hnew;

            // warp cw ships the 32 new h values to rank cw (one target each)
            st_cluster_f32(rh + (uint32_t)(b ^ 1) * 1152u, hnew);
            if (cw == 0) d_h[(size_t)t * 512 + dir * HID + j] = hnew;

            __syncwarp();
            if (lane == 0) mbar_arrive_rel_cluster(rm);

            // prefetch gx for next step (overlaps the wait)
            if (s + 1 < T_LEN) {
                t += tstep;
                const float* gp = gx + (size_t)t * G3H + j;
                xr = gp[0]; xz = gp[HID]; xn = gp[2 * HID];
            }
        }

        mbar_wait_parity_relaxed(mb_local, (uint32_t)b);
    }
}

// =====================================================================
// Kernel 3: scores[t] = relu(h[t] @ Ws1^T + bs1) @ Ws2^T + bs2
// =====================================================================
#define SCORES_SMEM_FLOATS (64 * 516 + 64 + 64 + 32 * 512)
__global__ __launch_bounds__(512)
void scores_kernel(const float* __restrict__ Ws1, const float* __restrict__ bs1,
                   const float* __restrict__ Ws2, const float* __restrict__ bs2,
                   float* __restrict__ out)
{
    extern __shared__ float sm[];
    float* sW1 = sm;                  // 64 x 516 (padded, 16B-aligned rows)
    float* sW2 = sm + 64 * 516;       // 64
    float* sb1 = sW2 + 64;            // 64
    float* sh  = sb1 + 64;            // 32 x 512

    const int tid = threadIdx.x;
    for (int i = tid; i < 64 * 512; i += 512) {
        const int kk = i >> 9, jcol = i & 511;
        sW1[kk * 516 + jcol] = Ws1[i];
    }
    if (tid < 64) { sW2[tid] = Ws2[tid]; sb1[tid] = bs1[tid]; }
    const float bs2v = bs2[0];
    __syncthreads();

    const int warp = tid >> 5, lane = tid & 31;
    const float* w0p = sW1 + (size_t)lane * 516;
    const float* w1p = sW1 + (size_t)(lane + 32) * 516;

    for (int iter = 0; iter < 4; iter++) {
        const int r0 = blockIdx.x * 128 + iter * 32;
        __syncthreads();
        for (int e = tid * 4; e < 32 * 512; e += 512 * 4) {
            const int rrow = e >> 9, col = e & 511;
            *(float4*)&sh[e] = *(const float4*)&d_h[(size_t)(r0 + rrow) * 512 + col];
        }
        __syncthreads();

#pragma unroll
        for (int rr = 0; rr < 2; rr++) {
            const int rowl = warp * 2 + rr;
            const float* hrow = sh + (size_t)rowl * 512;
            unsigned long long c00 = 0ull, c01 = 0ull, c10 = 0ull, c11 = 0ull;
            for (int jc = 0; jc < 512; jc += 4) {
                F4U hv, w0v, w1v;
                hv.f4  = *(const float4*)(hrow + jc);
                w0v.f4 = *(const float4*)(w0p + jc);
                w1v.f4 = *(const float4*)(w1p + jc);
                FMA_F32X2(c00, hv.u[0], w0v.u[0], c00);
                FMA_F32X2(c01, hv.u[1], w0v.u[1], c01);
                FMA_F32X2(c10, hv.u[0], w1v.u[0], c10);
                FMA_F32X2(c11, hv.u[1], w1v.u[1], c11);
            }
            ADD_F32X2_(c00, c00, c01);
            ADD_F32X2_(c10, c10, c11);
            float2 s0 = u2f2(c00), s1 = u2f2(c10);
            const float acc0 = s0.x + s0.y;
            const float acc1 = s1.x + s1.y;
            float v = fmaxf(acc0 + sb1[lane], 0.f) * sW2[lane]
                    + fmaxf(acc1 + sb1[lane + 32], 0.f) * sW2[lane + 32];
#pragma unroll
            for (int o = 16; o; o >>= 1) v += __shfl_down_sync(0xffffffffu, v, o);
            if (lane == 0) out[2 + r0 + rowl] = v + bs2v;
        }
    }
}

// =====================================================================
// Kernel 4a: top-8 -> softmax weights -> clip_repr (1 CTA, 1024 thr)
// =====================================================================
__global__ __launch_bounds__(1024)
void topk_clip_kernel(const float* __restrict__ feat, const float* __restrict__ temp,
                      const float* __restrict__ out_scores)
{
    __shared__ float rv[1024];
    __shared__ int   ri[1024];
    __shared__ int   chosen[8];
    __shared__ float chval[8];
    __shared__ float wts[8];

    const float* scores = out_scores + 2;
    const int tid = threadIdx.x;

    float sc[16];
#pragma unroll
    for (int i = 0; i < 16; i++) sc[i] = scores[tid + (i << 10)];
    unsigned taken = 0;

    for (int k = 0; k < 8; k++) {
        float best = -3.4e38f; int bi = 0x7fffffff;
#pragma unroll
        for (int i = 0; i < 16; i++) {
            const int jg = tid + (i << 10);
            const float v = sc[i];
            if (!(taken & (1u << i)) && (v > best || (v == best && jg < bi))) {
                best = v; bi = jg;
            }
        }
        rv[tid] = best; ri[tid] = bi;
        __syncthreads();
        for (int s = 512; s; s >>= 1) {
            if (tid < s) {
                if (rv[tid + s] > rv[tid] ||
                    (rv[tid + s] == rv[tid] && ri[tid + s] < ri[tid])) {
                    rv[tid] = rv[tid + s]; ri[tid] = ri[tid + s];
                }
            }
            __syncthreads();
        }
        if (tid == 0) { chosen[k] = ri[0]; chval[k] = rv[0]; }
        __syncthreads();
        const int ck = chosen[k];
        if ((ck & 1023) == tid) taken |= 1u << (ck >> 10);
    }

    if (tid == 0) {
        const float tmp = temp[0];
        float m = chval[0];
        for (int k = 1; k < 8; k++) m = fmaxf(m, chval[k]);
        float ssum = 0.f;
        for (int k = 0; k < 8; k++) { const float e = expf((chval[k] - m) / tmp); wts[k] = e; ssum += e; }
        for (int k = 0; k < 8; k++) { wts[k] /= ssum; d_wts[k] = wts[k]; d_chosen[k] = chosen[k]; }
    }
    __syncthreads();

    for (int d = tid; d < D_IN; d += 1024) {
        float c = 0.f;
#pragma unroll
        for (int k = 0; k < 8; k++)
            c = fmaf(wts[k], feat[(size_t)chosen[k] * D_IN + d], c);
        d_clip[d] = c;
    }
}

// =====================================================================
// Kernel 4b: c1 = relu(Wc1 @ clip + bc1), 16 CTAs x 256 thr (16 thr/row)
// =====================================================================
__global__ __launch_bounds__(256)
void classify_kernel(const float* __restrict__ Wc1, const float* __restrict__ bc1)
{
    const int tid = threadIdx.x;
    const int o = blockIdx.x * 16 + (tid >> 4);
    const int part = tid & 15;
    const float* wr = Wc1 + (size_t)o * D_IN + part * 128;
    const float* cp = d_clip + part * 128;
    float s0 = 0.f, s1 = 0.f, s2 = 0.f, s3 = 0.f;
#pragma unroll
    for (int jc = 0; jc < 128; jc += 16) {
        const float4 c0 = *(const float4*)(cp + jc);
        const float4 w0 = *(const float4*)(wr + jc);
        const float4 c1v = *(const float4*)(cp + jc + 4);
        const float4 w1 = *(const float4*)(wr + jc + 4);
        const float4 c2 = *(const float4*)(cp + jc + 8);
        const float4 w2 = *(const float4*)(wr + jc + 8);
        const float4 c3 = *(const float4*)(cp + jc + 12);
        const float4 w3 = *(const float4*)(wr + jc + 12);
        s0 = fmaf(c0.x, w0.x, s0); s0 = fmaf(c0.y, w0.y, s0);
        s0 = fmaf(c0.z, w0.z, s0); s0 = fmaf(c0.w, w0.w, s0);
        s1 = fmaf(c1v.x, w1.x, s1); s1 = fmaf(c1v.y, w1.y, s1);
        s1 = fmaf(c1v.z, w1.z, s1); s1 = fmaf(c1v.w, w1.w, s1);
        s2 = fmaf(c2.x, w2.x, s2); s2 = fmaf(c2.y, w2.y, s2);
        s2 = fmaf(c2.z, w2.z, s2); s2 = fmaf(c2.w, w2.w, s2);
        s3 = fmaf(c3.x, w3.x, s3); s3 = fmaf(c3.y, w3.y, s3);
        s3 = fmaf(c3.z, w3.z, s3); s3 = fmaf(c3.w, w3.w, s3);
    }
    float s = (s0 + s1) + (s2 + s3);
    s += __shfl_down_sync(0xffffffffu, s, 8, 16);
    s += __shfl_down_sync(0xffffffffu, s, 4, 16);
    s += __shfl_down_sync(0xffffffffu, s, 2, 16);
    s += __shfl_down_sync(0xffffffffu, s, 1, 16);
    if (part == 0) d_c1[o] = fmaxf(s + bc1[o], 0.f);
}

// =====================================================================
// Kernel 4c: logits = c1 @ Wc2^T + bc2 (1 CTA, 64 thr)
// =====================================================================
__global__ __launch_bounds__(64)
void logits_kernel(const float* __restrict__ Wc2, const float* __restrict__ bc2,
                   float* __restrict__ out)
{
    const int tid = threadIdx.x;
    const int c = tid >> 5, lane = tid & 31;
    float s = 0.f;
    for (int kk = lane; kk < 256; kk += 32)
        s = fmaf(d_c1[kk], Wc2[(size_t)c * 256 + kk], s);
#pragma unroll
    for (int o = 16; o; o >>= 1) s += __shfl_down_sync(0xffffffffu, s, o);
    if (lane == 0) out[c] = s + bc2[c];
}

// =====================================================================
extern "C" void kernel_launch(void* const* d_in, const int* in_sizes, int n_in,
                              void* d_out, int out_size)
{
    const float* feat   = (const float*)d_in[0];
    const float* temp   = (const float*)d_in[1];
    const float* W_ih_f = (const float*)d_in[2];
    const float* W_hh_f = (const float*)d_in[3];
    const float* b_ih_f = (const float*)d_in[4];
    const float* b_hh_f = (const float*)d_in[5];
    const float* W_ih_b = (const float*)d_in[6];
    const float* W_hh_b = (const float*)d_in[7];
    const float* b_ih_b = (const float*)d_in[8];
    const float* b_hh_b = (const float*)d_in[9];
    const float* Ws1    = (const float*)d_in[10];
    const float* bs1    = (const float*)d_in[11];
    const float* Ws2    = (const float*)d_in[12];
    const float* bs2    = (const float*)d_in[13];
    const float* Wc1    = (const float*)d_in[14];
    const float* bc1    = (const float*)d_in[15];
    const float* Wc2    = (const float*)d_in[16];
    const float* bc2    = (const float*)d_in[17];
    float* out = (float*)d_out;

    // 1) input projections (both directions)
    gemm_gx_kernel<<<dim3(12, 128, 2), 256>>>(feat, W_ih_f, b_ih_f, W_ih_b, b_ih_b);

    // 2) BiGRU scan: 2 clusters of 8 CTAs
    scan_kernel<<<16, SCAN_THREADS>>>(W_hh_f, b_hh_f, W_hh_b, b_hh_b);

    // 3) frame scores
    cudaFuncSetAttribute(scores_kernel, cudaFuncAttributeMaxDynamicSharedMemorySize,
                         SCORES_SMEM_FLOATS * 4);
    scores_kernel<<<128, 512, SCORES_SMEM_FLOATS * 4>>>(Ws1, bs1, Ws2, bs2, out);

    // 4) top-k + softmax + weighted sum + classifier
    topk_clip_kernel<<<1, 1024>>>(feat, temp, out);
    classify_kernel<<<16, 256>>>(Wc1, bc1);
    logits_kernel<<<1, 64>>>(Wc2, bc2, out);
}

// round 12
// speedup vs baseline: 1.9042x; 1.4285x over previous
#include <cuda_runtime.h>
#include <cstdint>
#include <math.h>

#define T_LEN 16384
#define D_IN  2048
#define HID   256
#define G3H   768
#define NCLUS 8
#define SCAN_THREADS 384

// ---------------- device scratch (static, no allocation) ----------------
__device__ float d_gx[2][(size_t)T_LEN * G3H];   // input projections, both dirs
__device__ float d_h[(size_t)T_LEN * 512];       // concat(h_f, h_b)
__device__ float d_clip[D_IN];
__device__ float d_wts[8];
__device__ int   d_chosen[8];
__device__ float d_c1[256];
__device__ float d_dummy_sink;

// ---------------- helpers ----------------
union F4U { float4 f4; unsigned long long u[2]; float f[4]; float2 f2[2]; };

#define FMA_F32X2(d, a, b, c) \
    asm("fma.rn.f32x2 %0, %1, %2, %3;" : "=l"(d) : "l"(a), "l"(b), "l"(c))
#define ADD_F32X2_(d, a, b) \
    asm("add.rn.f32x2 %0, %1, %2;" : "=l"(d) : "l"(a), "l"(b))
#define PACKF2(u, x, y) \
    asm("mov.b64 %0, {%1, %2};" : "=l"(u) : "f"(x), "f"(y))

__device__ __forceinline__ float2 u2f2(unsigned long long u) {
    float2 r; asm("mov.b64 {%0, %1}, %2;" : "=f"(r.x), "=f"(r.y) : "l"(u)); return r;
}
__device__ __forceinline__ uint32_t smem_u32(const void* p) {
    return (uint32_t)__cvta_generic_to_shared(p);
}
__device__ __forceinline__ uint32_t mapa_rank(uint32_t addr, uint32_t rank) {
    uint32_t d;
    asm("mapa.shared::cluster.u32 %0, %1, %2;" : "=r"(d) : "r"(addr), "r"(rank));
    return d;
}
__device__ __forceinline__ void mbar_init(uint32_t addr, uint32_t cnt) {
    asm volatile("mbarrier.init.shared.b64 [%0], %1;" :: "r"(addr), "r"(cnt) : "memory");
}
__device__ __forceinline__ void mbar_arrive_local(uint32_t addr) {
    asm volatile("mbarrier.arrive.shared.b64 _, [%0];" :: "r"(addr) : "memory");
}
__device__ __forceinline__ void mbar_arrive_expect_tx(uint32_t addr, uint32_t tx) {
    asm volatile("mbarrier.arrive.expect_tx.shared.b64 _, [%0], %1;"
                 :: "r"(addr), "r"(tx) : "memory");
}
// One-way remote store with transaction accounting on the TARGET CTA's
// mbarrier: data lands + tx-count updated atomically by HW. No release
// fence, no separate arrive flight.
__device__ __forceinline__ void st_async_cluster_f32(uint32_t daddr, float v, uint32_t mbar) {
    asm volatile(
        "st.async.shared::cluster.mbarrier::complete_tx::bytes.b32 [%0], %1, [%2];"
        :: "r"(daddr), "r"(__float_as_uint(v)), "r"(mbar) : "memory");
}
// RELAXED wait: tx-completion semantics guarantee landed data (TMA-style).
__device__ __forceinline__ void mbar_wait_parity_relaxed(uint32_t addr, uint32_t par) {
    asm volatile(
        "{\n\t.reg .pred P;\n\t"
        "W%=:\n\t"
        "mbarrier.try_wait.parity.relaxed.cta.shared::cta.b64 P, [%0], %1, 0x989680;\n\t"
        "@P bra D%=;\n\t"
        "bra W%=;\n\t"
        "D%=:\n\t}"
        :: "r"(addr), "r"(par) : "memory");
}
// fast sigmoid / tanh (MUFU-based, ~1e-7 rel err)
__device__ __forceinline__ float fast_sigmoid(float x) {
    return __fdividef(1.f, 1.f + __expf(-x));
}
__device__ __forceinline__ float fast_tanh(float x) {
    return __fdividef(2.f, 1.f + __expf(-2.f * x)) - 1.f;
}

// =====================================================================
// Kernel 1: gx[dir] = feat @ W_ih[dir]^T + b_ih[dir]
// =====================================================================
__global__ __launch_bounds__(256)
void gemm_gx_kernel(const float* __restrict__ feat,
                    const float* __restrict__ Wf, const float* __restrict__ bf,
                    const float* __restrict__ Wb, const float* __restrict__ bb)
{
    const int dir = blockIdx.z;
    const float* __restrict__ W    = dir ? Wb : Wf;
    const float* __restrict__ bias = dir ? bb : bf;
    float* __restrict__ C = d_gx[dir];

    const int t0 = blockIdx.y * 128;
    const int o0 = blockIdx.x * 64;

    __shared__ float As[16][132];
    __shared__ float Bs[16][68];

    const int tid = threadIdx.x;
    const int tx = tid & 15, ty = tid >> 4;
    const int m0 = ty * 8, n0 = tx * 4;

    const int ar0 = tid >> 2;
    const int akq = (tid & 3) * 4;

    const float* aptr0 = feat + (size_t)(t0 + ar0)      * D_IN + akq;
    const float* aptr1 = feat + (size_t)(t0 + ar0 + 64) * D_IN + akq;
    const float* bptr  = W    + (size_t)(o0 + ar0)      * D_IN + akq;

    float4 pa0 = *(const float4*)(aptr0);
    float4 pa1 = *(const float4*)(aptr1);
    float4 pb  = *(const float4*)(bptr);

    unsigned long long acc2[4][4];
#pragma unroll
    for (int i = 0; i < 4; i++)
#pragma unroll
        for (int j = 0; j < 4; j++) acc2[i][j] = 0ull;

    for (int kt = 0; kt < D_IN; kt += 16) {
        As[akq + 0][ar0] = pa0.x; As[akq + 1][ar0] = pa0.y;
        As[akq + 2][ar0] = pa0.z; As[akq + 3][ar0] = pa0.w;
        As[akq + 0][ar0 + 64] = pa1.x; As[akq + 1][ar0 + 64] = pa1.y;
        As[akq + 2][ar0 + 64] = pa1.z; As[akq + 3][ar0 + 64] = pa1.w;
        Bs[akq + 0][ar0] = pb.x; Bs[akq + 1][ar0] = pb.y;
        Bs[akq + 2][ar0] = pb.z; Bs[akq + 3][ar0] = pb.w;
        __syncthreads();

        if (kt + 16 < D_IN) {
            pa0 = *(const float4*)(aptr0 + kt + 16);
            pa1 = *(const float4*)(aptr1 + kt + 16);
            pb  = *(const float4*)(bptr  + kt + 16);
        }

#pragma unroll
        for (int k = 0; k < 16; k++) {
            F4U a0, a1, b;
            a0.f4 = *(const float4*)&As[k][m0];
            a1.f4 = *(const float4*)&As[k][m0 + 4];
            b.f4  = *(const float4*)&Bs[k][n0];
            unsigned long long a2[4] = {a0.u[0], a0.u[1], a1.u[0], a1.u[1]};
            unsigned long long bd[4];
            PACKF2(bd[0], b.f[0], b.f[0]);
            PACKF2(bd[1], b.f[1], b.f[1]);
            PACKF2(bd[2], b.f[2], b.f[2]);
            PACKF2(bd[3], b.f[3], b.f[3]);
#pragma unroll
            for (int i = 0; i < 4; i++)
#pragma unroll
                for (int j = 0; j < 4; j++)
                    FMA_F32X2(acc2[i][j], a2[i], bd[j], acc2[i][j]);
        }
        __syncthreads();
    }

    const float4 bv4 = *(const float4*)&bias[o0 + n0];
#pragma unroll
    for (int i2 = 0; i2 < 4; i2++) {
        float2 p0 = u2f2(acc2[i2][0]);
        float2 p1 = u2f2(acc2[i2][1]);
        float2 p2 = u2f2(acc2[i2][2]);
        float2 p3 = u2f2(acc2[i2][3]);
        float4 v0, v1;
        v0.x = p0.x + bv4.x; v0.y = p1.x + bv4.y; v0.z = p2.x + bv4.z; v0.w = p3.x + bv4.w;
        v1.x = p0.y + bv4.x; v1.y = p1.y + bv4.y; v1.z = p2.y + bv4.z; v1.w = p3.y + bv4.w;
        *(float4*)&C[(size_t)(t0 + m0 + 2 * i2 + 0) * G3H + o0 + n0] = v0;
        *(float4*)&C[(size_t)(t0 + m0 + 2 * i2 + 1) * G3H + o0 + n0] = v1;
    }
}

// Separator no-ops so ncu's fixed -s 5 lands on scan_kernel next round.
__global__ void sep_kernel_a() { if (threadIdx.x == 1024) d_dummy_sink = 1.f; }
__global__ void sep_kernel_b() { if (threadIdx.x == 1024) d_dummy_sink = 2.f; }

// =====================================================================
// Kernel 2: BiGRU scan. Grid = 16 CTAs = 2 clusters of 8 (dir = blk/8).
// 384 threads/CTA. CTA rank owns j in [32r,32r+32) + its 3 gate rows.
// Per step: matvec (f32x2, W in regs, 4 segs/row) -> 2-shfl reduce ->
// seg0 STS gh -> bar -> warps 0..7 redundantly combine 32 gates; warp w
// st.async's h to rank w (double-buffered sh_h) with complete_tx on
// rank w's mbars[b^1] -> relaxed parity wait (expect_tx 1024 B issued by
// an off-path thread at top of step).
// =====================================================================
__global__ void __cluster_dims__(NCLUS, 1, 1) __launch_bounds__(SCAN_THREADS, 1)
scan_kernel(const float* __restrict__ Whf, const float* __restrict__ bhf,
            const float* __restrict__ Whb, const float* __restrict__ bhb)
{
    // padded h: idx(k) = k + (k>>6)*8 ; buffer stride 288 floats
    __shared__ __align__(16) float sh_h[2 * 288];
    __shared__ float gh_buf[2][96];
    __shared__ __align__(8) unsigned long long mbars[2];

    const int rank = blockIdx.x & 7;
    const int dir  = blockIdx.x >> 3;
    const float* __restrict__ Whh = dir ? Whb : Whf;
    const float* __restrict__ bhh = dir ? bhb : bhf;
    const float* __restrict__ gx  = d_gx[dir];

    const int tid = threadIdx.x;
    const int rl  = tid >> 2;          // 0..95 local row
    const int seg = tid & 3;           // 0..3
    const int g   = rl >> 5;           // gate 0..2 (r,z,n)
    const int jj  = rl & 31;
    const int row = (g << 8) + (rank << 5) + jj;   // 256*g + 32*rank + jj

    // weights in registers: 64 floats = 16 float4 = 32 f32x2
    F4U w[16];
    const float4* wp = (const float4*)(Whh + (size_t)row * HID + seg * 64);
#pragma unroll
    for (int i = 0; i < 16; i++) w[i].f4 = wp[i];
    const float bias = bhh[row];

    for (int i = tid; i < 2 * 288; i += SCAN_THREADS) sh_h[i] = 0.f;
    const uint32_t mb0 = smem_u32(&mbars[0]);
    const uint32_t mb1 = smem_u32(&mbars[1]);
    if (tid == 0) {
        mbar_init(mb0, 1);
        mbar_init(mb1, 1);
        // pre-consume one phase of mbars[0] so both barriers' observed
        // parity sequences match ((s+1)>>1)&1
        mbar_arrive_local(mb0);
    }
    __syncthreads();
    asm volatile("barrier.cluster.arrive.aligned;" ::: "memory");
    asm volatile("barrier.cluster.wait.aligned;" ::: "memory");

    const float* hs0 = sh_h + 72 * seg;

    // combine warps 0..7: warp cw targets remote rank cw; own h in regs.
    const bool isComb = (tid < 256);
    const int  cw     = tid >> 5;
    const int  lane   = tid & 31;
    const int  j      = (rank << 5) + lane;               // owned j
    const uint32_t hword = (uint32_t)(j + ((j >> 6) << 3));  // padded word idx
    uint32_t rh = 0, rmb[2] = {0, 0};
    float xr = 0.f, xz = 0.f, xn = 0.f;
    float hold = 0.f;
    int t = dir ? (T_LEN - 1) : 0;
    const int tstep = dir ? -1 : 1;
    if (isComb) {
        rh     = mapa_rank(smem_u32(&sh_h[0]), (uint32_t)cw) + hword * 4u;
        rmb[0] = mapa_rank(mb0, (uint32_t)cw);
        rmb[1] = mapa_rank(mb1, (uint32_t)cw);
        const float* gp = gx + (size_t)t * G3H + j;
        xr = gp[0]; xz = gp[HID]; xn = gp[2 * HID];
    }
    const uint32_t mbl[2] = {mb0, mb1};

#pragma unroll 2
    for (int s = 0; s < T_LEN; s++) {
        const int b = s & 1;

        // off-critical-path: declare expected tx bytes for step s+1's h
        if (tid == 256) mbar_arrive_expect_tx(mbl[b ^ 1], 8 * 32 * 4);

        // ---- matvec: gh[row] partial over this seg's 64 h values ----
        const float* hp = hs0 + b * 288;
        unsigned long long a0 = 0ull, a1 = 0ull, a2 = 0ull, a3 = 0ull;
#pragma unroll
        for (int i = 0; i < 16; i += 4) {
            F4U h0, h1, h2, h3;
            h0.f4 = *(const float4*)(hp + 4 * i);
            h1.f4 = *(const float4*)(hp + 4 * i + 4);
            h2.f4 = *(const float4*)(hp + 4 * i + 8);
            h3.f4 = *(const float4*)(hp + 4 * i + 12);
            FMA_F32X2(a0, w[i].u[0],     h0.u[0], a0);
            FMA_F32X2(a1, w[i].u[1],     h0.u[1], a1);
            FMA_F32X2(a2, w[i + 1].u[0], h1.u[0], a2);
            FMA_F32X2(a3, w[i + 1].u[1], h1.u[1], a3);
            FMA_F32X2(a0, w[i + 2].u[0], h2.u[0], a0);
            FMA_F32X2(a1, w[i + 2].u[1], h2.u[1], a1);
            FMA_F32X2(a2, w[i + 3].u[0], h3.u[0], a2);
            FMA_F32X2(a3, w[i + 3].u[1], h3.u[1], a3);
        }
        ADD_F32X2_(a0, a0, a1);
        ADD_F32X2_(a2, a2, a3);
        ADD_F32X2_(a0, a0, a2);
        float2 pr = u2f2(a0);
        float acc = pr.x + pr.y;
        acc += __shfl_down_sync(0xffffffffu, acc, 2);
        acc += __shfl_down_sync(0xffffffffu, acc, 1);
        if (seg == 0) gh_buf[b][rl] = acc + bias;
        __syncthreads();

        if (isComb) {
            // redundant gate combine (identical in warps 0..7)
            const float hr = gh_buf[b][lane];
            const float hz = gh_buf[b][32 + lane];
            const float hn = gh_buf[b][64 + lane];
            const float r = fast_sigmoid(xr + hr);
            const float z = fast_sigmoid(xz + hz);
            const float n = fast_tanh(xn + r * hn);
            const float hnew = (1.f - z) * n + z * hold;
            hold = hnew;

            // one-way store+tx to rank cw's next-step buffer
            st_async_cluster_f32(rh + (uint32_t)(b ^ 1) * 1152u, hnew, rmb[b ^ 1]);
            if (cw == 0) d_h[(size_t)t * 512 + dir * HID + j] = hnew;

            // prefetch gx for next step (overlaps the wait)
            if (s + 1 < T_LEN) {
                t += tstep;
                const float* gp = gx + (size_t)t * G3H + j;
                xr = gp[0]; xz = gp[HID]; xn = gp[2 * HID];
            }
        }

        mbar_wait_parity_relaxed(mbl[b ^ 1], (uint32_t)(((s + 1) >> 1) & 1));
    }

    asm volatile("barrier.cluster.arrive.aligned;" ::: "memory");
    asm volatile("barrier.cluster.wait.aligned;" ::: "memory");
}

// =====================================================================
// Kernel 3: scores[t] = relu(h[t] @ Ws1^T + bs1) @ Ws2^T + bs2
// =====================================================================
#define SCORES_SMEM_FLOATS (64 * 516 + 64 + 64 + 32 * 512)
__global__ __launch_bounds__(512)
void scores_kernel(const float* __restrict__ Ws1, const float* __restrict__ bs1,
                   const float* __restrict__ Ws2, const float* __restrict__ bs2,
                   float* __restrict__ out)
{
    extern __shared__ float sm[];
    float* sW1 = sm;                  // 64 x 516 (padded, 16B-aligned rows)
    float* sW2 = sm + 64 * 516;       // 64
    float* sb1 = sW2 + 64;            // 64
    float* sh  = sb1 + 64;            // 32 x 512

    const int tid = threadIdx.x;
    for (int i = tid; i < 64 * 512; i += 512) {
        const int kk = i >> 9, jcol = i & 511;
        sW1[kk * 516 + jcol] = Ws1[i];
    }
    if (tid < 64) { sW2[tid] = Ws2[tid]; sb1[tid] = bs1[tid]; }
    const float bs2v = bs2[0];
    __syncthreads();

    const int warp = tid >> 5, lane = tid & 31;
    const float* w0p = sW1 + (size_t)lane * 516;
    const float* w1p = sW1 + (size_t)(lane + 32) * 516;

    for (int iter = 0; iter < 4; iter++) {
        const int r0 = blockIdx.x * 128 + iter * 32;
        __syncthreads();
        for (int e = tid * 4; e < 32 * 512; e += 512 * 4) {
            const int rrow = e >> 9, col = e & 511;
            *(float4*)&sh[e] = *(const float4*)&d_h[(size_t)(r0 + rrow) * 512 + col];
        }
        __syncthreads();

#pragma unroll
        for (int rr = 0; rr < 2; rr++) {
            const int rowl = warp * 2 + rr;
            const float* hrow = sh + (size_t)rowl * 512;
            unsigned long long c00 = 0ull, c01 = 0ull, c10 = 0ull, c11 = 0ull;
            for (int jc = 0; jc < 512; jc += 4) {
                F4U hv, w0v, w1v;
                hv.f4  = *(const float4*)(hrow + jc);
                w0v.f4 = *(const float4*)(w0p + jc);
                w1v.f4 = *(const float4*)(w1p + jc);
                FMA_F32X2(c00, hv.u[0], w0v.u[0], c00);
                FMA_F32X2(c01, hv.u[1], w0v.u[1], c01);
                FMA_F32X2(c10, hv.u[0], w1v.u[0], c10);
                FMA_F32X2(c11, hv.u[1], w1v.u[1], c11);
            }
            ADD_F32X2_(c00, c00, c01);
            ADD_F32X2_(c10, c10, c11);
            float2 s0 = u2f2(c00), s1 = u2f2(c10);
            const float acc0 = s0.x + s0.y;
            const float acc1 = s1.x + s1.y;
            float v = fmaxf(acc0 + sb1[lane], 0.f) * sW2[lane]
                    + fmaxf(acc1 + sb1[lane + 32], 0.f) * sW2[lane + 32];
#pragma unroll
            for (int o = 16; o; o >>= 1) v += __shfl_down_sync(0xffffffffu, v, o);
            if (lane == 0) out[2 + r0 + rowl] = v + bs2v;
        }
    }
}

// =====================================================================
// Kernel 4a: top-8 -> softmax weights -> clip_repr (1 CTA, 1024 thr)
// =====================================================================
__global__ __launch_bounds__(1024)
void topk_clip_kernel(const float* __restrict__ feat, const float* __restrict__ temp,
                      const float* __restrict__ out_scores)
{
    __shared__ float rv[1024];
    __shared__ int   ri[1024];
    __shared__ int   chosen[8];
    __shared__ float chval[8];
    __shared__ float wts[8];

    const float* scores = out_scores + 2;
    const int tid = threadIdx.x;

    float sc[16];
#pragma unroll
    for (int i = 0; i < 16; i++) sc[i] = scores[tid + (i << 10)];
    unsigned taken = 0;

    for (int k = 0; k < 8; k++) {
        float best = -3.4e38f; int bi = 0x7fffffff;
#pragma unroll
        for (int i = 0; i < 16; i++) {
            const int jg = tid + (i << 10);
            const float v = sc[i];
            if (!(taken & (1u << i)) && (v > best || (v == best && jg < bi))) {
                best = v; bi = jg;
            }
        }
        rv[tid] = best; ri[tid] = bi;
        __syncthreads();
        for (int s = 512; s; s >>= 1) {
            if (tid < s) {
                if (rv[tid + s] > rv[tid] ||
                    (rv[tid + s] == rv[tid] && ri[tid + s] < ri[tid])) {
                    rv[tid] = rv[tid + s]; ri[tid] = ri[tid + s];
                }
            }
            __syncthreads();
        }
        if (tid == 0) { chosen[k] = ri[0]; chval[k] = rv[0]; }
        __syncthreads();
        const int ck = chosen[k];
        if ((ck & 1023) == tid) taken |= 1u << (ck >> 10);
    }

    if (tid == 0) {
        const float tmp = temp[0];
        float m = chval[0];
        for (int k = 1; k < 8; k++) m = fmaxf(m, chval[k]);
        float ssum = 0.f;
        for (int k = 0; k < 8; k++) { const float e = expf((chval[k] - m) / tmp); wts[k] = e; ssum += e; }
        for (int k = 0; k < 8; k++) { wts[k] /= ssum; d_wts[k] = wts[k]; d_chosen[k] = chosen[k]; }
    }
    __syncthreads();

    for (int d = tid; d < D_IN; d += 1024) {
        float c = 0.f;
#pragma unroll
        for (int k = 0; k < 8; k++)
            c = fmaf(wts[k], feat[(size_t)chosen[k] * D_IN + d], c);
        d_clip[d] = c;
    }
}

// =====================================================================
// Kernel 4b: c1 = relu(Wc1 @ clip + bc1), 16 CTAs x 256 thr (16 thr/row)
// =====================================================================
__global__ __launch_bounds__(256)
void classify_kernel(const float* __restrict__ Wc1, const float* __restrict__ bc1)
{
    const int tid = threadIdx.x;
    const int o = blockIdx.x * 16 + (tid >> 4);
    const int part = tid & 15;
    const float* wr = Wc1 + (size_t)o * D_IN + part * 128;
    const float* cp = d_clip + part * 128;
    float s0 = 0.f, s1 = 0.f, s2 = 0.f, s3 = 0.f;
#pragma unroll
    for (int jc = 0; jc < 128; jc += 16) {
        const float4 c0 = *(const float4*)(cp + jc);
        const float4 w0 = *(const float4*)(wr + jc);
        const float4 c1v = *(const float4*)(cp + jc + 4);
        const float4 w1 = *(const float4*)(wr + jc + 4);
        const float4 c2 = *(const float4*)(cp + jc + 8);
        const float4 w2 = *(const float4*)(wr + jc + 8);
        const float4 c3 = *(const float4*)(cp + jc + 12);
        const float4 w3 = *(const float4*)(wr + jc + 12);
        s0 = fmaf(c0.x, w0.x, s0); s0 = fmaf(c0.y, w0.y, s0);
        s0 = fmaf(c0.z, w0.z, s0); s0 = fmaf(c0.w, w0.w, s0);
        s1 = fmaf(c1v.x, w1.x, s1); s1 = fmaf(c1v.y, w1.y, s1);
        s1 = fmaf(c1v.z, w1.z, s1); s1 = fmaf(c1v.w, w1.w, s1);
        s2 = fmaf(c2.x, w2.x, s2); s2 = fmaf(c2.y, w2.y, s2);
        s2 = fmaf(c2.z, w2.z, s2); s2 = fmaf(c2.w, w2.w, s2);
        s3 = fmaf(c3.x, w3.x, s3); s3 = fmaf(c3.y, w3.y, s3);
        s3 = fmaf(c3.z, w3.z, s3); s3 = fmaf(c3.w, w3.w, s3);
    }
    float s = (s0 + s1) + (s2 + s3);
    s += __shfl_down_sync(0xffffffffu, s, 8, 16);
    s += __shfl_down_sync(0xffffffffu, s, 4, 16);
    s += __shfl_down_sync(0xffffffffu, s, 2, 16);
    s += __shfl_down_sync(0xffffffffu, s, 1, 16);
    if (part == 0) d_c1[o] = fmaxf(s + bc1[o], 0.f);
}

// =====================================================================
// Kernel 4c: logits = c1 @ Wc2^T + bc2 (1 CTA, 64 thr)
// =====================================================================
__global__ __launch_bounds__(64)
void logits_kernel(const float* __restrict__ Wc2, const float* __restrict__ bc2,
                   float* __restrict__ out)
{
    const int tid = threadIdx.x;
    const int c = tid >> 5, lane = tid & 31;
    float s = 0.f;
    for (int kk = lane; kk < 256; kk += 32)
        s = fmaf(d_c1[kk], Wc2[(size_t)c * 256 + kk], s);
#pragma unroll
    for (int o = 16; o; o >>= 1) s += __shfl_down_sync(0xffffffffu, s, o);
    if (lane == 0) out[c] = s + bc2[c];
}

// =====================================================================
extern "C" void kernel_launch(void* const* d_in, const int* in_sizes, int n_in,
                              void* d_out, int out_size)
{
    const float* feat   = (const float*)d_in[0];
    const float* temp   = (const float*)d_in[1];
    const float* W_ih_f = (const float*)d_in[2];
    const float* W_hh_f = (const float*)d_in[3];
    const float* b_ih_f = (const float*)d_in[4];
    const float* b_hh_f = (const float*)d_in[5];
    const float* W_ih_b = (const float*)d_in[6];
    const float* W_hh_b = (const float*)d_in[7];
    const float* b_ih_b = (const float*)d_in[8];
    const float* b_hh_b = (const float*)d_in[9];
    const float* Ws1    = (const float*)d_in[10];
    const float* bs1    = (const float*)d_in[11];
    const float* Ws2    = (const float*)d_in[12];
    const float* bs2    = (const float*)d_in[13];
    const float* Wc1    = (const float*)d_in[14];
    const float* bc1    = (const float*)d_in[15];
    const float* Wc2    = (const float*)d_in[16];
    const float* bc2    = (const float*)d_in[17];
    float* out = (float*)d_out;

    // 1) input projections (both directions)
    gemm_gx_kernel<<<dim3(12, 128, 2), 256>>>(feat, W_ih_f, b_ih_f, W_ih_b, b_ih_b);

    // separators: align scan_kernel with ncu's fixed skip count (-s 5)
    sep_kernel_a<<<1, 32>>>();
    sep_kernel_b<<<1, 32>>>();

    // 2) BiGRU scan: 2 clusters of 8 CTAs
    scan_kernel<<<16, SCAN_THREADS>>>(W_hh_f, b_hh_f, W_hh_b, b_hh_b);

    // 3) frame scores
    cudaFuncSetAttribute(scores_kernel, cudaFuncAttributeMaxDynamicSharedMemorySize,
                         SCORES_SMEM_FLOATS * 4);
    scores_kernel<<<128, 512, SCORES_SMEM_FLOATS * 4>>>(Ws1, bs1, Ws2, bs2, out);

    // 4) top-k + softmax + weighted sum + classifier
    topk_clip_kernel<<<1, 1024>>>(feat, temp, out);
    classify_kernel<<<16, 256>>>(Wc1, bc1);
    logits_kernel<<<1, 64>>>(Wc2, bc2, out);
}

// round 13
// speedup vs baseline: 2.0397x; 1.0712x over previous
#include <cuda_runtime.h>
#include <cstdint>
#include <math.h>

#define T_LEN 16384
#define D_IN  2048
#define HID   256
#define G3H   768
#define NCLUS 8
#define SCAN_THREADS 384

// ---------------- device scratch (static, no allocation) ----------------
__device__ float d_gx[2][(size_t)T_LEN * G3H];   // input projections, both dirs
__device__ float d_h[(size_t)T_LEN * 512];       // concat(h_f, h_b)
__device__ float d_clip[D_IN];
__device__ float d_wts[8];
__device__ int   d_chosen[8];
__device__ float d_c1[256];
__device__ float d_dummy_sink;

// ---------------- helpers ----------------
union F4U { float4 f4; unsigned long long u[2]; float f[4]; float2 f2[2]; };

#define FMA_F32X2(d, a, b, c) \
    asm("fma.rn.f32x2 %0, %1, %2, %3;" : "=l"(d) : "l"(a), "l"(b), "l"(c))
#define ADD_F32X2_(d, a, b) \
    asm("add.rn.f32x2 %0, %1, %2;" : "=l"(d) : "l"(a), "l"(b))
#define PACKF2(u, x, y) \
    asm("mov.b64 %0, {%1, %2};" : "=l"(u) : "f"(x), "f"(y))

__device__ __forceinline__ float2 u2f2(unsigned long long u) {
    float2 r; asm("mov.b64 {%0, %1}, %2;" : "=f"(r.x), "=f"(r.y) : "l"(u)); return r;
}
__device__ __forceinline__ uint32_t smem_u32(const void* p) {
    return (uint32_t)__cvta_generic_to_shared(p);
}
__device__ __forceinline__ uint32_t mapa_rank(uint32_t addr, uint32_t rank) {
    uint32_t d;
    asm("mapa.shared::cluster.u32 %0, %1, %2;" : "=r"(d) : "r"(addr), "r"(rank));
    return d;
}
__device__ __forceinline__ void mbar_init(uint32_t addr, uint32_t cnt) {
    asm volatile("mbarrier.init.shared.b64 [%0], %1;" :: "r"(addr), "r"(cnt) : "memory");
}
__device__ __forceinline__ void mbar_arrive_local(uint32_t addr) {
    asm volatile("mbarrier.arrive.shared.b64 _, [%0];" :: "r"(addr) : "memory");
}
__device__ __forceinline__ void mbar_arrive_expect_tx(uint32_t addr, uint32_t tx) {
    asm volatile("mbarrier.arrive.expect_tx.shared.b64 _, [%0], %1;"
                 :: "r"(addr), "r"(tx) : "memory");
}
// One-way remote store with transaction accounting on the TARGET CTA's
// mbarrier: data lands + tx-count updated atomically by HW.
__device__ __forceinline__ void st_async_cluster_f32(uint32_t daddr, float v, uint32_t mbar) {
    asm volatile(
        "st.async.shared::cluster.mbarrier::complete_tx::bytes.b32 [%0], %1, [%2];"
        :: "r"(daddr), "r"(__float_as_uint(v)), "r"(mbar) : "memory");
}
// RELAXED wait: tx-completion semantics guarantee landed data (TMA-style).
__device__ __forceinline__ void mbar_wait_parity_relaxed(uint32_t addr, uint32_t par) {
    asm volatile(
        "{\n\t.reg .pred P;\n\t"
        "W%=:\n\t"
        "mbarrier.try_wait.parity.relaxed.cta.shared::cta.b64 P, [%0], %1, 0x989680;\n\t"
        "@P bra D%=;\n\t"
        "bra W%=;\n\t"
        "D%=:\n\t}"
        :: "r"(addr), "r"(par) : "memory");
}
// fast sigmoid / tanh (MUFU-based, ~1e-7 rel err)
__device__ __forceinline__ float fast_sigmoid(float x) {
    return __fdividef(1.f, 1.f + __expf(-x));
}
__device__ __forceinline__ float fast_tanh(float x) {
    return __fdividef(2.f, 1.f + __expf(-2.f * x)) - 1.f;
}

// =====================================================================
// Kernel 1: gx[dir] = feat @ W_ih[dir]^T + b_ih[dir]
// =====================================================================
__global__ __launch_bounds__(256)
void gemm_gx_kernel(const float* __restrict__ feat,
                    const float* __restrict__ Wf, const float* __restrict__ bf,
                    const float* __restrict__ Wb, const float* __restrict__ bb)
{
    const int dir = blockIdx.z;
    const float* __restrict__ W    = dir ? Wb : Wf;
    const float* __restrict__ bias = dir ? bb : bf;
    float* __restrict__ C = d_gx[dir];

    const int t0 = blockIdx.y * 128;
    const int o0 = blockIdx.x * 64;

    __shared__ float As[16][132];
    __shared__ float Bs[16][68];

    const int tid = threadIdx.x;
    const int tx = tid & 15, ty = tid >> 4;
    const int m0 = ty * 8, n0 = tx * 4;

    const int ar0 = tid >> 2;
    const int akq = (tid & 3) * 4;

    const float* aptr0 = feat + (size_t)(t0 + ar0)      * D_IN + akq;
    const float* aptr1 = feat + (size_t)(t0 + ar0 + 64) * D_IN + akq;
    const float* bptr  = W    + (size_t)(o0 + ar0)      * D_IN + akq;

    float4 pa0 = *(const float4*)(aptr0);
    float4 pa1 = *(const float4*)(aptr1);
    float4 pb  = *(const float4*)(bptr);

    unsigned long long acc2[4][4];
#pragma unroll
    for (int i = 0; i < 4; i++)
#pragma unroll
        for (int j = 0; j < 4; j++) acc2[i][j] = 0ull;

    for (int kt = 0; kt < D_IN; kt += 16) {
        As[akq + 0][ar0] = pa0.x; As[akq + 1][ar0] = pa0.y;
        As[akq + 2][ar0] = pa0.z; As[akq + 3][ar0] = pa0.w;
        As[akq + 0][ar0 + 64] = pa1.x; As[akq + 1][ar0 + 64] = pa1.y;
        As[akq + 2][ar0 + 64] = pa1.z; As[akq + 3][ar0 + 64] = pa1.w;
        Bs[akq + 0][ar0] = pb.x; Bs[akq + 1][ar0] = pb.y;
        Bs[akq + 2][ar0] = pb.z; Bs[akq + 3][ar0] = pb.w;
        __syncthreads();

        if (kt + 16 < D_IN) {
            pa0 = *(const float4*)(aptr0 + kt + 16);
            pa1 = *(const float4*)(aptr1 + kt + 16);
            pb  = *(const float4*)(bptr  + kt + 16);
        }

#pragma unroll
        for (int k = 0; k < 16; k++) {
            F4U a0, a1, b;
            a0.f4 = *(const float4*)&As[k][m0];
            a1.f4 = *(const float4*)&As[k][m0 + 4];
            b.f4  = *(const float4*)&Bs[k][n0];
            unsigned long long a2[4] = {a0.u[0], a0.u[1], a1.u[0], a1.u[1]};
            unsigned long long bd[4];
            PACKF2(bd[0], b.f[0], b.f[0]);
            PACKF2(bd[1], b.f[1], b.f[1]);
            PACKF2(bd[2], b.f[2], b.f[2]);
            PACKF2(bd[3], b.f[3], b.f[3]);
#pragma unroll
            for (int i = 0; i < 4; i++)
#pragma unroll
                for (int j = 0; j < 4; j++)
                    FMA_F32X2(acc2[i][j], a2[i], bd[j], acc2[i][j]);
        }
        __syncthreads();
    }

    const float4 bv4 = *(const float4*)&bias[o0 + n0];
#pragma unroll
    for (int i2 = 0; i2 < 4; i2++) {
        float2 p0 = u2f2(acc2[i2][0]);
        float2 p1 = u2f2(acc2[i2][1]);
        float2 p2 = u2f2(acc2[i2][2]);
        float2 p3 = u2f2(acc2[i2][3]);
        float4 v0, v1;
        v0.x = p0.x + bv4.x; v0.y = p1.x + bv4.y; v0.z = p2.x + bv4.z; v0.w = p3.x + bv4.w;
        v1.x = p0.y + bv4.x; v1.y = p1.y + bv4.y; v1.z = p2.y + bv4.z; v1.w = p3.y + bv4.w;
        *(float4*)&C[(size_t)(t0 + m0 + 2 * i2 + 0) * G3H + o0 + n0] = v0;
        *(float4*)&C[(size_t)(t0 + m0 + 2 * i2 + 1) * G3H + o0 + n0] = v1;
    }
}

// Separator no-ops so ncu's fixed -s 5 keeps landing on scan_kernel.
__global__ void sep_kernel_a() { if (threadIdx.x == 1024) d_dummy_sink = 1.f; }
__global__ void sep_kernel_b() { if (threadIdx.x == 1024) d_dummy_sink = 2.f; }

// =====================================================================
// Kernel 2: BiGRU scan. Grid = 16 CTAs = 2 clusters of 8 (dir = blk/8).
// 384 threads/CTA. CTA rank owns j in [32r,32r+32) + its 3 gate rows.
// Matvec layout: 48 row-PAIRS x 8 segs of 32 h. Each thread: 2 rows over
// the SAME 32 h floats (8 LDS.128, 4-way warp broadcast, conflict-free)
// -> halves crossbar bytes vs 1 row/thread. 3-shfl seg reduce; seg0
// lanes STS.64 two gh values. Combine warps 0..7 as before: gates,
// st.async h to rank cw with complete_tx, relaxed parity wait.
// =====================================================================
__global__ void __cluster_dims__(NCLUS, 1, 1) __launch_bounds__(SCAN_THREADS, 1)
scan_kernel(const float* __restrict__ Whf, const float* __restrict__ bhf,
            const float* __restrict__ Whb, const float* __restrict__ bhb)
{
    // padded h: idx(k) = k + (k>>5)*4 ; 8 segs of 32 floats at word 36*seg
    // (bank-offset 4*seg -> conflict-free float4 across segs); stride 288.
    __shared__ __align__(16) float sh_h[2 * 288];
    __shared__ __align__(8) float gh_buf[2][96];
    __shared__ __align__(8) unsigned long long mbars[2];

    const int rank = blockIdx.x & 7;
    const int dir  = blockIdx.x >> 3;
    const float* __restrict__ Whh = dir ? Whb : Whf;
    const float* __restrict__ bhh = dir ? bhb : bhf;
    const float* __restrict__ gx  = d_gx[dir];

    const int tid  = threadIdx.x;
    const int pair = tid >> 3;         // 0..47 row pair
    const int seg  = tid & 7;          // 0..7 (32 h each)
    const int r0l  = pair * 2;         // local rows r0l, r0l+1 (same gate blk)
    const int g    = r0l >> 5;         // gate 0..2 (r,z,n)
    const int jj   = r0l & 31;
    const int grow0 = (g << 8) + (rank << 5) + jj;       // global W_hh row
    const int grow1 = grow0 + 1;

    // weights in registers: 2 rows x 32 floats = 16 float4
    F4U w0[8], w1[8];
    {
        const float4* wp0 = (const float4*)(Whh + (size_t)grow0 * HID + seg * 32);
        const float4* wp1 = (const float4*)(Whh + (size_t)grow1 * HID + seg * 32);
#pragma unroll
        for (int i = 0; i < 8; i++) { w0[i].f4 = wp0[i]; w1[i].f4 = wp1[i]; }
    }
    const float bias0 = bhh[grow0];
    const float bias1 = bhh[grow1];

    for (int i = tid; i < 2 * 288; i += SCAN_THREADS) sh_h[i] = 0.f;
    const uint32_t mb0 = smem_u32(&mbars[0]);
    const uint32_t mb1 = smem_u32(&mbars[1]);
    if (tid == 0) {
        mbar_init(mb0, 1);
        mbar_init(mb1, 1);
        mbar_arrive_local(mb0);   // align parity sequences to ((s+1)>>1)&1
    }
    __syncthreads();
    asm volatile("barrier.cluster.arrive.aligned;" ::: "memory");
    asm volatile("barrier.cluster.wait.aligned;" ::: "memory");

    const float* hs0 = sh_h + 36 * seg;

    // combine warps 0..7: warp cw targets remote rank cw; own h in regs.
    const bool isComb = (tid < 256);
    const int  cw     = tid >> 5;
    const int  lane   = tid & 31;
    const int  j      = (rank << 5) + lane;                  // owned j
    const uint32_t hword = (uint32_t)(j + ((j >> 5) << 2));  // padded word idx
    uint32_t rh = 0, rmb[2] = {0, 0};
    float xr = 0.f, xz = 0.f, xn = 0.f;
    float hold = 0.f;
    int t = dir ? (T_LEN - 1) : 0;
    const int tstep = dir ? -1 : 1;
    if (isComb) {
        rh     = mapa_rank(smem_u32(&sh_h[0]), (uint32_t)cw) + hword * 4u;
        rmb[0] = mapa_rank(mb0, (uint32_t)cw);
        rmb[1] = mapa_rank(mb1, (uint32_t)cw);
        const float* gp = gx + (size_t)t * G3H + j;
        xr = gp[0]; xz = gp[HID]; xn = gp[2 * HID];
    }
    const uint32_t mbl[2] = {mb0, mb1};

#pragma unroll 2
    for (int s = 0; s < T_LEN; s++) {
        const int b = s & 1;

        // off-critical-path: declare expected tx bytes for step s+1's h
        if (tid == 256) mbar_arrive_expect_tx(mbl[b ^ 1], 8 * 32 * 4);

        // ---- matvec: 2 rows x this seg's 32 h values (h loads shared) ----
        const float* hp = hs0 + b * 288;
        unsigned long long a00 = 0ull, a01 = 0ull, a10 = 0ull, a11 = 0ull;
#pragma unroll
        for (int i = 0; i < 8; i += 2) {
            F4U h0, h1;
            h0.f4 = *(const float4*)(hp + 4 * i);
            h1.f4 = *(const float4*)(hp + 4 * i + 4);
            FMA_F32X2(a00, w0[i].u[0],     h0.u[0], a00);
            FMA_F32X2(a01, w0[i].u[1],     h0.u[1], a01);
            FMA_F32X2(a10, w1[i].u[0],     h0.u[0], a10);
            FMA_F32X2(a11, w1[i].u[1],     h0.u[1], a11);
            FMA_F32X2(a00, w0[i + 1].u[0], h1.u[0], a00);
            FMA_F32X2(a01, w0[i + 1].u[1], h1.u[1], a01);
            FMA_F32X2(a10, w1[i + 1].u[0], h1.u[0], a10);
            FMA_F32X2(a11, w1[i + 1].u[1], h1.u[1], a11);
        }
        ADD_F32X2_(a00, a00, a01);
        ADD_F32X2_(a10, a10, a11);
        float2 p0 = u2f2(a00), p1 = u2f2(a10);
        float acc0 = p0.x + p0.y;
        float acc1 = p1.x + p1.y;
        // reduce over 8 segs (lanes within 8-lane groups)
        acc0 += __shfl_down_sync(0xffffffffu, acc0, 4);
        acc1 += __shfl_down_sync(0xffffffffu, acc1, 4);
        acc0 += __shfl_down_sync(0xffffffffu, acc0, 2);
        acc1 += __shfl_down_sync(0xffffffffu, acc1, 2);
        acc0 += __shfl_down_sync(0xffffffffu, acc0, 1);
        acc1 += __shfl_down_sync(0xffffffffu, acc1, 1);
        if (seg == 0)
            *(float2*)&gh_buf[b][r0l] = make_float2(acc0 + bias0, acc1 + bias1);
        __syncthreads();

        if (isComb) {
            // redundant gate combine (identical in warps 0..7)
            const float hr = gh_buf[b][lane];
            const float hz = gh_buf[b][32 + lane];
            const float hn = gh_buf[b][64 + lane];
            const float r = fast_sigmoid(xr + hr);
            const float z = fast_sigmoid(xz + hz);
            const float n = fast_tanh(xn + r * hn);
            const float hnew = (1.f - z) * n + z * hold;
            hold = hnew;

            // one-way store+tx to rank cw's next-step buffer
            st_async_cluster_f32(rh + (uint32_t)(b ^ 1) * 1152u, hnew, rmb[b ^ 1]);
            if (cw == 0) d_h[(size_t)t * 512 + dir * HID + j] = hnew;

            // prefetch gx for next step (overlaps the wait)
            if (s + 1 < T_LEN) {
                t += tstep;
                const float* gp = gx + (size_t)t * G3H + j;
                xr = gp[0]; xz = gp[HID]; xn = gp[2 * HID];
            }
        }

        mbar_wait_parity_relaxed(mbl[b ^ 1], (uint32_t)(((s + 1) >> 1) & 1));
    }

    asm volatile("barrier.cluster.arrive.aligned;" ::: "memory");
    asm volatile("barrier.cluster.wait.aligned;" ::: "memory");
}

// =====================================================================
// Kernel 3: scores[t] = relu(h[t] @ Ws1^T + bs1) @ Ws2^T + bs2
// =====================================================================
#define SCORES_SMEM_FLOATS (64 * 516 + 64 + 64 + 32 * 512)
__global__ __launch_bounds__(512)
void scores_kernel(const float* __restrict__ Ws1, const float* __restrict__ bs1,
                   const float* __restrict__ Ws2, const float* __restrict__ bs2,
                   float* __restrict__ out)
{
    extern __shared__ float sm[];
    float* sW1 = sm;                  // 64 x 516 (padded, 16B-aligned rows)
    float* sW2 = sm + 64 * 516;       // 64
    float* sb1 = sW2 + 64;            // 64
    float* sh  = sb1 + 64;            // 32 x 512

    const int tid = threadIdx.x;
    for (int i = tid; i < 64 * 512; i += 512) {
        const int kk = i >> 9, jcol = i & 511;
        sW1[kk * 516 + jcol] = Ws1[i];
    }
    if (tid < 64) { sW2[tid] = Ws2[tid]; sb1[tid] = bs1[tid]; }
    const float bs2v = bs2[0];
    __syncthreads();

    const int warp = tid >> 5, lane = tid & 31;
    const float* w0p = sW1 + (size_t)lane * 516;
    const float* w1p = sW1 + (size_t)(lane + 32) * 516;

    for (int iter = 0; iter < 4; iter++) {
        const int r0 = blockIdx.x * 128 + iter * 32;
        __syncthreads();
        for (int e = tid * 4; e < 32 * 512; e += 512 * 4) {
            const int rrow = e >> 9, col = e & 511;
            *(float4*)&sh[e] = *(const float4*)&d_h[(size_t)(r0 + rrow) * 512 + col];
        }
        __syncthreads();

#pragma unroll
        for (int rr = 0; rr < 2; rr++) {
            const int rowl = warp * 2 + rr;
            const float* hrow = sh + (size_t)rowl * 512;
            unsigned long long c00 = 0ull, c01 = 0ull, c10 = 0ull, c11 = 0ull;
            for (int jc = 0; jc < 512; jc += 4) {
                F4U hv, w0v, w1v;
                hv.f4  = *(const float4*)(hrow + jc);
                w0v.f4 = *(const float4*)(w0p + jc);
                w1v.f4 = *(const float4*)(w1p + jc);
                FMA_F32X2(c00, hv.u[0], w0v.u[0], c00);
                FMA_F32X2(c01, hv.u[1], w0v.u[1], c01);
                FMA_F32X2(c10, hv.u[0], w1v.u[0], c10);
                FMA_F32X2(c11, hv.u[1], w1v.u[1], c11);
            }
            ADD_F32X2_(c00, c00, c01);
            ADD_F32X2_(c10, c10, c11);
            float2 s0 = u2f2(c00), s1 = u2f2(c10);
            const float acc0 = s0.x + s0.y;
            const float acc1 = s1.x + s1.y;
            float v = fmaxf(acc0 + sb1[lane], 0.f) * sW2[lane]
                    + fmaxf(acc1 + sb1[lane + 32], 0.f) * sW2[lane + 32];
#pragma unroll
            for (int o = 16; o; o >>= 1) v += __shfl_down_sync(0xffffffffu, v, o);
            if (lane == 0) out[2 + r0 + rowl] = v + bs2v;
        }
    }
}

// =====================================================================
// Kernel 4a: top-8 -> softmax weights -> clip_repr (1 CTA, 1024 thr)
// =====================================================================
__global__ __launch_bounds__(1024)
void topk_clip_kernel(const float* __restrict__ feat, const float* __restrict__ temp,
                      const float* __restrict__ out_scores)
{
    __shared__ float rv[1024];
    __shared__ int   ri[1024];
    __shared__ int   chosen[8];
    __shared__ float chval[8];
    __shared__ float wts[8];

    const float* scores = out_scores + 2;
    const int tid = threadIdx.x;

    float sc[16];
#pragma unroll
    for (int i = 0; i < 16; i++) sc[i] = scores[tid + (i << 10)];
    unsigned taken = 0;

    for (int k = 0; k < 8; k++) {
        float best = -3.4e38f; int bi = 0x7fffffff;
#pragma unroll
        for (int i = 0; i < 16; i++) {
            const int jg = tid + (i << 10);
            const float v = sc[i];
            if (!(taken & (1u << i)) && (v > best || (v == best && jg < bi))) {
                best = v; bi = jg;
            }
        }
        rv[tid] = best; ri[tid] = bi;
        __syncthreads();
        for (int s = 512; s; s >>= 1) {
            if (tid < s) {
                if (rv[tid + s] > rv[tid] ||
                    (rv[tid + s] == rv[tid] && ri[tid + s] < ri[tid])) {
                    rv[tid] = rv[tid + s]; ri[tid] = ri[tid + s];
                }
            }
            __syncthreads();
        }
        if (tid == 0) { chosen[k] = ri[0]; chval[k] = rv[0]; }
        __syncthreads();
        const int ck = chosen[k];
        if ((ck & 1023) == tid) taken |= 1u << (ck >> 10);
    }

    if (tid == 0) {
        const float tmp = temp[0];
        float m = chval[0];
        for (int k = 1; k < 8; k++) m = fmaxf(m, chval[k]);
        float ssum = 0.f;
        for (int k = 0; k < 8; k++) { const float e = expf((chval[k] - m) / tmp); wts[k] = e; ssum += e; }
        for (int k = 0; k < 8; k++) { wts[k] /= ssum; d_wts[k] = wts[k]; d_chosen[k] = chosen[k]; }
    }
    __syncthreads();

    for (int d = tid; d < D_IN; d += 1024) {
        float c = 0.f;
#pragma unroll
        for (int k = 0; k < 8; k++)
            c = fmaf(wts[k], feat[(size_t)chosen[k] * D_IN + d], c);
        d_clip[d] = c;
    }
}

// =====================================================================
// Kernel 4b: c1 = relu(Wc1 @ clip + bc1), 16 CTAs x 256 thr (16 thr/row)
// =====================================================================
__global__ __launch_bounds__(256)
void classify_kernel(const float* __restrict__ Wc1, const float* __restrict__ bc1)
{
    const int tid = threadIdx.x;
    const int o = blockIdx.x * 16 + (tid >> 4);
    const int part = tid & 15;
    const float* wr = Wc1 + (size_t)o * D_IN + part * 128;
    const float* cp = d_clip + part * 128;
    float s0 = 0.f, s1 = 0.f, s2 = 0.f, s3 = 0.f;
#pragma unroll
    for (int jc = 0; jc < 128; jc += 16) {
        const float4 c0 = *(const float4*)(cp + jc);
        const float4 w0 = *(const float4*)(wr + jc);
        const float4 c1v = *(const float4*)(cp + jc + 4);
        const float4 w1 = *(const float4*)(wr + jc + 4);
        const float4 c2 = *(const float4*)(cp + jc + 8);
        const float4 w2 = *(const float4*)(wr + jc + 8);
        const float4 c3 = *(const float4*)(cp + jc + 12);
        const float4 w3 = *(const float4*)(wr + jc + 12);
        s0 = fmaf(c0.x, w0.x, s0); s0 = fmaf(c0.y, w0.y, s0);
        s0 = fmaf(c0.z, w0.z, s0); s0 = fmaf(c0.w, w0.w, s0);
        s1 = fmaf(c1v.x, w1.x, s1); s1 = fmaf(c1v.y, w1.y, s1);
        s1 = fmaf(c1v.z, w1.z, s1); s1 = fmaf(c1v.w, w1.w, s1);
        s2 = fmaf(c2.x, w2.x, s2); s2 = fmaf(c2.y, w2.y, s2);
        s2 = fmaf(c2.z, w2.z, s2); s2 = fmaf(c2.w, w2.w, s2);
        s3 = fmaf(c3.x, w3.x, s3); s3 = fmaf(c3.y, w3.y, s3);
        s3 = fmaf(c3.z, w3.z, s3); s3 = fmaf(c3.w, w3.w, s3);
    }
    float s = (s0 + s1) + (s2 + s3);
    s += __shfl_down_sync(0xffffffffu, s, 8, 16);
    s += __shfl_down_sync(0xffffffffu, s, 4, 16);
    s += __shfl_down_sync(0xffffffffu, s, 2, 16);
    s += __shfl_down_sync(0xffffffffu, s, 1, 16);
    if (part == 0) d_c1[o] = fmaxf(s + bc1[o], 0.f);
}

// =====================================================================
// Kernel 4c: logits = c1 @ Wc2^T + bc2 (1 CTA, 64 thr)
// =====================================================================
__global__ __launch_bounds__(64)
void logits_kernel(const float* __restrict__ Wc2, const float* __restrict__ bc2,
                   float* __restrict__ out)
{
    const int tid = threadIdx.x;
    const int c = tid >> 5, lane = tid & 31;
    float s = 0.f;
    for (int kk = lane; kk < 256; kk += 32)
        s = fmaf(d_c1[kk], Wc2[(size_t)c * 256 + kk], s);
#pragma unroll
    for (int o = 16; o; o >>= 1) s += __shfl_down_sync(0xffffffffu, s, o);
    if (lane == 0) out[c] = s + bc2[c];
}

// =====================================================================
extern "C" void kernel_launch(void* const* d_in, const int* in_sizes, int n_in,
                              void* d_out, int out_size)
{
    const float* feat   = (const float*)d_in[0];
    const float* temp   = (const float*)d_in[1];
    const float* W_ih_f = (const float*)d_in[2];
    const float* W_hh_f = (const float*)d_in[3];
    const float* b_ih_f = (const float*)d_in[4];
    const float* b_hh_f = (const float*)d_in[5];
    const float* W_ih_b = (const float*)d_in[6];
    const float* W_hh_b = (const float*)d_in[7];
    const float* b_ih_b = (const float*)d_in[8];
    const float* b_hh_b = (const float*)d_in[9];
    const float* Ws1    = (const float*)d_in[10];
    const float* bs1    = (const float*)d_in[11];
    const float* Ws2    = (const float*)d_in[12];
    const float* bs2    = (const float*)d_in[13];
    const float* Wc1    = (const float*)d_in[14];
    const float* bc1    = (const float*)d_in[15];
    const float* Wc2    = (const float*)d_in[16];
    const float* bc2    = (const float*)d_in[17];
    float* out = (float*)d_out;

    // 1) input projections (both directions)
    gemm_gx_kernel<<<dim3(12, 128, 2), 256>>>(feat, W_ih_f, b_ih_f, W_ih_b, b_ih_b);

    // separators: keep scan_kernel aligned with ncu's fixed skip count (-s 5)
    sep_kernel_a<<<1, 32>>>();
    sep_kernel_b<<<1, 32>>>();

    // 2) BiGRU scan: 2 clusters of 8 CTAs
    scan_kernel<<<16, SCAN_THREADS>>>(W_hh_f, b_hh_f, W_hh_b, b_hh_b);

    // 3) frame scores
    cudaFuncSetAttribute(scores_kernel, cudaFuncAttributeMaxDynamicSharedMemorySize,
                         SCORES_SMEM_FLOATS * 4);
    scores_kernel<<<128, 512, SCORES_SMEM_FLOATS * 4>>>(Ws1, bs1, Ws2, bs2, out);

    // 4) top-k + softmax + weighted sum + classifier
    topk_clip_kernel<<<1, 1024>>>(feat, temp, out);
    classify_kernel<<<16, 256>>>(Wc1, bc1);
    logits_kernel<<<1, 64>>>(Wc2, bc2, out);
}

// round 14
// speedup vs baseline: 2.1146x; 1.0367x over previous
#include <cuda_runtime.h>
#include <cstdint>
#include <math.h>

#define T_LEN 16384
#define D_IN  2048
#define HID   256
#define G3H   768
#define NCLUS 8
#define SCAN_THREADS 256

// ---------------- device scratch (static, no allocation) ----------------
__device__ float d_gx[2][(size_t)T_LEN * G3H];   // input projections, both dirs
__device__ float d_h[(size_t)T_LEN * 512];       // concat(h_f, h_b)
__device__ float d_clip[D_IN];
__device__ float d_wts[8];
__device__ int   d_chosen[8];
__device__ float d_c1[256];
__device__ float d_dummy_sink;

// ---------------- helpers ----------------
union F4U { float4 f4; unsigned long long u[2]; float f[4]; float2 f2[2]; };

#define FMA_F32X2(d, a, b, c) \
    asm("fma.rn.f32x2 %0, %1, %2, %3;" : "=l"(d) : "l"(a), "l"(b), "l"(c))
#define ADD_F32X2_(d, a, b) \
    asm("add.rn.f32x2 %0, %1, %2;" : "=l"(d) : "l"(a), "l"(b))
#define PACKF2(u, x, y) \
    asm("mov.b64 %0, {%1, %2};" : "=l"(u) : "f"(x), "f"(y))

__device__ __forceinline__ float2 u2f2(unsigned long long u) {
    float2 r; asm("mov.b64 {%0, %1}, %2;" : "=f"(r.x), "=f"(r.y) : "l"(u)); return r;
}
__device__ __forceinline__ uint32_t smem_u32(const void* p) {
    return (uint32_t)__cvta_generic_to_shared(p);
}
__device__ __forceinline__ uint32_t mapa_rank(uint32_t addr, uint32_t rank) {
    uint32_t d;
    asm("mapa.shared::cluster.u32 %0, %1, %2;" : "=r"(d) : "r"(addr), "r"(rank));
    return d;
}
__device__ __forceinline__ void mbar_init(uint32_t addr, uint32_t cnt) {
    asm volatile("mbarrier.init.shared.b64 [%0], %1;" :: "r"(addr), "r"(cnt) : "memory");
}
__device__ __forceinline__ void mbar_arrive_local(uint32_t addr) {
    asm volatile("mbarrier.arrive.shared.b64 _, [%0];" :: "r"(addr) : "memory");
}
__device__ __forceinline__ void mbar_arrive_expect_tx(uint32_t addr, uint32_t tx) {
    asm volatile("mbarrier.arrive.expect_tx.shared.b64 _, [%0], %1;"
                 :: "r"(addr), "r"(tx) : "memory");
}
// One-way remote store with transaction accounting on the TARGET CTA's
// mbarrier: data lands + tx-count updated atomically by HW.
__device__ __forceinline__ void st_async_cluster_f32(uint32_t daddr, float v, uint32_t mbar) {
    asm volatile(
        "st.async.shared::cluster.mbarrier::complete_tx::bytes.b32 [%0], %1, [%2];"
        :: "r"(daddr), "r"(__float_as_uint(v)), "r"(mbar) : "memory");
}
// RELAXED wait: tx-completion semantics guarantee landed data (TMA-style).
__device__ __forceinline__ void mbar_wait_parity_relaxed(uint32_t addr, uint32_t par) {
    asm volatile(
        "{\n\t.reg .pred P;\n\t"
        "W%=:\n\t"
        "mbarrier.try_wait.parity.relaxed.cta.shared::cta.b64 P, [%0], %1, 0x989680;\n\t"
        "@P bra D%=;\n\t"
        "bra W%=;\n\t"
        "D%=:\n\t}"
        :: "r"(addr), "r"(par) : "memory");
}
// fast sigmoid / tanh (MUFU-based, ~1e-7 rel err)
__device__ __forceinline__ float fast_sigmoid(float x) {
    return __fdividef(1.f, 1.f + __expf(-x));
}
__device__ __forceinline__ float fast_tanh(float x) {
    return __fdividef(2.f, 1.f + __expf(-2.f * x)) - 1.f;
}

// =====================================================================
// Kernel 1: gx[dir] = feat @ W_ih[dir]^T + b_ih[dir]
// =====================================================================
__global__ __launch_bounds__(256)
void gemm_gx_kernel(const float* __restrict__ feat,
                    const float* __restrict__ Wf, const float* __restrict__ bf,
                    const float* __restrict__ Wb, const float* __restrict__ bb)
{
    const int dir = blockIdx.z;
    const float* __restrict__ W    = dir ? Wb : Wf;
    const float* __restrict__ bias = dir ? bb : bf;
    float* __restrict__ C = d_gx[dir];

    const int t0 = blockIdx.y * 128;
    const int o0 = blockIdx.x * 64;

    __shared__ float As[16][132];
    __shared__ float Bs[16][68];

    const int tid = threadIdx.x;
    const int tx = tid & 15, ty = tid >> 4;
    const int m0 = ty * 8, n0 = tx * 4;

    const int ar0 = tid >> 2;
    const int akq = (tid & 3) * 4;

    const float* aptr0 = feat + (size_t)(t0 + ar0)      * D_IN + akq;
    const float* aptr1 = feat + (size_t)(t0 + ar0 + 64) * D_IN + akq;
    const float* bptr  = W    + (size_t)(o0 + ar0)      * D_IN + akq;

    float4 pa0 = *(const float4*)(aptr0);
    float4 pa1 = *(const float4*)(aptr1);
    float4 pb  = *(const float4*)(bptr);

    unsigned long long acc2[4][4];
#pragma unroll
    for (int i = 0; i < 4; i++)
#pragma unroll
        for (int j = 0; j < 4; j++) acc2[i][j] = 0ull;

    for (int kt = 0; kt < D_IN; kt += 16) {
        As[akq + 0][ar0] = pa0.x; As[akq + 1][ar0] = pa0.y;
        As[akq + 2][ar0] = pa0.z; As[akq + 3][ar0] = pa0.w;
        As[akq + 0][ar0 + 64] = pa1.x; As[akq + 1][ar0 + 64] = pa1.y;
        As[akq + 2][ar0 + 64] = pa1.z; As[akq + 3][ar0 + 64] = pa1.w;
        Bs[akq + 0][ar0] = pb.x; Bs[akq + 1][ar0] = pb.y;
        Bs[akq + 2][ar0] = pb.z; Bs[akq + 3][ar0] = pb.w;
        __syncthreads();

        if (kt + 16 < D_IN) {
            pa0 = *(const float4*)(aptr0 + kt + 16);
            pa1 = *(const float4*)(aptr1 + kt + 16);
            pb  = *(const float4*)(bptr  + kt + 16);
        }

#pragma unroll
        for (int k = 0; k < 16; k++) {
            F4U a0, a1, b;
            a0.f4 = *(const float4*)&As[k][m0];
            a1.f4 = *(const float4*)&As[k][m0 + 4];
            b.f4  = *(const float4*)&Bs[k][n0];
            unsigned long long a2[4] = {a0.u[0], a0.u[1], a1.u[0], a1.u[1]};
            unsigned long long bd[4];
            PACKF2(bd[0], b.f[0], b.f[0]);
            PACKF2(bd[1], b.f[1], b.f[1]);
            PACKF2(bd[2], b.f[2], b.f[2]);
            PACKF2(bd[3], b.f[3], b.f[3]);
#pragma unroll
            for (int i = 0; i < 4; i++)
#pragma unroll
                for (int j = 0; j < 4; j++)
                    FMA_F32X2(acc2[i][j], a2[i], bd[j], acc2[i][j]);
        }
        __syncthreads();
    }

    const float4 bv4 = *(const float4*)&bias[o0 + n0];
#pragma unroll
    for (int i2 = 0; i2 < 4; i2++) {
        float2 p0 = u2f2(acc2[i2][0]);
        float2 p1 = u2f2(acc2[i2][1]);
        float2 p2 = u2f2(acc2[i2][2]);
        float2 p3 = u2f2(acc2[i2][3]);
        float4 v0, v1;
        v0.x = p0.x + bv4.x; v0.y = p1.x + bv4.y; v0.z = p2.x + bv4.z; v0.w = p3.x + bv4.w;
        v1.x = p0.y + bv4.x; v1.y = p1.y + bv4.y; v1.z = p2.y + bv4.z; v1.w = p3.y + bv4.w;
        *(float4*)&C[(size_t)(t0 + m0 + 2 * i2 + 0) * G3H + o0 + n0] = v0;
        *(float4*)&C[(size_t)(t0 + m0 + 2 * i2 + 1) * G3H + o0 + n0] = v1;
    }
}

// Separator no-ops so ncu's fixed -s 5 keeps landing on scan_kernel.
__global__ void sep_kernel_a() { if (threadIdx.x == 1024) d_dummy_sink = 1.f; }
__global__ void sep_kernel_b() { if (threadIdx.x == 1024) d_dummy_sink = 2.f; }

// =====================================================================
// Kernel 2: BiGRU scan. Grid = 16 CTAs = 2 clusters of 8 (dir = blk/8).
// 256 threads/CTA (8 warps). CTA rank owns j in [32r,32r+32).
// Thread (jloc, seg) owns ALL THREE gate rows (r,z,n) of j over seg's
// 32 h values (24 float4 of W in regs). Per step:
//   8x LDS.128 h (shared by 3 rows) -> 48 FMA2 -> 3x3 shfl_xor butterfly
//   over the 8-lane seg group (every lane gets all 3 full gate sums) ->
//   redundant gate combine on all lanes -> lane seg st.async's h[j] to
//   rank seg with complete_tx -> relaxed parity wait. NO __syncthreads,
//   no gh smem round-trip, no separate combine warps.
// =====================================================================
__global__ void __cluster_dims__(NCLUS, 1, 1) __launch_bounds__(SCAN_THREADS, 1)
scan_kernel(const float* __restrict__ Whf, const float* __restrict__ bhf,
            const float* __restrict__ Whb, const float* __restrict__ bhb)
{
    // padded h: idx(k) = k + (k>>5)*4 ; 8 segs of 32 floats at word 36*seg
    // (conflict-free float4 across segs, 4-way broadcast); stride 288.
    __shared__ __align__(16) float sh_h[2 * 288];
    __shared__ __align__(8) unsigned long long mbars[2];

    const int rank = blockIdx.x & 7;
    const int dir  = blockIdx.x >> 3;
    const float* __restrict__ Whh = dir ? Whb : Whf;
    const float* __restrict__ bhh = dir ? bhb : bhf;
    const float* __restrict__ gx  = d_gx[dir];

    const int tid  = threadIdx.x;
    const int jloc = tid >> 3;         // 0..31 owned hidden unit
    const int seg  = tid & 7;          // 0..7 (32 h each); also target rank
    const int j    = (rank << 5) + jloc;

    // W rows for gates r (row j), z (256+j), n (512+j), this seg's 32 cols
    F4U wr[8], wz[8], wn[8];
    {
        const float4* pr = (const float4*)(Whh + (size_t)(j)       * HID + seg * 32);
        const float4* pz = (const float4*)(Whh + (size_t)(256 + j) * HID + seg * 32);
        const float4* pn = (const float4*)(Whh + (size_t)(512 + j) * HID + seg * 32);
#pragma unroll
        for (int i = 0; i < 8; i++) { wr[i].f4 = pr[i]; wz[i].f4 = pz[i]; wn[i].f4 = pn[i]; }
    }
    const float biasr = bhh[j];
    const float biasz = bhh[256 + j];
    const float biasn = bhh[512 + j];

    for (int i = tid; i < 2 * 288; i += SCAN_THREADS) sh_h[i] = 0.f;
    const uint32_t mb0 = smem_u32(&mbars[0]);
    const uint32_t mb1 = smem_u32(&mbars[1]);
    if (tid == 0) {
        mbar_init(mb0, 1);
        mbar_init(mb1, 1);
        mbar_arrive_local(mb0);   // align parity sequences to ((s+1)>>1)&1
    }
    __syncthreads();
    asm volatile("barrier.cluster.arrive.aligned;" ::: "memory");
    asm volatile("barrier.cluster.wait.aligned;" ::: "memory");

    const float* hs0 = sh_h + 36 * seg;
    const uint32_t hword = (uint32_t)(j + ((j >> 5) << 2));   // padded word idx

    // remote targets: this lane ships h[j] to rank 'seg'
    const uint32_t rh     = mapa_rank(smem_u32(&sh_h[0]), (uint32_t)seg) + hword * 4u;
    const uint32_t rmb[2] = { mapa_rank(mb0, (uint32_t)seg),
                              mapa_rank(mb1, (uint32_t)seg) };
    const uint32_t mbl[2] = { mb0, mb1 };

    int t = dir ? (T_LEN - 1) : 0;
    const int tstep = dir ? -1 : 1;
    float hold = 0.f;
    float xr, xz, xn;
    {
        const float* gp = gx + (size_t)t * G3H + j;
        xr = gp[0]; xz = gp[HID]; xn = gp[2 * HID];
    }

#pragma unroll 2
    for (int s = 0; s < T_LEN; s++) {
        const int b = s & 1;

        // declare expected tx bytes for step s+1's h (8 src CTAs x 32 x 4B)
        if (tid == 0) mbar_arrive_expect_tx(mbl[b ^ 1], 8 * 32 * 4);

        // ---- matvec: 3 gate rows x this seg's 32 h (h loads shared) ----
        const float* hp = hs0 + b * 288;
        unsigned long long ar0 = 0ull, ar1 = 0ull, az0 = 0ull, az1 = 0ull,
                           an0 = 0ull, an1 = 0ull;
#pragma unroll
        for (int i = 0; i < 8; i += 2) {
            F4U h0, h1;
            h0.f4 = *(const float4*)(hp + 4 * i);
            h1.f4 = *(const float4*)(hp + 4 * i + 4);
            FMA_F32X2(ar0, wr[i].u[0],     h0.u[0], ar0);
            FMA_F32X2(ar1, wr[i].u[1],     h0.u[1], ar1);
            FMA_F32X2(az0, wz[i].u[0],     h0.u[0], az0);
            FMA_F32X2(az1, wz[i].u[1],     h0.u[1], az1);
            FMA_F32X2(an0, wn[i].u[0],     h0.u[0], an0);
            FMA_F32X2(an1, wn[i].u[1],     h0.u[1], an1);
            FMA_F32X2(ar0, wr[i + 1].u[0], h1.u[0], ar0);
            FMA_F32X2(ar1, wr[i + 1].u[1], h1.u[1], ar1);
            FMA_F32X2(az0, wz[i + 1].u[0], h1.u[0], az0);
            FMA_F32X2(az1, wz[i + 1].u[1], h1.u[1], az1);
            FMA_F32X2(an0, wn[i + 1].u[0], h1.u[0], an0);
            FMA_F32X2(an1, wn[i + 1].u[1], h1.u[1], an1);
        }
        ADD_F32X2_(ar0, ar0, ar1);
        ADD_F32X2_(az0, az0, az1);
        ADD_F32X2_(an0, an0, an1);
        float2 prx = u2f2(ar0), pzx = u2f2(az0), pnx = u2f2(an0);
        float gr = prx.x + prx.y;
        float gz = pzx.x + pzx.y;
        float gn = pnx.x + pnx.y;
        // butterfly over the 8-lane seg group: ALL lanes get full sums
#pragma unroll
        for (int d = 4; d; d >>= 1) {
            gr += __shfl_xor_sync(0xffffffffu, gr, d);
            gz += __shfl_xor_sync(0xffffffffu, gz, d);
            gn += __shfl_xor_sync(0xffffffffu, gn, d);
        }

        // ---- gate combine (redundant across the 8 lanes of the group) ----
        const float r = fast_sigmoid(xr + gr + biasr);
        const float z = fast_sigmoid(xz + gz + biasz);
        const float n = fast_tanh(xn + r * (gn + biasn));
        const float hnew = (1.f - z) * n + z * hold;
        hold = hnew;

        // lane 'seg' ships h[j] to rank 'seg' (one-way store+tx)
        st_async_cluster_f32(rh + (uint32_t)(b ^ 1) * 1152u, hnew, rmb[b ^ 1]);
        if (seg == 0) d_h[(size_t)t * 512 + dir * HID + j] = hnew;

        // prefetch gx for next step (overlaps the wait; L1-broadcast)
        if (s + 1 < T_LEN) {
            t += tstep;
            const float* gp = gx + (size_t)t * G3H + j;
            xr = gp[0]; xz = gp[HID]; xn = gp[2 * HID];
        }

        mbar_wait_parity_relaxed(mbl[b ^ 1], (uint32_t)(((s + 1) >> 1) & 1));
    }

    asm volatile("barrier.cluster.arrive.aligned;" ::: "memory");
    asm volatile("barrier.cluster.wait.aligned;" ::: "memory");
}

// =====================================================================
// Kernel 3: scores[t] = relu(h[t] @ Ws1^T + bs1) @ Ws2^T + bs2
// =====================================================================
#define SCORES_SMEM_FLOATS (64 * 516 + 64 + 64 + 32 * 512)
__global__ __launch_bounds__(512)
void scores_kernel(const float* __restrict__ Ws1, const float* __restrict__ bs1,
                   const float* __restrict__ Ws2, const float* __restrict__ bs2,
                   float* __restrict__ out)
{
    extern __shared__ float sm[];
    float* sW1 = sm;                  // 64 x 516 (padded, 16B-aligned rows)
    float* sW2 = sm + 64 * 516;       // 64
    float* sb1 = sW2 + 64;            // 64
    float* sh  = sb1 + 64;            // 32 x 512

    const int tid = threadIdx.x;
    for (int i = tid; i < 64 * 512; i += 512) {
        const int kk = i >> 9, jcol = i & 511;
        sW1[kk * 516 + jcol] = Ws1[i];
    }
    if (tid < 64) { sW2[tid] = Ws2[tid]; sb1[tid] = bs1[tid]; }
    const float bs2v = bs2[0];
    __syncthreads();

    const int warp = tid >> 5, lane = tid & 31;
    const float* w0p = sW1 + (size_t)lane * 516;
    const float* w1p = sW1 + (size_t)(lane + 32) * 516;

    for (int iter = 0; iter < 4; iter++) {
        const int r0 = blockIdx.x * 128 + iter * 32;
        __syncthreads();
        for (int e = tid * 4; e < 32 * 512; e += 512 * 4) {
            const int rrow = e >> 9, col = e & 511;
            *(float4*)&sh[e] = *(const float4*)&d_h[(size_t)(r0 + rrow) * 512 + col];
        }
        __syncthreads();

#pragma unroll
        for (int rr = 0; rr < 2; rr++) {
            const int rowl = warp * 2 + rr;
            const float* hrow = sh + (size_t)rowl * 512;
            unsigned long long c00 = 0ull, c01 = 0ull, c10 = 0ull, c11 = 0ull;
            for (int jc = 0; jc < 512; jc += 4) {
                F4U hv, w0v, w1v;
                hv.f4  = *(const float4*)(hrow + jc);
                w0v.f4 = *(const float4*)(w0p + jc);
                w1v.f4 = *(const float4*)(w1p + jc);
                FMA_F32X2(c00, hv.u[0], w0v.u[0], c00);
                FMA_F32X2(c01, hv.u[1], w0v.u[1], c01);
                FMA_F32X2(c10, hv.u[0], w1v.u[0], c10);
                FMA_F32X2(c11, hv.u[1], w1v.u[1], c11);
            }
            ADD_F32X2_(c00, c00, c01);
            ADD_F32X2_(c10, c10, c11);
            float2 s0 = u2f2(c00), s1 = u2f2(c10);
            const float acc0 = s0.x + s0.y;
            const float acc1 = s1.x + s1.y;
            float v = fmaxf(acc0 + sb1[lane], 0.f) * sW2[lane]
                    + fmaxf(acc1 + sb1[lane + 32], 0.f) * sW2[lane + 32];
#pragma unroll
            for (int o = 16; o; o >>= 1) v += __shfl_down_sync(0xffffffffu, v, o);
            if (lane == 0) out[2 + r0 + rowl] = v + bs2v;
        }
    }
}

// =====================================================================
// Kernel 4a: top-8 -> softmax weights -> clip_repr (1 CTA, 1024 thr)
// =====================================================================
__global__ __launch_bounds__(1024)
void topk_clip_kernel(const float* __restrict__ feat, const float* __restrict__ temp,
                      const float* __restrict__ out_scores)
{
    __shared__ float rv[1024];
    __shared__ int   ri[1024];
    __shared__ int   chosen[8];
    __shared__ float chval[8];
    __shared__ float wts[8];

    const float* scores = out_scores + 2;
    const int tid = threadIdx.x;

    float sc[16];
#pragma unroll
    for (int i = 0; i < 16; i++) sc[i] = scores[tid + (i << 10)];
    unsigned taken = 0;

    for (int k = 0; k < 8; k++) {
        float best = -3.4e38f; int bi = 0x7fffffff;
#pragma unroll
        for (int i = 0; i < 16; i++) {
            const int jg = tid + (i << 10);
            const float v = sc[i];
            if (!(taken & (1u << i)) && (v > best || (v == best && jg < bi))) {
                best = v; bi = jg;
            }
        }
        rv[tid] = best; ri[tid] = bi;
        __syncthreads();
        for (int s = 512; s; s >>= 1) {
            if (tid < s) {
                if (rv[tid + s] > rv[tid] ||
                    (rv[tid + s] == rv[tid] && ri[tid + s] < ri[tid])) {
                    rv[tid] = rv[tid + s]; ri[tid] = ri[tid + s];
                }
            }
            __syncthreads();
        }
        if (tid == 0) { chosen[k] = ri[0]; chval[k] = rv[0]; }
        __syncthreads();
        const int ck = chosen[k];
        if ((ck & 1023) == tid) taken |= 1u << (ck >> 10);
    }

    if (tid == 0) {
        const float tmp = temp[0];
        float m = chval[0];
        for (int k = 1; k < 8; k++) m = fmaxf(m, chval[k]);
        float ssum = 0.f;
        for (int k = 0; k < 8; k++) { const float e = expf((chval[k] - m) / tmp); wts[k] = e; ssum += e; }
        for (int k = 0; k < 8; k++) { wts[k] /= ssum; d_wts[k] = wts[k]; d_chosen[k] = chosen[k]; }
    }
    __syncthreads();

    for (int d = tid; d < D_IN; d += 1024) {
        float c = 0.f;
#pragma unroll
        for (int k = 0; k < 8; k++)
            c = fmaf(wts[k], feat[(size_t)chosen[k] * D_IN + d], c);
        d_clip[d] = c;
    }
}

// =====================================================================
// Kernel 4b: c1 = relu(Wc1 @ clip + bc1), 16 CTAs x 256 thr (16 thr/row)
// =====================================================================
__global__ __launch_bounds__(256)
void classify_kernel(const float* __restrict__ Wc1, const float* __restrict__ bc1)
{
    const int tid = threadIdx.x;
    const int o = blockIdx.x * 16 + (tid >> 4);
    const int part = tid & 15;
    const float* wr = Wc1 + (size_t)o * D_IN + part * 128;
    const float* cp = d_clip + part * 128;
    float s0 = 0.f, s1 = 0.f, s2 = 0.f, s3 = 0.f;
#pragma unroll
    for (int jc = 0; jc < 128; jc += 16) {
        const float4 c0 = *(const float4*)(cp + jc);
        const float4 w0 = *(const float4*)(wr + jc);
        const float4 c1v = *(const float4*)(cp + jc + 4);
        const float4 w1 = *(const float4*)(wr + jc + 4);
        const float4 c2 = *(const float4*)(cp + jc + 8);
        const float4 w2 = *(const float4*)(wr + jc + 8);
        const float4 c3 = *(const float4*)(cp + jc + 12);
        const float4 w3 = *(const float4*)(wr + jc + 12);
        s0 = fmaf(c0.x, w0.x, s0); s0 = fmaf(c0.y, w0.y, s0);
        s0 = fmaf(c0.z, w0.z, s0); s0 = fmaf(c0.w, w0.w, s0);
        s1 = fmaf(c1v.x, w1.x, s1); s1 = fmaf(c1v.y, w1.y, s1);
        s1 = fmaf(c1v.z, w1.z, s1); s1 = fmaf(c1v.w, w1.w, s1);
        s2 = fmaf(c2.x, w2.x, s2); s2 = fmaf(c2.y, w2.y, s2);
        s2 = fmaf(c2.z, w2.z, s2); s2 = fmaf(c2.w, w2.w, s2);
        s3 = fmaf(c3.x, w3.x, s3); s3 = fmaf(c3.y, w3.y, s3);
        s3 = fmaf(c3.z, w3.z, s3); s3 = fmaf(c3.w, w3.w, s3);
    }
    float s = (s0 + s1) + (s2 + s3);
    s += __shfl_down_sync(0xffffffffu, s, 8, 16);
    s += __shfl_down_sync(0xffffffffu, s, 4, 16);
    s += __shfl_down_sync(0xffffffffu, s, 2, 16);
    s += __shfl_down_sync(0xffffffffu, s, 1, 16);
    if (part == 0) d_c1[o] = fmaxf(s + bc1[o], 0.f);
}

// =====================================================================
// Kernel 4c: logits = c1 @ Wc2^T + bc2 (1 CTA, 64 thr)
// =====================================================================
__global__ __launch_bounds__(64)
void logits_kernel(const float* __restrict__ Wc2, const float* __restrict__ bc2,
                   float* __restrict__ out)
{
    const int tid = threadIdx.x;
    const int c = tid >> 5, lane = tid & 31;
    float s = 0.f;
    for (int kk = lane; kk < 256; kk += 32)
        s = fmaf(d_c1[kk], Wc2[(size_t)c * 256 + kk], s);
#pragma unroll
    for (int o = 16; o; o >>= 1) s += __shfl_down_sync(0xffffffffu, s, o);
    if (lane == 0) out[c] = s + bc2[c];
}

// =====================================================================
extern "C" void kernel_launch(void* const* d_in, const int* in_sizes, int n_in,
                              void* d_out, int out_size)
{
    const float* feat   = (const float*)d_in[0];
    const float* temp   = (const float*)d_in[1];
    const float* W_ih_f = (const float*)d_in[2];
    const float* W_hh_f = (const float*)d_in[3];
    const float* b_ih_f = (const float*)d_in[4];
    const float* b_hh_f = (const float*)d_in[5];
    const float* W_ih_b = (const float*)d_in[6];
    const float* W_hh_b = (const float*)d_in[7];
    const float* b_ih_b = (const float*)d_in[8];
    const float* b_hh_b = (const float*)d_in[9];
    const float* Ws1    = (const float*)d_in[10];
    const float* bs1    = (const float*)d_in[11];
    const float* Ws2    = (const float*)d_in[12];
    const float* bs2    = (const float*)d_in[13];
    const float* Wc1    = (const float*)d_in[14];
    const float* bc1    = (const float*)d_in[15];
    const float* Wc2    = (const float*)d_in[16];
    const float* bc2    = (const float*)d_in[17];
    float* out = (float*)d_out;

    // 1) input projections (both directions)
    gemm_gx_kernel<<<dim3(12, 128, 2), 256>>>(feat, W_ih_f, b_ih_f, W_ih_b, b_ih_b);

    // separators: keep scan_kernel aligned with ncu's fixed skip count (-s 5)
    sep_kernel_a<<<1, 32>>>();
    sep_kernel_b<<<1, 32>>>();

    // 2) BiGRU scan: 2 clusters of 8 CTAs
    scan_kernel<<<16, SCAN_THREADS>>>(W_hh_f, b_hh_f, W_hh_b, b_hh_b);

    // 3) frame scores
    cudaFuncSetAttribute(scores_kernel, cudaFuncAttributeMaxDynamicSharedMemorySize,
                         SCORES_SMEM_FLOATS * 4);
    scores_kernel<<<128, 512, SCORES_SMEM_FLOATS * 4>>>(Ws1, bs1, Ws2, bs2, out);

    // 4) top-k + softmax + weighted sum + classifier
    topk_clip_kernel<<<1, 1024>>>(feat, temp, out);
    classify_kernel<<<16, 256>>>(Wc1, bc1);
    logits_kernel<<<1, 64>>>(Wc2, bc2, out);
}

// round 15
// speedup vs baseline: 2.3360x; 1.1047x over previous
#include <cuda_runtime.h>
#include <cstdint>
#include <math.h>

#define T_LEN 16384
#define D_IN  2048
#define HID   256
#define G3H   768
#define NCLUS 8
#define FUSED_THREADS 256
#define GEMM_CTAS 3072           // 12 x 128 x 2
#define FUSED_GRID (16 + GEMM_CTAS)

// ---------------- device scratch (static, no allocation) ----------------
__device__ float d_gx[2][(size_t)T_LEN * G3H];   // input projections, both dirs
__device__ float d_h[(size_t)T_LEN * 512];       // concat(h_f, h_b)
__device__ float d_clip[D_IN];
__device__ float d_wts[8];
__device__ int   d_chosen[8];
__device__ float d_c1[256];
__device__ int   d_ready_cnt[2][128];            // monotonic chunk counters

// ---------------- helpers ----------------
union F4U { float4 f4; unsigned long long u[2]; float f[4]; float2 f2[2]; };

#define FMA_F32X2(d, a, b, c) \
    asm("fma.rn.f32x2 %0, %1, %2, %3;" : "=l"(d) : "l"(a), "l"(b), "l"(c))
#define ADD_F32X2_(d, a, b) \
    asm("add.rn.f32x2 %0, %1, %2;" : "=l"(d) : "l"(a), "l"(b))
#define PACKF2(u, x, y) \
    asm("mov.b64 %0, {%1, %2};" : "=l"(u) : "f"(x), "f"(y))

__device__ __forceinline__ float2 u2f2(unsigned long long u) {
    float2 r; asm("mov.b64 {%0, %1}, %2;" : "=f"(r.x), "=f"(r.y) : "l"(u)); return r;
}
__device__ __forceinline__ uint32_t smem_u32(const void* p) {
    return (uint32_t)__cvta_generic_to_shared(p);
}
__device__ __forceinline__ uint32_t mapa_rank(uint32_t addr, uint32_t rank) {
    uint32_t d;
    asm("mapa.shared::cluster.u32 %0, %1, %2;" : "=r"(d) : "r"(addr), "r"(rank));
    return d;
}
__device__ __forceinline__ void mbar_init(uint32_t addr, uint32_t cnt) {
    asm volatile("mbarrier.init.shared.b64 [%0], %1;" :: "r"(addr), "r"(cnt) : "memory");
}
__device__ __forceinline__ void mbar_arrive_local(uint32_t addr) {
    asm volatile("mbarrier.arrive.shared.b64 _, [%0];" :: "r"(addr) : "memory");
}
__device__ __forceinline__ void mbar_arrive_expect_tx(uint32_t addr, uint32_t tx) {
    asm volatile("mbarrier.arrive.expect_tx.shared.b64 _, [%0], %1;"
                 :: "r"(addr), "r"(tx) : "memory");
}
__device__ __forceinline__ void st_async_cluster_f32(uint32_t daddr, float v, uint32_t mbar) {
    asm volatile(
        "st.async.shared::cluster.mbarrier::complete_tx::bytes.b32 [%0], %1, [%2];"
        :: "r"(daddr), "r"(__float_as_uint(v)), "r"(mbar) : "memory");
}
__device__ __forceinline__ void mbar_wait_parity_relaxed(uint32_t addr, uint32_t par) {
    asm volatile(
        "{\n\t.reg .pred P;\n\t"
        "W%=:\n\t"
        "mbarrier.try_wait.parity.relaxed.cta.shared::cta.b64 P, [%0], %1, 0x989680;\n\t"
        "@P bra D%=;\n\t"
        "bra W%=;\n\t"
        "D%=:\n\t}"
        :: "r"(addr), "r"(par) : "memory");
}
__device__ __forceinline__ float fast_sigmoid(float x) {
    return __fdividef(1.f, 1.f + __expf(-x));
}
__device__ __forceinline__ float fast_tanh(float x) {
    return __fdividef(2.f, 1.f + __expf(-2.f * x)) - 1.f;
}
// gate the scan's gx consumption on GEMM chunk completion (monotonic cnt)
__device__ __forceinline__ void wait_chunk(int dir, int c) {
    const volatile int* p = &d_ready_cnt[dir][c];
    if (*p < 12) { while (*p < 12) { } }
    __threadfence();
}

// =====================================================================
// FUSED kernel: blocks 0..15 = BiGRU scan clusters (2 clusters of 8),
// blocks 16..3087 = gx GEMM tiles feeding the scan through d_ready_cnt.
// =====================================================================
__global__ void __cluster_dims__(NCLUS, 1, 1) __launch_bounds__(FUSED_THREADS, 1)
fused_kernel(const float* __restrict__ feat,
             const float* __restrict__ Wihf, const float* __restrict__ bihf,
             const float* __restrict__ Wihb, const float* __restrict__ bihb,
             const float* __restrict__ Whf,  const float* __restrict__ bhf,
             const float* __restrict__ Whb,  const float* __restrict__ bhb)
{
    if (blockIdx.x >= 16) {
        // ================== GEMM path ==================
        const int bid = blockIdx.x - 16;
        const int dir = bid / 1536;
        const int rem = bid - dir * 1536;
        const int ox  = rem % 12;
        const int yraw = rem / 12;
        // both-ends-first: forward scan needs low t, backward needs high t
        const int ty = (yraw & 1) ? (127 - (yraw >> 1)) : (yraw >> 1);

        const float* __restrict__ W    = dir ? Wihb : Wihf;
        const float* __restrict__ bias = dir ? bihb : bihf;
        float* __restrict__ C = d_gx[dir];

        const int t0 = ty * 128;
        const int o0 = ox * 64;

        __shared__ float As[16][132];
        __shared__ float Bs[16][68];

        const int tid = threadIdx.x;
        const int tx = tid & 15, tyy = tid >> 4;
        const int m0 = tyy * 8, n0 = tx * 4;

        const int ar0 = tid >> 2;
        const int akq = (tid & 3) * 4;

        const float* aptr0 = feat + (size_t)(t0 + ar0)      * D_IN + akq;
        const float* aptr1 = feat + (size_t)(t0 + ar0 + 64) * D_IN + akq;
        const float* bptr  = W    + (size_t)(o0 + ar0)      * D_IN + akq;

        float4 pa0 = *(const float4*)(aptr0);
        float4 pa1 = *(const float4*)(aptr1);
        float4 pb  = *(const float4*)(bptr);

        unsigned long long acc2[4][4];
#pragma unroll
        for (int i = 0; i < 4; i++)
#pragma unroll
            for (int j = 0; j < 4; j++) acc2[i][j] = 0ull;

        for (int kt = 0; kt < D_IN; kt += 16) {
            As[akq + 0][ar0] = pa0.x; As[akq + 1][ar0] = pa0.y;
            As[akq + 2][ar0] = pa0.z; As[akq + 3][ar0] = pa0.w;
            As[akq + 0][ar0 + 64] = pa1.x; As[akq + 1][ar0 + 64] = pa1.y;
            As[akq + 2][ar0 + 64] = pa1.z; As[akq + 3][ar0 + 64] = pa1.w;
            Bs[akq + 0][ar0] = pb.x; Bs[akq + 1][ar0] = pb.y;
            Bs[akq + 2][ar0] = pb.z; Bs[akq + 3][ar0] = pb.w;
            __syncthreads();

            if (kt + 16 < D_IN) {
                pa0 = *(const float4*)(aptr0 + kt + 16);
                pa1 = *(const float4*)(aptr1 + kt + 16);
                pb  = *(const float4*)(bptr  + kt + 16);
            }

#pragma unroll
            for (int k = 0; k < 16; k++) {
                F4U a0, a1, b;
                a0.f4 = *(const float4*)&As[k][m0];
                a1.f4 = *(const float4*)&As[k][m0 + 4];
                b.f4  = *(const float4*)&Bs[k][n0];
                unsigned long long a2[4] = {a0.u[0], a0.u[1], a1.u[0], a1.u[1]};
                unsigned long long bd[4];
                PACKF2(bd[0], b.f[0], b.f[0]);
                PACKF2(bd[1], b.f[1], b.f[1]);
                PACKF2(bd[2], b.f[2], b.f[2]);
                PACKF2(bd[3], b.f[3], b.f[3]);
#pragma unroll
                for (int i = 0; i < 4; i++)
#pragma unroll
                    for (int j = 0; j < 4; j++)
                        FMA_F32X2(acc2[i][j], a2[i], bd[j], acc2[i][j]);
            }
            __syncthreads();
        }

        const float4 bv4 = *(const float4*)&bias[o0 + n0];
#pragma unroll
        for (int i2 = 0; i2 < 4; i2++) {
            float2 p0 = u2f2(acc2[i2][0]);
            float2 p1 = u2f2(acc2[i2][1]);
            float2 p2 = u2f2(acc2[i2][2]);
            float2 p3 = u2f2(acc2[i2][3]);
            float4 v0, v1;
            v0.x = p0.x + bv4.x; v0.y = p1.x + bv4.y; v0.z = p2.x + bv4.z; v0.w = p3.x + bv4.w;
            v1.x = p0.y + bv4.x; v1.y = p1.y + bv4.y; v1.z = p2.y + bv4.z; v1.w = p3.y + bv4.w;
            *(float4*)&C[(size_t)(t0 + m0 + 2 * i2 + 0) * G3H + o0 + n0] = v0;
            *(float4*)&C[(size_t)(t0 + m0 + 2 * i2 + 1) * G3H + o0 + n0] = v1;
        }

        // publish chunk completion (canonical fence -> sync -> flag)
        __threadfence();
        __syncthreads();
        if (tid == 0) atomicAdd(&d_ready_cnt[dir][ty], 1);
        return;
    }

    // ================== SCAN path ==================
    // padded h: idx(k) = k + (k>>5)*4 ; 8 segs of 32 floats at word 36*seg
    __shared__ __align__(16) float sh_h[2 * 288];
    __shared__ __align__(8) unsigned long long mbars[2];

    const int rank = blockIdx.x & 7;
    const int dir  = blockIdx.x >> 3;
    const float* __restrict__ Whh = dir ? Whb : Whf;
    const float* __restrict__ bhh = dir ? bhb : bhf;
    const float* __restrict__ gx  = d_gx[dir];

    const int tid  = threadIdx.x;
    const int jloc = tid >> 3;         // 0..31 owned hidden unit
    const int seg  = tid & 7;          // 0..7 (32 h each); also target rank
    const int j    = (rank << 5) + jloc;

    // W rows for gates r (row j), z (256+j), n (512+j), this seg's 32 cols
    F4U wr[8], wz[8], wn[8];
    {
        const float4* pr = (const float4*)(Whh + (size_t)(j)       * HID + seg * 32);
        const float4* pz = (const float4*)(Whh + (size_t)(256 + j) * HID + seg * 32);
        const float4* pn = (const float4*)(Whh + (size_t)(512 + j) * HID + seg * 32);
#pragma unroll
        for (int i = 0; i < 8; i++) { wr[i].f4 = pr[i]; wz[i].f4 = pz[i]; wn[i].f4 = pn[i]; }
    }
    const float biasr = bhh[j];
    const float biasz = bhh[256 + j];
    const float biasn = bhh[512 + j];

    for (int i = tid; i < 2 * 288; i += FUSED_THREADS) sh_h[i] = 0.f;
    const uint32_t mb0 = smem_u32(&mbars[0]);
    const uint32_t mb1 = smem_u32(&mbars[1]);
    if (tid == 0) {
        mbar_init(mb0, 1);
        mbar_init(mb1, 1);
        mbar_arrive_local(mb0);   // align parity sequences to ((s+1)>>1)&1
    }
    __syncthreads();
    asm volatile("barrier.cluster.arrive.aligned;" ::: "memory");
    asm volatile("barrier.cluster.wait.aligned;" ::: "memory");

    const float* hs0 = sh_h + 36 * seg;
    const uint32_t hword = (uint32_t)(j + ((j >> 5) << 2));   // padded word idx

    const uint32_t rh     = mapa_rank(smem_u32(&sh_h[0]), (uint32_t)seg) + hword * 4u;
    const uint32_t rmb[2] = { mapa_rank(mb0, (uint32_t)seg),
                              mapa_rank(mb1, (uint32_t)seg) };
    const uint32_t mbl[2] = { mb0, mb1 };

    int t = dir ? (T_LEN - 1) : 0;
    const int tstep = dir ? -1 : 1;
    const int entry = dir ? 127 : 0;   // t&127 value on chunk entry
    float hold = 0.f;
    float xr, xz, xn;
    wait_chunk(dir, t >> 7);
    {
        const float* gp = gx + (size_t)t * G3H + j;
        xr = gp[0]; xz = gp[HID]; xn = gp[2 * HID];
    }

#pragma unroll 2
    for (int s = 0; s < T_LEN; s++) {
        const int b = s & 1;

        if (tid == 0) mbar_arrive_expect_tx(mbl[b ^ 1], 8 * 32 * 4);

        // ---- matvec: 3 gate rows x this seg's 32 h (h loads shared) ----
        const float* hp = hs0 + b * 288;
        unsigned long long ar0 = 0ull, ar1 = 0ull, az0 = 0ull, az1 = 0ull,
                           an0 = 0ull, an1 = 0ull;
#pragma unroll
        for (int i = 0; i < 8; i += 2) {
            F4U h0, h1;
            h0.f4 = *(const float4*)(hp + 4 * i);
            h1.f4 = *(const float4*)(hp + 4 * i + 4);
            FMA_F32X2(ar0, wr[i].u[0],     h0.u[0], ar0);
            FMA_F32X2(ar1, wr[i].u[1],     h0.u[1], ar1);
            FMA_F32X2(az0, wz[i].u[0],     h0.u[0], az0);
            FMA_F32X2(az1, wz[i].u[1],     h0.u[1], az1);
            FMA_F32X2(an0, wn[i].u[0],     h0.u[0], an0);
            FMA_F32X2(an1, wn[i].u[1],     h0.u[1], an1);
            FMA_F32X2(ar0, wr[i + 1].u[0], h1.u[0], ar0);
            FMA_F32X2(ar1, wr[i + 1].u[1], h1.u[1], ar1);
            FMA_F32X2(az0, wz[i + 1].u[0], h1.u[0], az0);
            FMA_F32X2(az1, wz[i + 1].u[1], h1.u[1], az1);
            FMA_F32X2(an0, wn[i + 1].u[0], h1.u[0], an0);
            FMA_F32X2(an1, wn[i + 1].u[1], h1.u[1], an1);
        }
        ADD_F32X2_(ar0, ar0, ar1);
        ADD_F32X2_(az0, az0, az1);
        ADD_F32X2_(an0, an0, an1);
        float2 prx = u2f2(ar0), pzx = u2f2(az0), pnx = u2f2(an0);
        float gr = prx.x + prx.y;
        float gz = pzx.x + pzx.y;
        float gn = pnx.x + pnx.y;
#pragma unroll
        for (int d = 4; d; d >>= 1) {
            gr += __shfl_xor_sync(0xffffffffu, gr, d);
            gz += __shfl_xor_sync(0xffffffffu, gz, d);
            gn += __shfl_xor_sync(0xffffffffu, gn, d);
        }

        // ---- gate combine (redundant across the 8 lanes of the group) ----
        const float r = fast_sigmoid(xr + gr + biasr);
        const float z = fast_sigmoid(xz + gz + biasz);
        const float n = fast_tanh(xn + r * (gn + biasn));
        const float hnew = (1.f - z) * n + z * hold;
        hold = hnew;

        st_async_cluster_f32(rh + (uint32_t)(b ^ 1) * 1152u, hnew, rmb[b ^ 1]);
        if (seg == 0) d_h[(size_t)t * 512 + dir * HID + j] = hnew;

        // prefetch gx for next step (gated on producer chunk readiness)
        if (s + 1 < T_LEN) {
            t += tstep;
            if ((t & 127) == entry) wait_chunk(dir, t >> 7);
            const float* gp = gx + (size_t)t * G3H + j;
            xr = gp[0]; xz = gp[HID]; xn = gp[2 * HID];
        }

        mbar_wait_parity_relaxed(mbl[b ^ 1], (uint32_t)(((s + 1) >> 1) & 1));
    }

    asm volatile("barrier.cluster.arrive.aligned;" ::: "memory");
    asm volatile("barrier.cluster.wait.aligned;" ::: "memory");
}

// =====================================================================
// Kernel 3: scores[t] = relu(h[t] @ Ws1^T + bs1) @ Ws2^T + bs2
// =====================================================================
#define SCORES_SMEM_FLOATS (64 * 516 + 64 + 64 + 32 * 512)
__global__ __launch_bounds__(512)
void scores_kernel(const float* __restrict__ Ws1, const float* __restrict__ bs1,
                   const float* __restrict__ Ws2, const float* __restrict__ bs2,
                   float* __restrict__ out)
{
    extern __shared__ float sm[];
    float* sW1 = sm;                  // 64 x 516 (padded, 16B-aligned rows)
    float* sW2 = sm + 64 * 516;       // 64
    float* sb1 = sW2 + 64;            // 64
    float* sh  = sb1 + 64;            // 32 x 512

    const int tid = threadIdx.x;
    for (int i = tid; i < 64 * 512; i += 512) {
        const int kk = i >> 9, jcol = i & 511;
        sW1[kk * 516 + jcol] = Ws1[i];
    }
    if (tid < 64) { sW2[tid] = Ws2[tid]; sb1[tid] = bs1[tid]; }
    const float bs2v = bs2[0];
    __syncthreads();

    const int warp = tid >> 5, lane = tid & 31;
    const float* w0p = sW1 + (size_t)lane * 516;
    const float* w1p = sW1 + (size_t)(lane + 32) * 516;

    for (int iter = 0; iter < 4; iter++) {
        const int r0 = blockIdx.x * 128 + iter * 32;
        __syncthreads();
        for (int e = tid * 4; e < 32 * 512; e += 512 * 4) {
            const int rrow = e >> 9, col = e & 511;
            *(float4*)&sh[e] = *(const float4*)&d_h[(size_t)(r0 + rrow) * 512 + col];
        }
        __syncthreads();

#pragma unroll
        for (int rr = 0; rr < 2; rr++) {
            const int rowl = warp * 2 + rr;
            const float* hrow = sh + (size_t)rowl * 512;
            unsigned long long c00 = 0ull, c01 = 0ull, c10 = 0ull, c11 = 0ull;
            for (int jc = 0; jc < 512; jc += 4) {
                F4U hv, w0v, w1v;
                hv.f4  = *(const float4*)(hrow + jc);
                w0v.f4 = *(const float4*)(w0p + jc);
                w1v.f4 = *(const float4*)(w1p + jc);
                FMA_F32X2(c00, hv.u[0], w0v.u[0], c00);
                FMA_F32X2(c01, hv.u[1], w0v.u[1], c01);
                FMA_F32X2(c10, hv.u[0], w1v.u[0], c10);
                FMA_F32X2(c11, hv.u[1], w1v.u[1], c11);
            }
            ADD_F32X2_(c00, c00, c01);
            ADD_F32X2_(c10, c10, c11);
            float2 s0 = u2f2(c00), s1 = u2f2(c10);
            const float acc0 = s0.x + s0.y;
            const float acc1 = s1.x + s1.y;
            float v = fmaxf(acc0 + sb1[lane], 0.f) * sW2[lane]
                    + fmaxf(acc1 + sb1[lane + 32], 0.f) * sW2[lane + 32];
#pragma unroll
            for (int o = 16; o; o >>= 1) v += __shfl_down_sync(0xffffffffu, v, o);
            if (lane == 0) out[2 + r0 + rowl] = v + bs2v;
        }
    }
}

// =====================================================================
// Kernel 4a: top-8 -> softmax weights -> clip_repr (1 CTA, 1024 thr)
// =====================================================================
__global__ __launch_bounds__(1024)
void topk_clip_kernel(const float* __restrict__ feat, const float* __restrict__ temp,
                      const float* __restrict__ out_scores)
{
    __shared__ float rv[1024];
    __shared__ int   ri[1024];
    __shared__ int   chosen[8];
    __shared__ float chval[8];
    __shared__ float wts[8];

    const float* scores = out_scores + 2;
    const int tid = threadIdx.x;

    float sc[16];
#pragma unroll
    for (int i = 0; i < 16; i++) sc[i] = scores[tid + (i << 10)];
    unsigned taken = 0;

    for (int k = 0; k < 8; k++) {
        float best = -3.4e38f; int bi = 0x7fffffff;
#pragma unroll
        for (int i = 0; i < 16; i++) {
            const int jg = tid + (i << 10);
            const float v = sc[i];
            if (!(taken & (1u << i)) && (v > best || (v == best && jg < bi))) {
                best = v; bi = jg;
            }
        }
        rv[tid] = best; ri[tid] = bi;
        __syncthreads();
        for (int s = 512; s; s >>= 1) {
            if (tid < s) {
                if (rv[tid + s] > rv[tid] ||
                    (rv[tid + s] == rv[tid] && ri[tid + s] < ri[tid])) {
                    rv[tid] = rv[tid + s]; ri[tid] = ri[tid + s];
                }
            }
            __syncthreads();
        }
        if (tid == 0) { chosen[k] = ri[0]; chval[k] = rv[0]; }
        __syncthreads();
        const int ck = chosen[k];
        if ((ck & 1023) == tid) taken |= 1u << (ck >> 10);
    }

    if (tid == 0) {
        const float tmp = temp[0];
        float m = chval[0];
        for (int k = 1; k < 8; k++) m = fmaxf(m, chval[k]);
        float ssum = 0.f;
        for (int k = 0; k < 8; k++) { const float e = expf((chval[k] - m) / tmp); wts[k] = e; ssum += e; }
        for (int k = 0; k < 8; k++) { wts[k] /= ssum; d_wts[k] = wts[k]; d_chosen[k] = chosen[k]; }
    }
    __syncthreads();

    for (int d = tid; d < D_IN; d += 1024) {
        float c = 0.f;
#pragma unroll
        for (int k = 0; k < 8; k++)
            c = fmaf(wts[k], feat[(size_t)chosen[k] * D_IN + d], c);
        d_clip[d] = c;
    }
}

// =====================================================================
// Kernel 4b: c1 = relu(Wc1 @ clip + bc1), 16 CTAs x 256 thr (16 thr/row)
// =====================================================================
__global__ __launch_bounds__(256)
void classify_kernel(const float* __restrict__ Wc1, const float* __restrict__ bc1)
{
    const int tid = threadIdx.x;
    const int o = blockIdx.x * 16 + (tid >> 4);
    const int part = tid & 15;
    const float* wr = Wc1 + (size_t)o * D_IN + part * 128;
    const float* cp = d_clip + part * 128;
    float s0 = 0.f, s1 = 0.f, s2 = 0.f, s3 = 0.f;
#pragma unroll
    for (int jc = 0; jc < 128; jc += 16) {
        const float4 c0 = *(const float4*)(cp + jc);
        const float4 w0 = *(const float4*)(wr + jc);
        const float4 c1v = *(const float4*)(cp + jc + 4);
        const float4 w1 = *(const float4*)(wr + jc + 4);
        const float4 c2 = *(const float4*)(cp + jc + 8);
        const float4 w2 = *(const float4*)(wr + jc + 8);
        const float4 c3 = *(const float4*)(cp + jc + 12);
        const float4 w3 = *(const float4*)(wr + jc + 12);
        s0 = fmaf(c0.x, w0.x, s0); s0 = fmaf(c0.y, w0.y, s0);
        s0 = fmaf(c0.z, w0.z, s0); s0 = fmaf(c0.w, w0.w, s0);
        s1 = fmaf(c1v.x, w1.x, s1); s1 = fmaf(c1v.y, w1.y, s1);
        s1 = fmaf(c1v.z, w1.z, s1); s1 = fmaf(c1v.w, w1.w, s1);
        s2 = fmaf(c2.x, w2.x, s2); s2 = fmaf(c2.y, w2.y, s2);
        s2 = fmaf(c2.z, w2.z, s2); s2 = fmaf(c2.w, w2.w, s2);
        s3 = fmaf(c3.x, w3.x, s3); s3 = fmaf(c3.y, w3.y, s3);
        s3 = fmaf(c3.z, w3.z, s3); s3 = fmaf(c3.w, w3.w, s3);
    }
    float s = (s0 + s1) + (s2 + s3);
    s += __shfl_down_sync(0xffffffffu, s, 8, 16);
    s += __shfl_down_sync(0xffffffffu, s, 4, 16);
    s += __shfl_down_sync(0xffffffffu, s, 2, 16);
    s += __shfl_down_sync(0xffffffffu, s, 1, 16);
    if (part == 0) d_c1[o] = fmaxf(s + bc1[o], 0.f);
}

// =====================================================================
// Kernel 4c: logits = c1 @ Wc2^T + bc2 (1 CTA, 64 thr)
// =====================================================================
__global__ __launch_bounds__(64)
void logits_kernel(const float* __restrict__ Wc2, const float* __restrict__ bc2,
                   float* __restrict__ out)
{
    const int tid = threadIdx.x;
    const int c = tid >> 5, lane = tid & 31;
    float s = 0.f;
    for (int kk = lane; kk < 256; kk += 32)
        s = fmaf(d_c1[kk], Wc2[(size_t)c * 256 + kk], s);
#pragma unroll
    for (int o = 16; o; o >>= 1) s += __shfl_down_sync(0xffffffffu, s, o);
    if (lane == 0) out[c] = s + bc2[c];
}

// =====================================================================
extern "C" void kernel_launch(void* const* d_in, const int* in_sizes, int n_in,
                              void* d_out, int out_size)
{
    const float* feat   = (const float*)d_in[0];
    const float* temp   = (const float*)d_in[1];
    const float* W_ih_f = (const float*)d_in[2];
    const float* W_hh_f = (const float*)d_in[3];
    const float* b_ih_f = (const float*)d_in[4];
    const float* b_hh_f = (const float*)d_in[5];
    const float* W_ih_b = (const float*)d_in[6];
    const float* W_hh_b = (const float*)d_in[7];
    const float* b_ih_b = (const float*)d_in[8];
    const float* b_hh_b = (const float*)d_in[9];
    const float* Ws1    = (const float*)d_in[10];
    const float* bs1    = (const float*)d_in[11];
    const float* Ws2    = (const float*)d_in[12];
    const float* bs2    = (const float*)d_in[13];
    const float* Wc1    = (const float*)d_in[14];
    const float* bc1    = (const float*)d_in[15];
    const float* Wc2    = (const float*)d_in[16];
    const float* bc2    = (const float*)d_in[17];
    float* out = (float*)d_out;

    // 1+2) fused: GEMM producers (3072 CTAs) + BiGRU scan (16 CTAs)
    fused_kernel<<<FUSED_GRID, FUSED_THREADS>>>(
        feat, W_ih_f, b_ih_f, W_ih_b, b_ih_b,
        W_hh_f, b_hh_f, W_hh_b, b_hh_b);

    // 3) frame scores
    cudaFuncSetAttribute(scores_kernel, cudaFuncAttributeMaxDynamicSharedMemorySize,
                         SCORES_SMEM_FLOATS * 4);
    scores_kernel<<<128, 512, SCORES_SMEM_FLOATS * 4>>>(Ws1, bs1, Ws2, bs2, out);

    // 4) top-k + softmax + weighted sum + classifier
    topk_clip_kernel<<<1, 1024>>>(feat, temp, out);
    classify_kernel<<<16, 256>>>(Wc1, bc1);
    logits_kernel<<<1, 64>>>(Wc2, bc2, out);
}